// round 3
// baseline (speedup 1.0000x reference)
#include <cuda_runtime.h>
#include <math.h>

// Problem constants
#define BB 2
#define SS 2048
#define DM 1024
#define NH 16
#define HD 64
#define MROWS (BB*SS)        // 4096

// Scratch (device globals; no allocations allowed)
__device__ float g_Q[BB*NH*SS*HD];     // [b,h,s,d]
__device__ float g_K[BB*NH*SS*HD];
__device__ float g_V[BB*NH*SS*HD];
__device__ float g_att[BB*SS*DM];      // [b,s, h*64+d]

// ---------------------------------------------------------------------------
// Tiled SGEMM: C[M,N] = A[M,K] @ B[K,N] + bias[N]
// BM=BN=128, BK=8, 256 threads, 8x8 per thread.
// head_split: write C in [b,h,s,d] layout instead of row-major.
// ---------------------------------------------------------------------------
__global__ __launch_bounds__(256) void gemm128(
    const float* __restrict__ A, const float* __restrict__ B,
    const float* __restrict__ bias, float* __restrict__ C,
    int M, int N, int K, int head_split)
{
    __shared__ float As[8][128];   // As[k][m]
    __shared__ float Bs[8][128];   // Bs[k][n]

    const int tid  = threadIdx.x;
    const int row0 = blockIdx.y * 128;
    const int col0 = blockIdx.x * 128;
    const int ty   = tid >> 4;     // 0..15
    const int tx   = tid & 15;     // 0..15

    // global load mapping
    const int ar = tid >> 1;           // 0..127
    const int ak = (tid & 1) * 4;      // 0 or 4
    const int br = tid >> 5;           // 0..7
    const int bc = (tid & 31) * 4;     // 0..124

    const float* Ap = A + (size_t)(row0 + ar) * K + ak;
    const float* Bp = B + (size_t)br * N + col0 + bc;

    float acc[8][8];
    #pragma unroll
    for (int i = 0; i < 8; i++)
        #pragma unroll
        for (int j = 0; j < 8; j++) acc[i][j] = 0.f;

    for (int k0 = 0; k0 < K; k0 += 8) {
        float4 av = *(const float4*)(Ap + k0);
        float4 bv = *(const float4*)(Bp + (size_t)k0 * N);
        __syncthreads();
        As[ak + 0][ar] = av.x;
        As[ak + 1][ar] = av.y;
        As[ak + 2][ar] = av.z;
        As[ak + 3][ar] = av.w;
        *(float4*)&Bs[br][bc] = bv;
        __syncthreads();

        #pragma unroll
        for (int k = 0; k < 8; k++) {
            float4 a0 = *(const float4*)&As[k][ty * 8];
            float4 a1 = *(const float4*)&As[k][ty * 8 + 4];
            float4 b0 = *(const float4*)&Bs[k][tx * 8];
            float4 b1 = *(const float4*)&Bs[k][tx * 8 + 4];
            float a[8] = {a0.x,a0.y,a0.z,a0.w,a1.x,a1.y,a1.z,a1.w};
            float b[8] = {b0.x,b0.y,b0.z,b0.w,b1.x,b1.y,b1.z,b1.w};
            #pragma unroll
            for (int i = 0; i < 8; i++)
                #pragma unroll
                for (int j = 0; j < 8; j++)
                    acc[i][j] += a[i] * b[j];
        }
    }

    #pragma unroll
    for (int i = 0; i < 8; i++) {
        int row = row0 + ty * 8 + i;
        #pragma unroll
        for (int j = 0; j < 8; j++) {
            int col = col0 + tx * 8 + j;
            float c = acc[i][j] + bias[col];
            if (head_split) {
                int b = row >> 11, s = row & 2047;
                int h = col >> 6,  d = col & 63;
                C[((((size_t)b * NH + h) * SS + s) * HD) + d] = c;
            } else {
                C[(size_t)row * N + col] = c;
            }
        }
    }
}

// ---------------------------------------------------------------------------
// Flash attention (causal). One block = one (b,h) x 64-query tile.
// 256 threads (8 warps). Warp w owns rows w*8..w*8+7.
// KV tiles of 32 keys. Online softmax.
// ---------------------------------------------------------------------------
__global__ __launch_bounds__(256) void attn_kernel(
    const float* __restrict__ Q, const float* __restrict__ K,
    const float* __restrict__ V, float* __restrict__ O)
{
    __shared__ float Qt[64][64];   // Qt[d][r]
    __shared__ float Kt[64][32];   // Kt[d][c]
    __shared__ float Vs[32][64];   // Vs[c][d]
    __shared__ float Ps[64][32];   // Ps[r][c]

    const int bh   = blockIdx.y;           // 0..31
    const int q0   = blockIdx.x * 64;
    const int tid  = threadIdx.x;
    const int warp = tid >> 5;
    const int lane = tid & 31;
    const int r0   = warp * 8;

    const float* Qb = Q + (size_t)bh * SS * HD;
    const float* Kb = K + (size_t)bh * SS * HD;
    const float* Vb = V + (size_t)bh * SS * HD;

    // load Q tile transposed
    {
        int r  = tid >> 4;
        int d4 = (tid & 15) * 4;
        #pragma unroll
        for (int it = 0; it < 4; it++) {
            int rr = r + it * 16;
            float4 v = *(const float4*)(Qb + (size_t)(q0 + rr) * HD + d4);
            Qt[d4 + 0][rr] = v.x;
            Qt[d4 + 1][rr] = v.y;
            Qt[d4 + 2][rr] = v.z;
            Qt[d4 + 3][rr] = v.w;
        }
    }

    float o[8][2], m[8], l[8];
    #pragma unroll
    for (int i = 0; i < 8; i++) {
        o[i][0] = 0.f; o[i][1] = 0.f;
        m[i] = -INFINITY; l[i] = 0.f;
    }

    const float sc = 0.125f;                 // 1/sqrt(64)
    const int nk = (q0 + 64) / 32;           // kv tiles covering keys <= q0+63
    const int d0 = lane * 2;

    for (int kt = 0; kt < nk; kt++) {
        const int k0 = kt * 32;
        __syncthreads();   // previous tile fully consumed
        {
            int c  = tid >> 4;
            int d4 = (tid & 15) * 4;
            #pragma unroll
            for (int it = 0; it < 2; it++) {
                int cc = c + it * 16;
                float4 kv = *(const float4*)(Kb + (size_t)(k0 + cc) * HD + d4);
                Kt[d4 + 0][cc] = kv.x;
                Kt[d4 + 1][cc] = kv.y;
                Kt[d4 + 2][cc] = kv.z;
                Kt[d4 + 3][cc] = kv.w;
                float4 vv = *(const float4*)(Vb + (size_t)(k0 + cc) * HD + d4);
                *(float4*)&Vs[cc][d4] = vv;
            }
        }
        __syncthreads();

        // skip tiles fully masked for this warp's rows
        if (k0 > q0 + r0 + 7) continue;

        // S = Q K^T : lane owns column 'lane'
        float s[8];
        #pragma unroll
        for (int i = 0; i < 8; i++) s[i] = 0.f;
        #pragma unroll
        for (int d = 0; d < 64; d++) {
            float kv = Kt[d][lane];
            float4 qa = *(const float4*)&Qt[d][r0];
            float4 qb = *(const float4*)&Qt[d][r0 + 4];
            s[0] += qa.x * kv; s[1] += qa.y * kv;
            s[2] += qa.z * kv; s[3] += qa.w * kv;
            s[4] += qb.x * kv; s[5] += qb.y * kv;
            s[6] += qb.z * kv; s[7] += qb.w * kv;
        }

        // mask + scale
        #pragma unroll
        for (int i = 0; i < 8; i++) {
            int qg = q0 + r0 + i;
            int kg = k0 + lane;
            s[i] = (kg <= qg) ? s[i] * sc : -INFINITY;
        }

        // online softmax per row
        #pragma unroll
        for (int i = 0; i < 8; i++) {
            float mx = s[i];
            #pragma unroll
            for (int off = 16; off > 0; off >>= 1)
                mx = fmaxf(mx, __shfl_xor_sync(0xFFFFFFFFu, mx, off));
            float mnew  = fmaxf(m[i], mx);
            float alpha = __expf(m[i] - mnew);
            float p     = __expf(s[i] - mnew);
            float ps = p;
            #pragma unroll
            for (int off = 16; off > 0; off >>= 1)
                ps += __shfl_xor_sync(0xFFFFFFFFu, ps, off);
            l[i] = l[i] * alpha + ps;
            m[i] = mnew;
            o[i][0] *= alpha;
            o[i][1] *= alpha;
            Ps[r0 + i][lane] = p;
        }
        __syncwarp();

        // O += P @ V : lane owns dims d0, d0+1
        #pragma unroll
        for (int c = 0; c < 32; c++) {
            float2 v = *(const float2*)&Vs[c][d0];
            #pragma unroll
            for (int i = 0; i < 8; i++) {
                float p = Ps[r0 + i][c];
                o[i][0] += p * v.x;
                o[i][1] += p * v.y;
            }
        }
    }

    // write O in [b, s, h*64+d] layout
    const int b = bh >> 4, h = bh & 15;
    #pragma unroll
    for (int i = 0; i < 8; i++) {
        float inv = 1.f / l[i];
        int sg = q0 + r0 + i;
        float* dst = O + ((size_t)(b * SS + sg)) * DM + h * HD + d0;
        float2 w;
        w.x = o[i][0] * inv;
        w.y = o[i][1] * inv;
        *(float2*)dst = w;
    }
}

// ---------------------------------------------------------------------------
extern "C" void kernel_launch(void* const* d_in, const int* in_sizes, int n_in,
                              void* d_out, int out_size)
{
    const float* x  = (const float*)d_in[0];
    const float* Wq = (const float*)d_in[1];
    const float* bq = (const float*)d_in[2];
    const float* Wk = (const float*)d_in[3];
    const float* bk = (const float*)d_in[4];
    const float* Wv = (const float*)d_in[5];
    const float* bv = (const float*)d_in[6];
    const float* Wo = (const float*)d_in[7];
    const float* bo = (const float*)d_in[8];

    float *qp, *kp, *vp, *ap;
    cudaGetSymbolAddress((void**)&qp, g_Q);
    cudaGetSymbolAddress((void**)&kp, g_K);
    cudaGetSymbolAddress((void**)&vp, g_V);
    cudaGetSymbolAddress((void**)&ap, g_att);

    dim3 gg(DM / 128, MROWS / 128);   // (8, 32)
    gemm128<<<gg, 256>>>(x, Wq, bq, qp, MROWS, DM, DM, 1);
    gemm128<<<gg, 256>>>(x, Wk, bk, kp, MROWS, DM, DM, 1);
    gemm128<<<gg, 256>>>(x, Wv, bv, vp, MROWS, DM, DM, 1);

    attn_kernel<<<dim3(SS / 64, BB * NH), 256>>>(qp, kp, vp, ap);

    gemm128<<<gg, 256>>>(ap, Wo, bo, (float*)d_out, MROWS, DM, DM, 0);
}

// round 4
// speedup vs baseline: 1.6972x; 1.6972x over previous
#include <cuda_runtime.h>
#include <math.h>
#include <stdint.h>

// Problem constants
#define BB 2
#define SS 2048
#define DM 1024
#define NH 16
#define HD 64
#define MROWS (BB*SS)        // 4096

// Scratch (device globals; no allocations allowed)
__device__ float g_Q[BB*NH*SS*HD];     // [b,h,s,d]
__device__ float g_K[BB*NH*SS*HD];
__device__ float g_V[BB*NH*SS*HD];
__device__ float g_att[BB*SS*DM];      // [b,s, h*64+d]

// ---------------------------------------------------------------------------
// tf32 tensor-core GEMM: C[M,N] = A[M,K] @ B[K,N] + bias[N]
// 128x128 block tile, BK=16, 256 threads (8 warps: 2x4 of 64x32 warp tiles).
// mma.sync.aligned.m16n8k8.row.col.f32.tf32.tf32.f32, fp32 accumulate.
// Double-buffered smem. A stored [m][k] stride 20; B stored [k][n] stride 136
// (both give conflict-free banks for the mma fragment load patterns).
// head_split: write C in [b,h,s,d] layout instead of row-major.
// ---------------------------------------------------------------------------

__device__ __forceinline__ float to_tf32(float x) {
    uint32_t u = __float_as_uint(x), y;
    asm("cvt.rna.tf32.f32 %0, %1;" : "=r"(y) : "r"(u));
    return __uint_as_float(y);
}

__device__ __forceinline__ void mma_tf32(float c[4],
    uint32_t a0, uint32_t a1, uint32_t a2, uint32_t a3,
    uint32_t b0, uint32_t b1)
{
    asm volatile(
        "mma.sync.aligned.m16n8k8.row.col.f32.tf32.tf32.f32 "
        "{%0,%1,%2,%3}, {%4,%5,%6,%7}, {%8,%9}, {%0,%1,%2,%3};"
        : "+f"(c[0]), "+f"(c[1]), "+f"(c[2]), "+f"(c[3])
        : "r"(a0), "r"(a1), "r"(a2), "r"(a3), "r"(b0), "r"(b1));
}

#define ASTRIDE 20
#define BSTRIDE 136

__global__ __launch_bounds__(256) void gemm_tf32(
    const float* __restrict__ A, const float* __restrict__ B,
    const float* __restrict__ bias, float* __restrict__ C,
    int M, int N, int K, int head_split)
{
    __shared__ float As[2][128][ASTRIDE];   // [m][k], k-padded
    __shared__ float Bs[2][16][BSTRIDE];    // [k][n], n-padded

    const int tid  = threadIdx.x;
    const int warp = tid >> 5;
    const int lane = tid & 31;
    const int wm   = (warp >> 2) * 64;      // warp row offset: 0 or 64
    const int wn   = (warp & 3) * 32;       // warp col offset: 0..96
    const int row0 = blockIdx.y * 128;
    const int col0 = blockIdx.x * 128;

    // global A load mapping: thread covers rows (tid>>2) and (tid>>2)+64,
    // k segment ((tid&3)*4 .. +4)
    const int arow = tid >> 2;              // 0..63
    const int akp  = (tid & 3) * 4;         // 0,4,8,12
    // global B load mapping: k rows (tid>>5) and (tid>>5)+8, cols (tid&31)*4
    const int brow = tid >> 5;              // 0..7
    const int bcol = (tid & 31) * 4;

    const float* Ap0 = A + (size_t)(row0 + arow) * K + akp;
    const float* Ap1 = A + (size_t)(row0 + arow + 64) * K + akp;
    const float* Bp0 = B + (size_t)brow * N + col0 + bcol;
    const float* Bp1 = B + (size_t)(brow + 8) * N + col0 + bcol;

    float acc[4][4][4];
    #pragma unroll
    for (int i = 0; i < 4; i++)
        #pragma unroll
        for (int j = 0; j < 4; j++)
            #pragma unroll
            for (int r = 0; r < 4; r++) acc[i][j][r] = 0.f;

    const int NT = K / 16;

    // ---- prologue: tile 0 -> smem buf 0 ----
    {
        float4 a0 = *(const float4*)Ap0;
        float4 a1 = *(const float4*)Ap1;
        float4 b0 = *(const float4*)Bp0;
        float4 b1 = *(const float4*)Bp1;
        As[0][arow][akp+0] = to_tf32(a0.x);
        As[0][arow][akp+1] = to_tf32(a0.y);
        As[0][arow][akp+2] = to_tf32(a0.z);
        As[0][arow][akp+3] = to_tf32(a0.w);
        As[0][arow+64][akp+0] = to_tf32(a1.x);
        As[0][arow+64][akp+1] = to_tf32(a1.y);
        As[0][arow+64][akp+2] = to_tf32(a1.z);
        As[0][arow+64][akp+3] = to_tf32(a1.w);
        float4 c0 = make_float4(to_tf32(b0.x), to_tf32(b0.y), to_tf32(b0.z), to_tf32(b0.w));
        float4 c1 = make_float4(to_tf32(b1.x), to_tf32(b1.y), to_tf32(b1.z), to_tf32(b1.w));
        *(float4*)&Bs[0][brow][bcol]     = c0;
        *(float4*)&Bs[0][brow + 8][bcol] = c1;
    }
    __syncthreads();

    const int fr = lane >> 2;     // 0..7
    const int fk = lane & 3;      // 0..3

    float4 av0, av1, bv0, bv1;

    for (int kt = 0; kt < NT; kt++) {
        const int cur = kt & 1;
        const bool pf = (kt + 1) < NT;

        if (pf) {
            const float* a0p = Ap0 + (size_t)(kt + 1) * 16;
            const float* a1p = Ap1 + (size_t)(kt + 1) * 16;
            const float* b0p = Bp0 + (size_t)(kt + 1) * 16 * N;
            const float* b1p = Bp1 + (size_t)(kt + 1) * 16 * N;
            av0 = *(const float4*)a0p;
            av1 = *(const float4*)a1p;
            bv0 = *(const float4*)b0p;
            bv1 = *(const float4*)b1p;
        }

        // ---- compute on smem[cur] ----
        #pragma unroll
        for (int ks = 0; ks < 16; ks += 8) {
            uint32_t af[4][4];
            uint32_t bf[4][2];
            #pragma unroll
            for (int mi = 0; mi < 4; mi++) {
                int r = wm + mi * 16 + fr;
                af[mi][0] = __float_as_uint(As[cur][r    ][ks + fk    ]);
                af[mi][1] = __float_as_uint(As[cur][r + 8][ks + fk    ]);
                af[mi][2] = __float_as_uint(As[cur][r    ][ks + fk + 4]);
                af[mi][3] = __float_as_uint(As[cur][r + 8][ks + fk + 4]);
            }
            #pragma unroll
            for (int ni = 0; ni < 4; ni++) {
                int c = wn + ni * 8 + fr;
                bf[ni][0] = __float_as_uint(Bs[cur][ks + fk    ][c]);
                bf[ni][1] = __float_as_uint(Bs[cur][ks + fk + 4][c]);
            }
            #pragma unroll
            for (int mi = 0; mi < 4; mi++)
                #pragma unroll
                for (int ni = 0; ni < 4; ni++)
                    mma_tf32(acc[mi][ni],
                             af[mi][0], af[mi][1], af[mi][2], af[mi][3],
                             bf[ni][0], bf[ni][1]);
        }

        if (pf) {
            const int nb = 1 - cur;
            As[nb][arow][akp+0] = to_tf32(av0.x);
            As[nb][arow][akp+1] = to_tf32(av0.y);
            As[nb][arow][akp+2] = to_tf32(av0.z);
            As[nb][arow][akp+3] = to_tf32(av0.w);
            As[nb][arow+64][akp+0] = to_tf32(av1.x);
            As[nb][arow+64][akp+1] = to_tf32(av1.y);
            As[nb][arow+64][akp+2] = to_tf32(av1.z);
            As[nb][arow+64][akp+3] = to_tf32(av1.w);
            float4 c0 = make_float4(to_tf32(bv0.x), to_tf32(bv0.y), to_tf32(bv0.z), to_tf32(bv0.w));
            float4 c1 = make_float4(to_tf32(bv1.x), to_tf32(bv1.y), to_tf32(bv1.z), to_tf32(bv1.w));
            *(float4*)&Bs[nb][brow][bcol]     = c0;
            *(float4*)&Bs[nb][brow + 8][bcol] = c1;
        }
        __syncthreads();
    }

    // ---- epilogue ----
    #pragma unroll
    for (int mi = 0; mi < 4; mi++) {
        int r = row0 + wm + mi * 16 + fr;
        #pragma unroll
        for (int ni = 0; ni < 4; ni++) {
            int c = col0 + wn + ni * 8 + 2 * fk;
            float bb0 = bias[c], bb1 = bias[c + 1];
            float2 v01 = make_float2(acc[mi][ni][0] + bb0, acc[mi][ni][1] + bb1);
            float2 v23 = make_float2(acc[mi][ni][2] + bb0, acc[mi][ni][3] + bb1);
            if (head_split) {
                int h = c >> 6, d = c & 63;
                int b0i = r >> 11, s0 = r & 2047;
                size_t i0 = ((((size_t)b0i * NH + h) * SS + s0) * HD) + d;
                *(float2*)&C[i0] = v01;
                int r2 = r + 8;
                int b1i = r2 >> 11, s1 = r2 & 2047;
                size_t i1 = ((((size_t)b1i * NH + h) * SS + s1) * HD) + d;
                *(float2*)&C[i1] = v23;
            } else {
                *(float2*)&C[(size_t)r * N + c]       = v01;
                *(float2*)&C[(size_t)(r + 8) * N + c] = v23;
            }
        }
    }
}

// ---------------------------------------------------------------------------
// Flash attention (causal). One block = one (b,h) x 64-query tile.
// 256 threads (8 warps). Warp w owns rows w*8..w*8+7.
// KV tiles of 32 keys. Online softmax.  (unchanged from R2)
// ---------------------------------------------------------------------------
__global__ __launch_bounds__(256) void attn_kernel(
    const float* __restrict__ Q, const float* __restrict__ K,
    const float* __restrict__ V, float* __restrict__ O)
{
    __shared__ float Qt[64][64];   // Qt[d][r]
    __shared__ float Kt[64][32];   // Kt[d][c]
    __shared__ float Vs[32][64];   // Vs[c][d]
    __shared__ float Ps[64][32];   // Ps[r][c]

    const int bh   = blockIdx.y;           // 0..31
    const int q0   = blockIdx.x * 64;
    const int tid  = threadIdx.x;
    const int warp = tid >> 5;
    const int lane = tid & 31;
    const int r0   = warp * 8;

    const float* Qb = Q + (size_t)bh * SS * HD;
    const float* Kb = K + (size_t)bh * SS * HD;
    const float* Vb = V + (size_t)bh * SS * HD;

    // load Q tile transposed
    {
        int r  = tid >> 4;
        int d4 = (tid & 15) * 4;
        #pragma unroll
        for (int it = 0; it < 4; it++) {
            int rr = r + it * 16;
            float4 v = *(const float4*)(Qb + (size_t)(q0 + rr) * HD + d4);
            Qt[d4 + 0][rr] = v.x;
            Qt[d4 + 1][rr] = v.y;
            Qt[d4 + 2][rr] = v.z;
            Qt[d4 + 3][rr] = v.w;
        }
    }

    float o[8][2], m[8], l[8];
    #pragma unroll
    for (int i = 0; i < 8; i++) {
        o[i][0] = 0.f; o[i][1] = 0.f;
        m[i] = -INFINITY; l[i] = 0.f;
    }

    const float sc = 0.125f;                 // 1/sqrt(64)
    const int nk = (q0 + 64) / 32;           // kv tiles covering keys <= q0+63
    const int d0 = lane * 2;

    for (int kt = 0; kt < nk; kt++) {
        const int k0 = kt * 32;
        __syncthreads();   // previous tile fully consumed
        {
            int c  = tid >> 4;
            int d4 = (tid & 15) * 4;
            #pragma unroll
            for (int it = 0; it < 2; it++) {
                int cc = c + it * 16;
                float4 kv = *(const float4*)(Kb + (size_t)(k0 + cc) * HD + d4);
                Kt[d4 + 0][cc] = kv.x;
                Kt[d4 + 1][cc] = kv.y;
                Kt[d4 + 2][cc] = kv.z;
                Kt[d4 + 3][cc] = kv.w;
                float4 vv = *(const float4*)(Vb + (size_t)(k0 + cc) * HD + d4);
                *(float4*)&Vs[cc][d4] = vv;
            }
        }
        __syncthreads();

        // skip tiles fully masked for this warp's rows
        if (k0 > q0 + r0 + 7) continue;

        // S = Q K^T : lane owns column 'lane'
        float s[8];
        #pragma unroll
        for (int i = 0; i < 8; i++) s[i] = 0.f;
        #pragma unroll
        for (int d = 0; d < 64; d++) {
            float kv = Kt[d][lane];
            float4 qa = *(const float4*)&Qt[d][r0];
            float4 qb = *(const float4*)&Qt[d][r0 + 4];
            s[0] += qa.x * kv; s[1] += qa.y * kv;
            s[2] += qa.z * kv; s[3] += qa.w * kv;
            s[4] += qb.x * kv; s[5] += qb.y * kv;
            s[6] += qb.z * kv; s[7] += qb.w * kv;
        }

        // mask + scale
        #pragma unroll
        for (int i = 0; i < 8; i++) {
            int qg = q0 + r0 + i;
            int kg = k0 + lane;
            s[i] = (kg <= qg) ? s[i] * sc : -INFINITY;
        }

        // online softmax per row
        #pragma unroll
        for (int i = 0; i < 8; i++) {
            float mx = s[i];
            #pragma unroll
            for (int off = 16; off > 0; off >>= 1)
                mx = fmaxf(mx, __shfl_xor_sync(0xFFFFFFFFu, mx, off));
            float mnew  = fmaxf(m[i], mx);
            float alpha = __expf(m[i] - mnew);
            float p     = __expf(s[i] - mnew);
            float ps = p;
            #pragma unroll
            for (int off = 16; off > 0; off >>= 1)
                ps += __shfl_xor_sync(0xFFFFFFFFu, ps, off);
            l[i] = l[i] * alpha + ps;
            m[i] = mnew;
            o[i][0] *= alpha;
            o[i][1] *= alpha;
            Ps[r0 + i][lane] = p;
        }
        __syncwarp();

        // O += P @ V : lane owns dims d0, d0+1
        #pragma unroll
        for (int c = 0; c < 32; c++) {
            float2 v = *(const float2*)&Vs[c][d0];
            #pragma unroll
            for (int i = 0; i < 8; i++) {
                float p = Ps[r0 + i][c];
                o[i][0] += p * v.x;
                o[i][1] += p * v.y;
            }
        }
    }

    // write O in [b, s, h*64+d] layout
    const int b = bh >> 4, h = bh & 15;
    #pragma unroll
    for (int i = 0; i < 8; i++) {
        float inv = 1.f / l[i];
        int sg = q0 + r0 + i;
        float* dst = O + ((size_t)(b * SS + sg)) * DM + h * HD + d0;
        float2 w;
        w.x = o[i][0] * inv;
        w.y = o[i][1] * inv;
        *(float2*)dst = w;
    }
}

// ---------------------------------------------------------------------------
extern "C" void kernel_launch(void* const* d_in, const int* in_sizes, int n_in,
                              void* d_out, int out_size)
{
    const float* x  = (const float*)d_in[0];
    const float* Wq = (const float*)d_in[1];
    const float* bq = (const float*)d_in[2];
    const float* Wk = (const float*)d_in[3];
    const float* bk = (const float*)d_in[4];
    const float* Wv = (const float*)d_in[5];
    const float* bv = (const float*)d_in[6];
    const float* Wo = (const float*)d_in[7];
    const float* bo = (const float*)d_in[8];

    float *qp, *kp, *vp, *ap;
    cudaGetSymbolAddress((void**)&qp, g_Q);
    cudaGetSymbolAddress((void**)&kp, g_K);
    cudaGetSymbolAddress((void**)&vp, g_V);
    cudaGetSymbolAddress((void**)&ap, g_att);

    dim3 gg(DM / 128, MROWS / 128);   // (8, 32)
    gemm_tf32<<<gg, 256>>>(x, Wq, bq, qp, MROWS, DM, DM, 1);
    gemm_tf32<<<gg, 256>>>(x, Wk, bk, kp, MROWS, DM, DM, 1);
    gemm_tf32<<<gg, 256>>>(x, Wv, bv, vp, MROWS, DM, DM, 1);

    attn_kernel<<<dim3(SS / 64, BB * NH), 256>>>(qp, kp, vp, ap);

    gemm_tf32<<<gg, 256>>>(ap, Wo, bo, (float*)d_out, MROWS, DM, DM, 0);
}

// round 5
// speedup vs baseline: 3.7138x; 2.1883x over previous
#include <cuda_runtime.h>
#include <math.h>
#include <stdint.h>

// Problem constants
#define BB 2
#define SS 2048
#define DM 1024
#define NH 16
#define HD 64
#define MROWS (BB*SS)        // 4096

// Scratch (device globals; no allocations allowed)
__device__ float g_Q[BB*NH*SS*HD];     // [b,h,s,d]
__device__ float g_K[BB*NH*SS*HD];
__device__ float g_V[BB*NH*SS*HD];
__device__ float g_att[BB*SS*DM];      // [b,s, h*64+d]

// ---------------------------------------------------------------------------
// tf32 helpers
// ---------------------------------------------------------------------------
__device__ __forceinline__ float to_tf32(float x) {
    uint32_t u = __float_as_uint(x), y;
    asm("cvt.rna.tf32.f32 %0, %1;" : "=r"(y) : "r"(u));
    return __uint_as_float(y);
}
__device__ __forceinline__ uint32_t to_tf32u(float x) {
    uint32_t u = __float_as_uint(x), y;
    asm("cvt.rna.tf32.f32 %0, %1;" : "=r"(y) : "r"(u));
    return y;
}

__device__ __forceinline__ void mma_tf32(float c[4],
    uint32_t a0, uint32_t a1, uint32_t a2, uint32_t a3,
    uint32_t b0, uint32_t b1)
{
    asm volatile(
        "mma.sync.aligned.m16n8k8.row.col.f32.tf32.tf32.f32 "
        "{%0,%1,%2,%3}, {%4,%5,%6,%7}, {%8,%9}, {%0,%1,%2,%3};"
        : "+f"(c[0]), "+f"(c[1]), "+f"(c[2]), "+f"(c[3])
        : "r"(a0), "r"(a1), "r"(a2), "r"(a3), "r"(b0), "r"(b1));
}

// ---------------------------------------------------------------------------
// tf32 tensor-core GEMM: C[M,N] = A[M,K] @ B[K,N] + bias[N]   (unchanged R3)
// ---------------------------------------------------------------------------
#define ASTRIDE 20
#define BSTRIDE 136

__global__ __launch_bounds__(256) void gemm_tf32(
    const float* __restrict__ A, const float* __restrict__ B,
    const float* __restrict__ bias, float* __restrict__ C,
    int M, int N, int K, int head_split)
{
    __shared__ float As[2][128][ASTRIDE];   // [m][k], k-padded
    __shared__ float Bs[2][16][BSTRIDE];    // [k][n], n-padded

    const int tid  = threadIdx.x;
    const int warp = tid >> 5;
    const int lane = tid & 31;
    const int wm   = (warp >> 2) * 64;
    const int wn   = (warp & 3) * 32;
    const int row0 = blockIdx.y * 128;
    const int col0 = blockIdx.x * 128;

    const int arow = tid >> 2;
    const int akp  = (tid & 3) * 4;
    const int brow = tid >> 5;
    const int bcol = (tid & 31) * 4;

    const float* Ap0 = A + (size_t)(row0 + arow) * K + akp;
    const float* Ap1 = A + (size_t)(row0 + arow + 64) * K + akp;
    const float* Bp0 = B + (size_t)brow * N + col0 + bcol;
    const float* Bp1 = B + (size_t)(brow + 8) * N + col0 + bcol;

    float acc[4][4][4];
    #pragma unroll
    for (int i = 0; i < 4; i++)
        #pragma unroll
        for (int j = 0; j < 4; j++)
            #pragma unroll
            for (int r = 0; r < 4; r++) acc[i][j][r] = 0.f;

    const int NT = K / 16;

    {
        float4 a0 = *(const float4*)Ap0;
        float4 a1 = *(const float4*)Ap1;
        float4 b0 = *(const float4*)Bp0;
        float4 b1 = *(const float4*)Bp1;
        As[0][arow][akp+0] = to_tf32(a0.x);
        As[0][arow][akp+1] = to_tf32(a0.y);
        As[0][arow][akp+2] = to_tf32(a0.z);
        As[0][arow][akp+3] = to_tf32(a0.w);
        As[0][arow+64][akp+0] = to_tf32(a1.x);
        As[0][arow+64][akp+1] = to_tf32(a1.y);
        As[0][arow+64][akp+2] = to_tf32(a1.z);
        As[0][arow+64][akp+3] = to_tf32(a1.w);
        float4 c0 = make_float4(to_tf32(b0.x), to_tf32(b0.y), to_tf32(b0.z), to_tf32(b0.w));
        float4 c1 = make_float4(to_tf32(b1.x), to_tf32(b1.y), to_tf32(b1.z), to_tf32(b1.w));
        *(float4*)&Bs[0][brow][bcol]     = c0;
        *(float4*)&Bs[0][brow + 8][bcol] = c1;
    }
    __syncthreads();

    const int fr = lane >> 2;
    const int fk = lane & 3;

    float4 av0, av1, bv0, bv1;

    for (int kt = 0; kt < NT; kt++) {
        const int cur = kt & 1;
        const bool pf = (kt + 1) < NT;

        if (pf) {
            av0 = *(const float4*)(Ap0 + (size_t)(kt + 1) * 16);
            av1 = *(const float4*)(Ap1 + (size_t)(kt + 1) * 16);
            bv0 = *(const float4*)(Bp0 + (size_t)(kt + 1) * 16 * N);
            bv1 = *(const float4*)(Bp1 + (size_t)(kt + 1) * 16 * N);
        }

        #pragma unroll
        for (int ks = 0; ks < 16; ks += 8) {
            uint32_t af[4][4];
            uint32_t bf[4][2];
            #pragma unroll
            for (int mi = 0; mi < 4; mi++) {
                int r = wm + mi * 16 + fr;
                af[mi][0] = __float_as_uint(As[cur][r    ][ks + fk    ]);
                af[mi][1] = __float_as_uint(As[cur][r + 8][ks + fk    ]);
                af[mi][2] = __float_as_uint(As[cur][r    ][ks + fk + 4]);
                af[mi][3] = __float_as_uint(As[cur][r + 8][ks + fk + 4]);
            }
            #pragma unroll
            for (int ni = 0; ni < 4; ni++) {
                int c = wn + ni * 8 + fr;
                bf[ni][0] = __float_as_uint(Bs[cur][ks + fk    ][c]);
                bf[ni][1] = __float_as_uint(Bs[cur][ks + fk + 4][c]);
            }
            #pragma unroll
            for (int mi = 0; mi < 4; mi++)
                #pragma unroll
                for (int ni = 0; ni < 4; ni++)
                    mma_tf32(acc[mi][ni],
                             af[mi][0], af[mi][1], af[mi][2], af[mi][3],
                             bf[ni][0], bf[ni][1]);
        }

        if (pf) {
            const int nb = 1 - cur;
            As[nb][arow][akp+0] = to_tf32(av0.x);
            As[nb][arow][akp+1] = to_tf32(av0.y);
            As[nb][arow][akp+2] = to_tf32(av0.z);
            As[nb][arow][akp+3] = to_tf32(av0.w);
            As[nb][arow+64][akp+0] = to_tf32(av1.x);
            As[nb][arow+64][akp+1] = to_tf32(av1.y);
            As[nb][arow+64][akp+2] = to_tf32(av1.z);
            As[nb][arow+64][akp+3] = to_tf32(av1.w);
            float4 c0 = make_float4(to_tf32(bv0.x), to_tf32(bv0.y), to_tf32(bv0.z), to_tf32(bv0.w));
            float4 c1 = make_float4(to_tf32(bv1.x), to_tf32(bv1.y), to_tf32(bv1.z), to_tf32(bv1.w));
            *(float4*)&Bs[nb][brow][bcol]     = c0;
            *(float4*)&Bs[nb][brow + 8][bcol] = c1;
        }
        __syncthreads();
    }

    #pragma unroll
    for (int mi = 0; mi < 4; mi++) {
        int r = row0 + wm + mi * 16 + fr;
        #pragma unroll
        for (int ni = 0; ni < 4; ni++) {
            int c = col0 + wn + ni * 8 + 2 * fk;
            float bb0 = bias[c], bb1 = bias[c + 1];
            float2 v01 = make_float2(acc[mi][ni][0] + bb0, acc[mi][ni][1] + bb1);
            float2 v23 = make_float2(acc[mi][ni][2] + bb0, acc[mi][ni][3] + bb1);
            if (head_split) {
                int h = c >> 6, d = c & 63;
                int b0i = r >> 11, s0 = r & 2047;
                size_t i0 = ((((size_t)b0i * NH + h) * SS + s0) * HD) + d;
                *(float2*)&C[i0] = v01;
                int r2 = r + 8;
                int b1i = r2 >> 11, s1 = r2 & 2047;
                size_t i1 = ((((size_t)b1i * NH + h) * SS + s1) * HD) + d;
                *(float2*)&C[i1] = v23;
            } else {
                *(float2*)&C[(size_t)r * N + c]       = v01;
                *(float2*)&C[(size_t)(r + 8) * N + c] = v23;
            }
        }
    }
}

// ---------------------------------------------------------------------------
// Tensor-core flash attention (causal, tf32 mma both stages).
// Block = one (b,h) x 128-query tile. 8 warps, each owns a 16-row stripe
// (warp-private online softmax; reductions are intra-quad shfl only).
// KV tiles of 32 keys. K,V kept in natural [key][d] smem layout (stride 68:
// fragment loads hit banks 4*fr+fk -> conflict-free). Q frags live in regs.
// P round-trips through per-warp smem (stride 36), tf32-rounded before both
// the store and the l-sum so normalization matches the mma operand exactly.
// ---------------------------------------------------------------------------
#define ABQ 128
#define ABK 32
#define KSTR 68
#define PSTR 36

__global__ __launch_bounds__(256) void attn_tc(
    const float* __restrict__ Q, const float* __restrict__ K,
    const float* __restrict__ V, float* __restrict__ O)
{
    __shared__ float Ks[ABK][KSTR];        // [key][d]
    __shared__ float Vs[ABK][KSTR];        // [key][d]
    __shared__ float Ps[8][16][PSTR];      // per-warp P tile [row][key]

    const int bh   = blockIdx.y;
    const int qb   = gridDim.x - 1 - blockIdx.x;  // heavy blocks first
    const int q0   = qb * ABQ;
    const int tid  = threadIdx.x;
    const int warp = tid >> 5;
    const int lane = tid & 31;
    const int fr   = lane >> 2;    // 0..7
    const int fk   = lane & 3;     // 0..3
    const int wrow = warp * 16;

    const float* Qb = Q + (size_t)bh * SS * HD;
    const float* Kb = K + (size_t)bh * SS * HD;
    const float* Vb = V + (size_t)bh * SS * HD;

    // Q fragments (tf32), pinned in registers for the whole kernel.
    uint32_t Qf[8][4];
    {
        const float* qr0 = Qb + (size_t)(q0 + wrow + fr) * HD;
        const float* qr1 = qr0 + 8 * HD;
        #pragma unroll
        for (int ks = 0; ks < 8; ks++) {
            Qf[ks][0] = to_tf32u(qr0[ks * 8 + fk]);
            Qf[ks][1] = to_tf32u(qr1[ks * 8 + fk]);
            Qf[ks][2] = to_tf32u(qr0[ks * 8 + fk + 4]);
            Qf[ks][3] = to_tf32u(qr1[ks * 8 + fk + 4]);
        }
    }

    float Oacc[8][4];
    #pragma unroll
    for (int nt = 0; nt < 8; nt++)
        #pragma unroll
        for (int r = 0; r < 4; r++) Oacc[nt][r] = 0.f;

    float m0 = -INFINITY, m1 = -INFINITY, l0 = 0.f, l1 = 0.f;
    const float tsc = 0.18033688f;     // (1/sqrt(64)) * log2(e)

    const int r0g = q0 + wrow + fr;    // global row of acc c0/c1
    const int r1g = r0g + 8;           // global row of acc c2/c3

    const int ntiles = (q0 + ABQ) / ABK;

    // K/V load mapping: 2048 floats each / 256 threads = 2 float4 apiece
    const int lr  = tid >> 3;          // 0..31 (key)
    const int lc  = (tid & 7) * 8;     // 0,8,..,56

    for (int kt = 0; kt < ntiles; kt++) {
        const int k0 = kt * ABK;
        __syncthreads();   // prev tile's Vs/Ps fully consumed
        {
            const float* kp = Kb + (size_t)(k0 + lr) * HD + lc;
            const float* vp = Vb + (size_t)(k0 + lr) * HD + lc;
            float4 a = *(const float4*)kp;
            float4 b = *(const float4*)(kp + 4);
            float4 c = *(const float4*)vp;
            float4 d = *(const float4*)(vp + 4);
            Ks[lr][lc+0] = to_tf32(a.x); Ks[lr][lc+1] = to_tf32(a.y);
            Ks[lr][lc+2] = to_tf32(a.z); Ks[lr][lc+3] = to_tf32(a.w);
            Ks[lr][lc+4] = to_tf32(b.x); Ks[lr][lc+5] = to_tf32(b.y);
            Ks[lr][lc+6] = to_tf32(b.z); Ks[lr][lc+7] = to_tf32(b.w);
            Vs[lr][lc+0] = to_tf32(c.x); Vs[lr][lc+1] = to_tf32(c.y);
            Vs[lr][lc+2] = to_tf32(c.z); Vs[lr][lc+3] = to_tf32(c.w);
            Vs[lr][lc+4] = to_tf32(d.x); Vs[lr][lc+5] = to_tf32(d.y);
            Vs[lr][lc+6] = to_tf32(d.z); Vs[lr][lc+7] = to_tf32(d.w);
        }
        __syncthreads();

        // warp-uniform causal skip: tile entirely above this warp's rows
        if (k0 > q0 + wrow + 15) continue;

        // ---- S = Q K^T (16 x 32 per warp) ----
        float Sacc[4][4];
        #pragma unroll
        for (int nt = 0; nt < 4; nt++)
            #pragma unroll
            for (int r = 0; r < 4; r++) Sacc[nt][r] = 0.f;

        #pragma unroll
        for (int ks = 0; ks < 8; ks++) {
            uint32_t bf[4][2];
            #pragma unroll
            for (int nt = 0; nt < 4; nt++) {
                bf[nt][0] = __float_as_uint(Ks[nt * 8 + fr][ks * 8 + fk    ]);
                bf[nt][1] = __float_as_uint(Ks[nt * 8 + fr][ks * 8 + fk + 4]);
            }
            #pragma unroll
            for (int nt = 0; nt < 4; nt++)
                mma_tf32(Sacc[nt], Qf[ks][0], Qf[ks][1], Qf[ks][2], Qf[ks][3],
                         bf[nt][0], bf[nt][1]);
        }

        // ---- mask + scale into exponent domain ----
        float t[4][4];
        #pragma unroll
        for (int nt = 0; nt < 4; nt++) {
            int c0 = k0 + nt * 8 + 2 * fk;
            t[nt][0] = (c0     <= r0g) ? Sacc[nt][0] * tsc : -INFINITY;
            t[nt][1] = (c0 + 1 <= r0g) ? Sacc[nt][1] * tsc : -INFINITY;
            t[nt][2] = (c0     <= r1g) ? Sacc[nt][2] * tsc : -INFINITY;
            t[nt][3] = (c0 + 1 <= r1g) ? Sacc[nt][3] * tsc : -INFINITY;
        }

        // ---- row max (local 8 vals, then quad shfl) ----
        float mx0 = t[0][0], mx1 = t[0][2];
        #pragma unroll
        for (int nt = 0; nt < 4; nt++) {
            mx0 = fmaxf(mx0, fmaxf(t[nt][0], t[nt][1]));
            mx1 = fmaxf(mx1, fmaxf(t[nt][2], t[nt][3]));
        }
        mx0 = fmaxf(mx0, __shfl_xor_sync(0xFFFFFFFFu, mx0, 1));
        mx0 = fmaxf(mx0, __shfl_xor_sync(0xFFFFFFFFu, mx0, 2));
        mx1 = fmaxf(mx1, __shfl_xor_sync(0xFFFFFFFFu, mx1, 1));
        mx1 = fmaxf(mx1, __shfl_xor_sync(0xFFFFFFFFu, mx1, 2));

        float mn0 = fmaxf(m0, mx0);
        float mn1 = fmaxf(m1, mx1);
        float al0 = exp2f(m0 - mn0);
        float al1 = exp2f(m1 - mn1);
        m0 = mn0; m1 = mn1;

        // ---- p = exp2(t - m), tf32-rounded; store P; accumulate l ----
        float ps0 = 0.f, ps1 = 0.f;
        #pragma unroll
        for (int nt = 0; nt < 4; nt++) {
            float p0 = to_tf32(exp2f(t[nt][0] - m0));
            float p1 = to_tf32(exp2f(t[nt][1] - m0));
            float p2 = to_tf32(exp2f(t[nt][2] - m1));
            float p3 = to_tf32(exp2f(t[nt][3] - m1));
            ps0 += p0 + p1;
            ps1 += p2 + p3;
            *(float2*)&Ps[warp][fr    ][nt * 8 + 2 * fk] = make_float2(p0, p1);
            *(float2*)&Ps[warp][fr + 8][nt * 8 + 2 * fk] = make_float2(p2, p3);
        }
        ps0 += __shfl_xor_sync(0xFFFFFFFFu, ps0, 1);
        ps0 += __shfl_xor_sync(0xFFFFFFFFu, ps0, 2);
        ps1 += __shfl_xor_sync(0xFFFFFFFFu, ps1, 1);
        ps1 += __shfl_xor_sync(0xFFFFFFFFu, ps1, 2);
        l0 = l0 * al0 + ps0;
        l1 = l1 * al1 + ps1;

        // rescale O accumulators
        #pragma unroll
        for (int nt = 0; nt < 8; nt++) {
            Oacc[nt][0] *= al0; Oacc[nt][1] *= al0;
            Oacc[nt][2] *= al1; Oacc[nt][3] *= al1;
        }
        __syncwarp();

        // ---- O += P V  (16 x 64 per warp, k = 32) ----
        #pragma unroll
        for (int ks = 0; ks < 4; ks++) {
            uint32_t a0 = __float_as_uint(Ps[warp][fr    ][ks * 8 + fk    ]);
            uint32_t a1 = __float_as_uint(Ps[warp][fr + 8][ks * 8 + fk    ]);
            uint32_t a2 = __float_as_uint(Ps[warp][fr    ][ks * 8 + fk + 4]);
            uint32_t a3 = __float_as_uint(Ps[warp][fr + 8][ks * 8 + fk + 4]);
            #pragma unroll
            for (int nt = 0; nt < 8; nt++) {
                uint32_t b0 = __float_as_uint(Vs[ks * 8 + fk    ][nt * 8 + fr]);
                uint32_t b1 = __float_as_uint(Vs[ks * 8 + fk + 4][nt * 8 + fr]);
                mma_tf32(Oacc[nt], a0, a1, a2, a3, b0, b1);
            }
        }
    }

    // ---- epilogue: normalize and write [b, s, h*64+d] ----
    const int b = bh >> 4, h = bh & 15;
    const float inv0 = 1.f / l0;
    const float inv1 = 1.f / l1;
    float* O0 = O + ((size_t)(b * SS + r0g)) * DM + h * HD;
    float* O1 = O + ((size_t)(b * SS + r1g)) * DM + h * HD;
    #pragma unroll
    for (int nt = 0; nt < 8; nt++) {
        int d = nt * 8 + 2 * fk;
        *(float2*)(O0 + d) = make_float2(Oacc[nt][0] * inv0, Oacc[nt][1] * inv0);
        *(float2*)(O1 + d) = make_float2(Oacc[nt][2] * inv1, Oacc[nt][3] * inv1);
    }
}

// ---------------------------------------------------------------------------
extern "C" void kernel_launch(void* const* d_in, const int* in_sizes, int n_in,
                              void* d_out, int out_size)
{
    const float* x  = (const float*)d_in[0];
    const float* Wq = (const float*)d_in[1];
    const float* bq = (const float*)d_in[2];
    const float* Wk = (const float*)d_in[3];
    const float* bk = (const float*)d_in[4];
    const float* Wv = (const float*)d_in[5];
    const float* bv = (const float*)d_in[6];
    const float* Wo = (const float*)d_in[7];
    const float* bo = (const float*)d_in[8];

    float *qp, *kp, *vp, *ap;
    cudaGetSymbolAddress((void**)&qp, g_Q);
    cudaGetSymbolAddress((void**)&kp, g_K);
    cudaGetSymbolAddress((void**)&vp, g_V);
    cudaGetSymbolAddress((void**)&ap, g_att);

    dim3 gg(DM / 128, MROWS / 128);   // (8, 32)
    gemm_tf32<<<gg, 256>>>(x, Wq, bq, qp, MROWS, DM, DM, 1);
    gemm_tf32<<<gg, 256>>>(x, Wk, bk, kp, MROWS, DM, DM, 1);
    gemm_tf32<<<gg, 256>>>(x, Wv, bv, vp, MROWS, DM, DM, 1);

    attn_tc<<<dim3(SS / ABQ, BB * NH), 256>>>(qp, kp, vp, ap);

    gemm_tf32<<<gg, 256>>>(ap, Wo, bo, (float*)d_out, MROWS, DM, DM, 0);
}

// round 6
// speedup vs baseline: 4.1347x; 1.1133x over previous
#include <cuda_runtime.h>
#include <math.h>
#include <stdint.h>

// Problem constants
#define BB 2
#define SS 2048
#define DM 1024
#define NH 16
#define HD 64
#define MROWS (BB*SS)        // 4096

// Scratch (device globals; no allocations allowed)
__device__ float g_Q[BB*NH*SS*HD];     // [b,h,s,d]
__device__ float g_K[BB*NH*SS*HD];
__device__ float g_V[BB*NH*SS*HD];
__device__ float g_att[BB*SS*DM];      // [b,s, h*64+d]

// ---------------------------------------------------------------------------
// tf32 helpers
// ---------------------------------------------------------------------------
__device__ __forceinline__ float to_tf32(float x) {
    uint32_t u = __float_as_uint(x), y;
    asm("cvt.rna.tf32.f32 %0, %1;" : "=r"(y) : "r"(u));
    return __uint_as_float(y);
}
__device__ __forceinline__ uint32_t to_tf32u(float x) {
    uint32_t u = __float_as_uint(x), y;
    asm("cvt.rna.tf32.f32 %0, %1;" : "=r"(y) : "r"(u));
    return y;
}

__device__ __forceinline__ void mma_tf32(float c[4],
    uint32_t a0, uint32_t a1, uint32_t a2, uint32_t a3,
    uint32_t b0, uint32_t b1)
{
    asm volatile(
        "mma.sync.aligned.m16n8k8.row.col.f32.tf32.tf32.f32 "
        "{%0,%1,%2,%3}, {%4,%5,%6,%7}, {%8,%9}, {%0,%1,%2,%3};"
        : "+f"(c[0]), "+f"(c[1]), "+f"(c[2]), "+f"(c[3])
        : "r"(a0), "r"(a1), "r"(a2), "r"(a3), "r"(b0), "r"(b1));
}

// ---------------------------------------------------------------------------
// tf32 tensor-core GEMM: C[M,N] = A[M,K] @ B[K,N] + bias[N]   (unchanged R3)
// ---------------------------------------------------------------------------
#define ASTRIDE 20
#define BSTRIDE 136

__global__ __launch_bounds__(256) void gemm_tf32(
    const float* __restrict__ A, const float* __restrict__ B,
    const float* __restrict__ bias, float* __restrict__ C,
    int M, int N, int K, int head_split)
{
    __shared__ float As[2][128][ASTRIDE];   // [m][k], k-padded
    __shared__ float Bs[2][16][BSTRIDE];    // [k][n], n-padded

    const int tid  = threadIdx.x;
    const int warp = tid >> 5;
    const int lane = tid & 31;
    const int wm   = (warp >> 2) * 64;
    const int wn   = (warp & 3) * 32;
    const int row0 = blockIdx.y * 128;
    const int col0 = blockIdx.x * 128;

    const int arow = tid >> 2;
    const int akp  = (tid & 3) * 4;
    const int brow = tid >> 5;
    const int bcol = (tid & 31) * 4;

    const float* Ap0 = A + (size_t)(row0 + arow) * K + akp;
    const float* Ap1 = A + (size_t)(row0 + arow + 64) * K + akp;
    const float* Bp0 = B + (size_t)brow * N + col0 + bcol;
    const float* Bp1 = B + (size_t)(brow + 8) * N + col0 + bcol;

    float acc[4][4][4];
    #pragma unroll
    for (int i = 0; i < 4; i++)
        #pragma unroll
        for (int j = 0; j < 4; j++)
            #pragma unroll
            for (int r = 0; r < 4; r++) acc[i][j][r] = 0.f;

    const int NT = K / 16;

    {
        float4 a0 = *(const float4*)Ap0;
        float4 a1 = *(const float4*)Ap1;
        float4 b0 = *(const float4*)Bp0;
        float4 b1 = *(const float4*)Bp1;
        As[0][arow][akp+0] = to_tf32(a0.x);
        As[0][arow][akp+1] = to_tf32(a0.y);
        As[0][arow][akp+2] = to_tf32(a0.z);
        As[0][arow][akp+3] = to_tf32(a0.w);
        As[0][arow+64][akp+0] = to_tf32(a1.x);
        As[0][arow+64][akp+1] = to_tf32(a1.y);
        As[0][arow+64][akp+2] = to_tf32(a1.z);
        As[0][arow+64][akp+3] = to_tf32(a1.w);
        float4 c0 = make_float4(to_tf32(b0.x), to_tf32(b0.y), to_tf32(b0.z), to_tf32(b0.w));
        float4 c1 = make_float4(to_tf32(b1.x), to_tf32(b1.y), to_tf32(b1.z), to_tf32(b1.w));
        *(float4*)&Bs[0][brow][bcol]     = c0;
        *(float4*)&Bs[0][brow + 8][bcol] = c1;
    }
    __syncthreads();

    const int fr = lane >> 2;
    const int fk = lane & 3;

    float4 av0, av1, bv0, bv1;

    for (int kt = 0; kt < NT; kt++) {
        const int cur = kt & 1;
        const bool pf = (kt + 1) < NT;

        if (pf) {
            av0 = *(const float4*)(Ap0 + (size_t)(kt + 1) * 16);
            av1 = *(const float4*)(Ap1 + (size_t)(kt + 1) * 16);
            bv0 = *(const float4*)(Bp0 + (size_t)(kt + 1) * 16 * N);
            bv1 = *(const float4*)(Bp1 + (size_t)(kt + 1) * 16 * N);
        }

        #pragma unroll
        for (int ks = 0; ks < 16; ks += 8) {
            uint32_t af[4][4];
            uint32_t bf[4][2];
            #pragma unroll
            for (int mi = 0; mi < 4; mi++) {
                int r = wm + mi * 16 + fr;
                af[mi][0] = __float_as_uint(As[cur][r    ][ks + fk    ]);
                af[mi][1] = __float_as_uint(As[cur][r + 8][ks + fk    ]);
                af[mi][2] = __float_as_uint(As[cur][r    ][ks + fk + 4]);
                af[mi][3] = __float_as_uint(As[cur][r + 8][ks + fk + 4]);
            }
            #pragma unroll
            for (int ni = 0; ni < 4; ni++) {
                int c = wn + ni * 8 + fr;
                bf[ni][0] = __float_as_uint(Bs[cur][ks + fk    ][c]);
                bf[ni][1] = __float_as_uint(Bs[cur][ks + fk + 4][c]);
            }
            #pragma unroll
            for (int mi = 0; mi < 4; mi++)
                #pragma unroll
                for (int ni = 0; ni < 4; ni++)
                    mma_tf32(acc[mi][ni],
                             af[mi][0], af[mi][1], af[mi][2], af[mi][3],
                             bf[ni][0], bf[ni][1]);
        }

        if (pf) {
            const int nb = 1 - cur;
            As[nb][arow][akp+0] = to_tf32(av0.x);
            As[nb][arow][akp+1] = to_tf32(av0.y);
            As[nb][arow][akp+2] = to_tf32(av0.z);
            As[nb][arow][akp+3] = to_tf32(av0.w);
            As[nb][arow+64][akp+0] = to_tf32(av1.x);
            As[nb][arow+64][akp+1] = to_tf32(av1.y);
            As[nb][arow+64][akp+2] = to_tf32(av1.z);
            As[nb][arow+64][akp+3] = to_tf32(av1.w);
            float4 c0 = make_float4(to_tf32(bv0.x), to_tf32(bv0.y), to_tf32(bv0.z), to_tf32(bv0.w));
            float4 c1 = make_float4(to_tf32(bv1.x), to_tf32(bv1.y), to_tf32(bv1.z), to_tf32(bv1.w));
            *(float4*)&Bs[nb][brow][bcol]     = c0;
            *(float4*)&Bs[nb][brow + 8][bcol] = c1;
        }
        __syncthreads();
    }

    #pragma unroll
    for (int mi = 0; mi < 4; mi++) {
        int r = row0 + wm + mi * 16 + fr;
        #pragma unroll
        for (int ni = 0; ni < 4; ni++) {
            int c = col0 + wn + ni * 8 + 2 * fk;
            float bb0 = bias[c], bb1 = bias[c + 1];
            float2 v01 = make_float2(acc[mi][ni][0] + bb0, acc[mi][ni][1] + bb1);
            float2 v23 = make_float2(acc[mi][ni][2] + bb0, acc[mi][ni][3] + bb1);
            if (head_split) {
                int h = c >> 6, d = c & 63;
                int b0i = r >> 11, s0 = r & 2047;
                size_t i0 = ((((size_t)b0i * NH + h) * SS + s0) * HD) + d;
                *(float2*)&C[i0] = v01;
                int r2 = r + 8;
                int b1i = r2 >> 11, s1 = r2 & 2047;
                size_t i1 = ((((size_t)b1i * NH + h) * SS + s1) * HD) + d;
                *(float2*)&C[i1] = v23;
            } else {
                *(float2*)&C[(size_t)r * N + c]       = v01;
                *(float2*)&C[(size_t)(r + 8) * N + c] = v23;
            }
        }
    }
}

// ---------------------------------------------------------------------------
// Tensor-core flash attention (causal, tf32 mma both stages). R6:
//  - 64-key load stages (2 barriers per 64 keys), computed in two 32-key halves
//  - K stride 68 (bank 4*fr+fk), V stride 72 (bank 8*fk+fr): both conflict-free
//  - float4 smem stores with register-side tf32 cvt
//  - P kept in registers: S-accum layout -> PV A-fragment layout via quad shfl
// ---------------------------------------------------------------------------
#define ABQ 128
#define LKEYS 64
#define KSTR 68
#define VSTR 72

__global__ __launch_bounds__(256) void attn_tc(
    const float* __restrict__ Q, const float* __restrict__ K,
    const float* __restrict__ V, float* __restrict__ O)
{
    __shared__ float Ks[LKEYS][KSTR];      // [key][d]
    __shared__ float Vs[LKEYS][VSTR];      // [key][d]

    const int bh   = blockIdx.y;
    const int qb   = gridDim.x - 1 - blockIdx.x;  // heavy blocks first
    const int q0   = qb * ABQ;
    const int tid  = threadIdx.x;
    const int warp = tid >> 5;
    const int lane = tid & 31;
    const int fr   = lane >> 2;    // 0..7
    const int fk   = lane & 3;     // 0..3
    const int wrow = warp * 16;

    const float* Qb = Q + (size_t)bh * SS * HD;
    const float* Kb = K + (size_t)bh * SS * HD;
    const float* Vb = V + (size_t)bh * SS * HD;

    // Q fragments (tf32), pinned in registers for the whole kernel.
    uint32_t Qf[8][4];
    {
        const float* qr0 = Qb + (size_t)(q0 + wrow + fr) * HD;
        const float* qr1 = qr0 + 8 * HD;
        #pragma unroll
        for (int ks = 0; ks < 8; ks++) {
            Qf[ks][0] = to_tf32u(qr0[ks * 8 + fk]);
            Qf[ks][1] = to_tf32u(qr1[ks * 8 + fk]);
            Qf[ks][2] = to_tf32u(qr0[ks * 8 + fk + 4]);
            Qf[ks][3] = to_tf32u(qr1[ks * 8 + fk + 4]);
        }
    }

    float Oacc[8][4];
    #pragma unroll
    for (int nt = 0; nt < 8; nt++)
        #pragma unroll
        for (int r = 0; r < 4; r++) Oacc[nt][r] = 0.f;

    float m0 = -INFINITY, m1 = -INFINITY, l0 = 0.f, l1 = 0.f;
    const float tsc = 0.18033688f;     // (1/sqrt(64)) * log2(e)

    const int r0g = q0 + wrow + fr;    // global row of acc c0/c1
    const int r1g = r0g + 8;           // global row of acc c2/c3

    const int nload = (q0 + ABQ) / LKEYS;
    const int j0sl  = (lane & ~3) | (fk >> 1);   // shuffle src for col fk
    const int j2sl  = j0sl + 2;                  // shuffle src for col fk+4
    const bool oddc = (fk & 1);

    for (int lt = 0; lt < nload; lt++) {
        const int k0 = lt * LKEYS;
        __syncthreads();   // previous stage fully consumed
        #pragma unroll
        for (int i = 0; i < 4; i++) {
            int idx = tid + 256 * i;        // 0..1023
            int row = idx >> 4;             // 0..63
            int col = (idx & 15) * 4;       // 0..60
            float4 kv = *(const float4*)(Kb + (size_t)(k0 + row) * HD + col);
            float4 vv = *(const float4*)(Vb + (size_t)(k0 + row) * HD + col);
            kv.x = to_tf32(kv.x); kv.y = to_tf32(kv.y);
            kv.z = to_tf32(kv.z); kv.w = to_tf32(kv.w);
            vv.x = to_tf32(vv.x); vv.y = to_tf32(vv.y);
            vv.z = to_tf32(vv.z); vv.w = to_tf32(vv.w);
            *(float4*)&Ks[row][col] = kv;
            *(float4*)&Vs[row][col] = vv;
        }
        __syncthreads();

        #pragma unroll
        for (int half = 0; half < 2; half++) {
            const int kh = k0 + half * 32;
            if (kh > q0 + wrow + 15) continue;   // warp-uniform causal skip
            const int kb = half * 32;

            // ---- S = Q K^T (16 x 32 per warp) ----
            float Sacc[4][4];
            #pragma unroll
            for (int nt = 0; nt < 4; nt++)
                #pragma unroll
                for (int r = 0; r < 4; r++) Sacc[nt][r] = 0.f;

            #pragma unroll
            for (int ks = 0; ks < 8; ks++) {
                uint32_t bf[4][2];
                #pragma unroll
                for (int nt = 0; nt < 4; nt++) {
                    bf[nt][0] = __float_as_uint(Ks[kb + nt * 8 + fr][ks * 8 + fk    ]);
                    bf[nt][1] = __float_as_uint(Ks[kb + nt * 8 + fr][ks * 8 + fk + 4]);
                }
                #pragma unroll
                for (int nt = 0; nt < 4; nt++)
                    mma_tf32(Sacc[nt], Qf[ks][0], Qf[ks][1], Qf[ks][2], Qf[ks][3],
                             bf[nt][0], bf[nt][1]);
            }

            // ---- mask + scale into exponent (log2) domain ----
            float t[4][4];
            #pragma unroll
            for (int nt = 0; nt < 4; nt++) {
                int c0 = kh + nt * 8 + 2 * fk;
                t[nt][0] = (c0     <= r0g) ? Sacc[nt][0] * tsc : -INFINITY;
                t[nt][1] = (c0 + 1 <= r0g) ? Sacc[nt][1] * tsc : -INFINITY;
                t[nt][2] = (c0     <= r1g) ? Sacc[nt][2] * tsc : -INFINITY;
                t[nt][3] = (c0 + 1 <= r1g) ? Sacc[nt][3] * tsc : -INFINITY;
            }

            // ---- row max (local, then quad shfl) ----
            float mx0 = t[0][0], mx1 = t[0][2];
            #pragma unroll
            for (int nt = 0; nt < 4; nt++) {
                mx0 = fmaxf(mx0, fmaxf(t[nt][0], t[nt][1]));
                mx1 = fmaxf(mx1, fmaxf(t[nt][2], t[nt][3]));
            }
            mx0 = fmaxf(mx0, __shfl_xor_sync(0xFFFFFFFFu, mx0, 1));
            mx0 = fmaxf(mx0, __shfl_xor_sync(0xFFFFFFFFu, mx0, 2));
            mx1 = fmaxf(mx1, __shfl_xor_sync(0xFFFFFFFFu, mx1, 1));
            mx1 = fmaxf(mx1, __shfl_xor_sync(0xFFFFFFFFu, mx1, 2));

            float mn0 = fmaxf(m0, mx0);
            float mn1 = fmaxf(m1, mx1);
            float al0 = exp2f(m0 - mn0);
            float al1 = exp2f(m1 - mn1);
            m0 = mn0; m1 = mn1;

            // ---- p = exp2(t - m), tf32-rounded; accumulate l ----
            float p[4][4];
            float ps0 = 0.f, ps1 = 0.f;
            #pragma unroll
            for (int nt = 0; nt < 4; nt++) {
                p[nt][0] = to_tf32(exp2f(t[nt][0] - m0));
                p[nt][1] = to_tf32(exp2f(t[nt][1] - m0));
                p[nt][2] = to_tf32(exp2f(t[nt][2] - m1));
                p[nt][3] = to_tf32(exp2f(t[nt][3] - m1));
                ps0 += p[nt][0] + p[nt][1];
                ps1 += p[nt][2] + p[nt][3];
            }
            ps0 += __shfl_xor_sync(0xFFFFFFFFu, ps0, 1);
            ps0 += __shfl_xor_sync(0xFFFFFFFFu, ps0, 2);
            ps1 += __shfl_xor_sync(0xFFFFFFFFu, ps1, 1);
            ps1 += __shfl_xor_sync(0xFFFFFFFFu, ps1, 2);
            l0 = l0 * al0 + ps0;
            l1 = l1 * al1 + ps1;

            // rescale O accumulators
            #pragma unroll
            for (int nt = 0; nt < 8; nt++) {
                Oacc[nt][0] *= al0; Oacc[nt][1] *= al0;
                Oacc[nt][2] *= al1; Oacc[nt][3] *= al1;
            }

            // ---- redistribute p (accum layout) -> PV A-fragments via shfl ----
            // accum: lane(fr,fk) holds cols {2fk,2fk+1}; A-frag needs cols fk, fk+4
            uint32_t Pf[4][4];
            #pragma unroll
            for (int g = 0; g < 4; g++) {
                float q00 = __shfl_sync(0xFFFFFFFFu, p[g][0], j0sl);
                float q01 = __shfl_sync(0xFFFFFFFFu, p[g][1], j0sl);
                float q10 = __shfl_sync(0xFFFFFFFFu, p[g][2], j0sl);
                float q11 = __shfl_sync(0xFFFFFFFFu, p[g][3], j0sl);
                float q20 = __shfl_sync(0xFFFFFFFFu, p[g][0], j2sl);
                float q21 = __shfl_sync(0xFFFFFFFFu, p[g][1], j2sl);
                float q30 = __shfl_sync(0xFFFFFFFFu, p[g][2], j2sl);
                float q31 = __shfl_sync(0xFFFFFFFFu, p[g][3], j2sl);
                Pf[g][0] = __float_as_uint(oddc ? q01 : q00);
                Pf[g][1] = __float_as_uint(oddc ? q11 : q10);
                Pf[g][2] = __float_as_uint(oddc ? q21 : q20);
                Pf[g][3] = __float_as_uint(oddc ? q31 : q30);
            }

            // ---- O += P V  (16 x 64 per warp, k = 32) ----
            #pragma unroll
            for (int g = 0; g < 4; g++) {
                #pragma unroll
                for (int nt = 0; nt < 8; nt++) {
                    uint32_t b0 = __float_as_uint(Vs[kb + g * 8 + fk    ][nt * 8 + fr]);
                    uint32_t b1 = __float_as_uint(Vs[kb + g * 8 + fk + 4][nt * 8 + fr]);
                    mma_tf32(Oacc[nt], Pf[g][0], Pf[g][1], Pf[g][2], Pf[g][3], b0, b1);
                }
            }
        }
    }

    // ---- epilogue: normalize and write [b, s, h*64+d] ----
    const int b = bh >> 4, h = bh & 15;
    const float inv0 = 1.f / l0;
    const float inv1 = 1.f / l1;
    float* O0 = O + ((size_t)(b * SS + r0g)) * DM + h * HD;
    float* O1 = O + ((size_t)(b * SS + r1g)) * DM + h * HD;
    #pragma unroll
    for (int nt = 0; nt < 8; nt++) {
        int d = nt * 8 + 2 * fk;
        *(float2*)(O0 + d) = make_float2(Oacc[nt][0] * inv0, Oacc[nt][1] * inv0);
        *(float2*)(O1 + d) = make_float2(Oacc[nt][2] * inv1, Oacc[nt][3] * inv1);
    }
}

// ---------------------------------------------------------------------------
extern "C" void kernel_launch(void* const* d_in, const int* in_sizes, int n_in,
                              void* d_out, int out_size)
{
    const float* x  = (const float*)d_in[0];
    const float* Wq = (const float*)d_in[1];
    const float* bq = (const float*)d_in[2];
    const float* Wk = (const float*)d_in[3];
    const float* bk = (const float*)d_in[4];
    const float* Wv = (const float*)d_in[5];
    const float* bv = (const float*)d_in[6];
    const float* Wo = (const float*)d_in[7];
    const float* bo = (const float*)d_in[8];

    float *qp, *kp, *vp, *ap;
    cudaGetSymbolAddress((void**)&qp, g_Q);
    cudaGetSymbolAddress((void**)&kp, g_K);
    cudaGetSymbolAddress((void**)&vp, g_V);
    cudaGetSymbolAddress((void**)&ap, g_att);

    dim3 gg(DM / 128, MROWS / 128);   // (8, 32)
    gemm_tf32<<<gg, 256>>>(x, Wq, bq, qp, MROWS, DM, DM, 1);
    gemm_tf32<<<gg, 256>>>(x, Wk, bk, kp, MROWS, DM, DM, 1);
    gemm_tf32<<<gg, 256>>>(x, Wv, bv, vp, MROWS, DM, DM, 1);

    attn_tc<<<dim3(SS / ABQ, BB * NH), 256>>>(qp, kp, vp, ap);

    gemm_tf32<<<gg, 256>>>(ap, Wo, bo, (float*)d_out, MROWS, DM, DM, 0);
}

// round 8
// speedup vs baseline: 4.3380x; 1.0492x over previous
#include <cuda_runtime.h>
#include <math.h>
#include <stdint.h>

// Problem constants
#define BB 2
#define SS 2048
#define DM 1024
#define NH 16
#define HD 64
#define MROWS (BB*SS)        // 4096

// Scratch (device globals; no allocations allowed)
__device__ float g_Q[BB*NH*SS*HD];     // [b,h,s,d]  (tf32-rounded values)
__device__ float g_K[BB*NH*SS*HD];
__device__ float g_V[BB*NH*SS*HD];
__device__ float g_att[BB*SS*DM];      // [b,s, h*64+d] (tf32-rounded)
__device__ float g_xc[MROWS*DM];       // tf32-rounded x
__device__ float g_Wc[4*DM*DM];        // tf32-rounded Wq,Wk,Wv,Wo

// ---------------------------------------------------------------------------
// helpers
// ---------------------------------------------------------------------------
__device__ __forceinline__ float to_tf32(float x) {
    uint32_t u = __float_as_uint(x), y;
    asm("cvt.rna.tf32.f32 %0, %1;" : "=r"(y) : "r"(u));
    return __uint_as_float(y);
}

__device__ __forceinline__ void mma_tf32(float c[4],
    uint32_t a0, uint32_t a1, uint32_t a2, uint32_t a3,
    uint32_t b0, uint32_t b1)
{
    asm volatile(
        "mma.sync.aligned.m16n8k8.row.col.f32.tf32.tf32.f32 "
        "{%0,%1,%2,%3}, {%4,%5,%6,%7}, {%8,%9}, {%0,%1,%2,%3};"
        : "+f"(c[0]), "+f"(c[1]), "+f"(c[2]), "+f"(c[3])
        : "r"(a0), "r"(a1), "r"(a2), "r"(a3), "r"(b0), "r"(b1));
}

__device__ __forceinline__ uint32_t smem_u32(const void* p) {
    uint32_t a;
    asm("{ .reg .u64 t; cvta.to.shared.u64 t, %1; cvt.u32.u64 %0, t; }"
        : "=r"(a) : "l"(p));
    return a;
}

#define CP16(dst, src) \
    asm volatile("cp.async.cg.shared.global [%0], [%1], 16;\n" \
                 :: "r"(dst), "l"(src))
#define CP_COMMIT() asm volatile("cp.async.commit_group;\n")
#define CP_WAIT0()  asm volatile("cp.async.wait_group 0;\n")
#define CP_WAIT1()  asm volatile("cp.async.wait_group 1;\n")

// ---------------------------------------------------------------------------
// prep: tf32-round x and the four weight matrices into scratch
// ---------------------------------------------------------------------------
__global__ __launch_bounds__(256) void cvt_x_kernel(const float* __restrict__ s,
                                                    float* __restrict__ d)
{
    int i = (blockIdx.x * 256 + threadIdx.x) * 4;
    float4 v = *(const float4*)(s + i);
    v.x = to_tf32(v.x); v.y = to_tf32(v.y);
    v.z = to_tf32(v.z); v.w = to_tf32(v.w);
    *(float4*)(d + i) = v;
}

__global__ __launch_bounds__(256) void cvt_w_kernel(
    const float* __restrict__ w0, const float* __restrict__ w1,
    const float* __restrict__ w2, const float* __restrict__ w3,
    float* __restrict__ d)
{
    const float* s = (blockIdx.y == 0) ? w0 : (blockIdx.y == 1) ? w1
                   : (blockIdx.y == 2) ? w2 : w3;
    int i = (blockIdx.x * 256 + threadIdx.x) * 4;
    float4 v = *(const float4*)(s + i);
    v.x = to_tf32(v.x); v.y = to_tf32(v.y);
    v.z = to_tf32(v.z); v.w = to_tf32(v.w);
    *(float4*)(d + (size_t)blockIdx.y * DM * DM + i) = v;
}

// ---------------------------------------------------------------------------
// 3-stage cp.async tf32 GEMM: C[M,N] = A[M,K] @ B[K,N] + bias[N]
// A, B must already hold tf32-rounded values. 128x128 tile, BK=16, 256 thr.
// round_out: tf32-round the output (for tensors feeding later tf32 mmas).
// head_split: write C in [b,h,s,d] layout.
// ---------------------------------------------------------------------------
#define GSTAGES 3
#define ASTRIDE 20
#define BSTRIDE 136
#define ASZ (128*ASTRIDE)
#define BSZ (16*BSTRIDE)
#define GEMM_SMEM ((GSTAGES*(ASZ+BSZ))*4)

__global__ __launch_bounds__(256) void gemm_tf32_pipe(
    const float* __restrict__ A, const float* __restrict__ B,
    const float* __restrict__ bias, float* __restrict__ C,
    int M, int N, int K, int head_split, int round_out)
{
    extern __shared__ float sm[];

    const int tid  = threadIdx.x;
    const int warp = tid >> 5;
    const int lane = tid & 31;
    const int wm   = (warp >> 2) * 64;
    const int wn   = (warp & 3) * 32;
    const int row0 = blockIdx.y * 128;
    const int col0 = blockIdx.x * 128;

    const int arow = tid >> 2;              // 0..63
    const int akp  = (tid & 3) * 4;         // 0,4,8,12
    const int brow = tid >> 5;              // 0..7
    const int bcol = (tid & 31) * 4;
    const int fr   = lane >> 2;
    const int fk   = lane & 3;

    const float* Ag0 = A + (size_t)(row0 + arow) * K + akp;
    const float* Ag1 = A + (size_t)(row0 + arow + 64) * K + akp;
    const float* Bg  = B + col0 + bcol;

    const uint32_t sbase = smem_u32(sm);
    const uint32_t ad0 = sbase + (arow * ASTRIDE + akp) * 4;
    const uint32_t ad1 = sbase + ((arow + 64) * ASTRIDE + akp) * 4;
    const uint32_t bd0 = sbase + (GSTAGES * ASZ + brow * BSTRIDE + bcol) * 4;
    const uint32_t bd1 = sbase + (GSTAGES * ASZ + (brow + 8) * BSTRIDE + bcol) * 4;

    float acc[4][4][4];
    #pragma unroll
    for (int i = 0; i < 4; i++)
        #pragma unroll
        for (int j = 0; j < 4; j++)
            #pragma unroll
            for (int r = 0; r < 4; r++) acc[i][j][r] = 0.f;

    const int NT = K / 16;   // 64

    // issue stage for k-tile kt into smem slot s
    #define G_ISSUE(kt, s) do {                                         \
        uint32_t off_a = (uint32_t)(s) * (ASZ * 4);                     \
        uint32_t off_b = (uint32_t)(s) * (BSZ * 4);                     \
        CP16(ad0 + off_a, Ag0 + (size_t)(kt) * 16);                     \
        CP16(ad1 + off_a, Ag1 + (size_t)(kt) * 16);                     \
        CP16(bd0 + off_b, Bg + (size_t)((kt) * 16 + brow) * N);         \
        CP16(bd1 + off_b, Bg + (size_t)((kt) * 16 + brow + 8) * N);     \
        CP_COMMIT();                                                    \
    } while (0)

    G_ISSUE(0, 0);
    G_ISSUE(1, 1);

    for (int kt = 0; kt < NT; kt++) {
        const int cur = kt % GSTAGES;
        CP_WAIT1();            // group kt complete (one later group may pend)
        __syncthreads();
        if (kt + 2 < NT) {
            G_ISSUE(kt + 2, (kt + 2) % GSTAGES);
        } else {
            CP_COMMIT();       // empty group keeps wait_group accounting uniform
        }

        const float* As = sm + cur * ASZ;                  // [128][ASTRIDE]
        const float* Bs = sm + GSTAGES * ASZ + cur * BSZ;  // [16][BSTRIDE]

        #pragma unroll
        for (int ks = 0; ks < 16; ks += 8) {
            uint32_t af[4][4];
            uint32_t bf[4][2];
            #pragma unroll
            for (int mi = 0; mi < 4; mi++) {
                int r = wm + mi * 16 + fr;
                af[mi][0] = __float_as_uint(As[(r    ) * ASTRIDE + ks + fk    ]);
                af[mi][1] = __float_as_uint(As[(r + 8) * ASTRIDE + ks + fk    ]);
                af[mi][2] = __float_as_uint(As[(r    ) * ASTRIDE + ks + fk + 4]);
                af[mi][3] = __float_as_uint(As[(r + 8) * ASTRIDE + ks + fk + 4]);
            }
            #pragma unroll
            for (int ni = 0; ni < 4; ni++) {
                int c = wn + ni * 8 + fr;
                bf[ni][0] = __float_as_uint(Bs[(ks + fk    ) * BSTRIDE + c]);
                bf[ni][1] = __float_as_uint(Bs[(ks + fk + 4) * BSTRIDE + c]);
            }
            #pragma unroll
            for (int mi = 0; mi < 4; mi++)
                #pragma unroll
                for (int ni = 0; ni < 4; ni++)
                    mma_tf32(acc[mi][ni],
                             af[mi][0], af[mi][1], af[mi][2], af[mi][3],
                             bf[ni][0], bf[ni][1]);
        }
        __syncthreads();
    }

    // ---- epilogue ----
    #pragma unroll
    for (int mi = 0; mi < 4; mi++) {
        int r = row0 + wm + mi * 16 + fr;
        #pragma unroll
        for (int ni = 0; ni < 4; ni++) {
            int c = col0 + wn + ni * 8 + 2 * fk;
            float bb0 = bias[c], bb1 = bias[c + 1];
            float v0 = acc[mi][ni][0] + bb0, v1 = acc[mi][ni][1] + bb1;
            float v2 = acc[mi][ni][2] + bb0, v3 = acc[mi][ni][3] + bb1;
            if (round_out) {
                v0 = to_tf32(v0); v1 = to_tf32(v1);
                v2 = to_tf32(v2); v3 = to_tf32(v3);
            }
            float2 v01 = make_float2(v0, v1);
            float2 v23 = make_float2(v2, v3);
            if (head_split) {
                int h = c >> 6, d = c & 63;
                int b0i = r >> 11, s0 = r & 2047;
                size_t i0 = ((((size_t)b0i * NH + h) * SS + s0) * HD) + d;
                *(float2*)&C[i0] = v01;
                int r2 = r + 8;
                int b1i = r2 >> 11, s1 = r2 & 2047;
                size_t i1 = ((((size_t)b1i * NH + h) * SS + s1) * HD) + d;
                *(float2*)&C[i1] = v23;
            } else {
                *(float2*)&C[(size_t)r * N + c]       = v01;
                *(float2*)&C[(size_t)(r + 8) * N + c] = v23;
            }
        }
    }
}

// ---------------------------------------------------------------------------
// Tensor-core flash attention (causal, tf32 mma both stages).
//  - inputs already tf32-rounded (gemm epilogue) -> no cvt in load paths
//  - 2-stage double-buffered cp.async K/V loads (overlap with compute)
//  - K stride 68 / V stride 72 conflict-free fragment banks
//  - P in registers via quad shuffles; output written tf32-rounded
// ---------------------------------------------------------------------------
#define ABQ 128
#define LKEYS 64
#define KSTR 68
#define VSTR 72
#define KS_FL (LKEYS*KSTR)        // floats per K stage
#define VS_FL (LKEYS*VSTR)
#define ATTN_SMEM ((2*KS_FL + 2*VS_FL)*4)

__global__ __launch_bounds__(256) void attn_tc(
    const float* __restrict__ Q, const float* __restrict__ K,
    const float* __restrict__ V, float* __restrict__ O)
{
    extern __shared__ float sm[];
    // layout: K stage0 | K stage1 | V stage0 | V stage1

    const int bh   = blockIdx.y;
    const int qb   = gridDim.x - 1 - blockIdx.x;  // heavy blocks first
    const int q0   = qb * ABQ;
    const int tid  = threadIdx.x;
    const int warp = tid >> 5;
    const int lane = tid & 31;
    const int fr   = lane >> 2;    // 0..7
    const int fk   = lane & 3;     // 0..3
    const int wrow = warp * 16;

    const float* Qb = Q + (size_t)bh * SS * HD;
    const float* Kb = K + (size_t)bh * SS * HD;
    const float* Vb = V + (size_t)bh * SS * HD;

    // Q fragments (already tf32), pinned in registers.
    uint32_t Qf[8][4];
    {
        const float* qr0 = Qb + (size_t)(q0 + wrow + fr) * HD;
        const float* qr1 = qr0 + 8 * HD;
        #pragma unroll
        for (int ks = 0; ks < 8; ks++) {
            Qf[ks][0] = __float_as_uint(qr0[ks * 8 + fk]);
            Qf[ks][1] = __float_as_uint(qr1[ks * 8 + fk]);
            Qf[ks][2] = __float_as_uint(qr0[ks * 8 + fk + 4]);
            Qf[ks][3] = __float_as_uint(qr1[ks * 8 + fk + 4]);
        }
    }

    float Oacc[8][4];
    #pragma unroll
    for (int nt = 0; nt < 8; nt++)
        #pragma unroll
        for (int r = 0; r < 4; r++) Oacc[nt][r] = 0.f;

    float m0 = -INFINITY, m1 = -INFINITY, l0 = 0.f, l1 = 0.f;
    const float tsc = 0.18033688f;     // (1/sqrt(64)) * log2(e)

    const int r0g = q0 + wrow + fr;
    const int r1g = r0g + 8;

    const int nload = (q0 + ABQ) / LKEYS;
    const int j0sl  = (lane & ~3) | (fk >> 1);
    const int j2sl  = j0sl + 2;
    const bool oddc = (fk & 1);

    // cp.async mapping: 4 iters x (16B K + 16B V) per thread per stage
    const int lrow = tid >> 4;           // 0..15 base row
    const int lcol = (tid & 15) * 4;     // 0..60
    const uint32_t sbase = smem_u32(sm);

    #define A_ISSUE(lt, s) do {                                              \
        const int kk0 = (lt) * LKEYS;                                        \
        uint32_t koff = sbase + (uint32_t)(s) * (KS_FL * 4);                 \
        uint32_t voff = sbase + (uint32_t)(2 * KS_FL + (s) * VS_FL) * 4;     \
        _Pragma("unroll")                                                    \
        for (int i = 0; i < 4; i++) {                                        \
            int row = lrow + i * 16;                                         \
            CP16(koff + (row * KSTR + lcol) * 4,                             \
                 Kb + (size_t)(kk0 + row) * HD + lcol);                      \
            CP16(voff + (row * VSTR + lcol) * 4,                             \
                 Vb + (size_t)(kk0 + row) * HD + lcol);                      \
        }                                                                    \
        CP_COMMIT();                                                         \
    } while (0)

    A_ISSUE(0, 0);

    for (int lt = 0; lt < nload; lt++) {
        const int k0  = lt * LKEYS;
        const int buf = lt & 1;
        CP_WAIT0();           // stage lt complete (only pending group)
        __syncthreads();
        if (lt + 1 < nload) A_ISSUE(lt + 1, buf ^ 1);

        const float* Ks = sm + buf * KS_FL;
        const float* Vs = sm + (2 * KS_FL + buf * VS_FL);

        #pragma unroll
        for (int half = 0; half < 2; half++) {
            const int kh = k0 + half * 32;
            if (kh > q0 + wrow + 15) continue;   // warp-uniform causal skip
            const int kb = half * 32;

            // ---- S = Q K^T (16 x 32 per warp) ----
            float Sacc[4][4];
            #pragma unroll
            for (int nt = 0; nt < 4; nt++)
                #pragma unroll
                for (int r = 0; r < 4; r++) Sacc[nt][r] = 0.f;

            #pragma unroll
            for (int ks = 0; ks < 8; ks++) {
                uint32_t bf[4][2];
                #pragma unroll
                for (int nt = 0; nt < 4; nt++) {
                    bf[nt][0] = __float_as_uint(Ks[(kb + nt * 8 + fr) * KSTR + ks * 8 + fk    ]);
                    bf[nt][1] = __float_as_uint(Ks[(kb + nt * 8 + fr) * KSTR + ks * 8 + fk + 4]);
                }
                #pragma unroll
                for (int nt = 0; nt < 4; nt++)
                    mma_tf32(Sacc[nt], Qf[ks][0], Qf[ks][1], Qf[ks][2], Qf[ks][3],
                             bf[nt][0], bf[nt][1]);
            }

            // ---- mask + scale into log2 domain ----
            float t[4][4];
            #pragma unroll
            for (int nt = 0; nt < 4; nt++) {
                int c0 = kh + nt * 8 + 2 * fk;
                t[nt][0] = (c0     <= r0g) ? Sacc[nt][0] * tsc : -INFINITY;
                t[nt][1] = (c0 + 1 <= r0g) ? Sacc[nt][1] * tsc : -INFINITY;
                t[nt][2] = (c0     <= r1g) ? Sacc[nt][2] * tsc : -INFINITY;
                t[nt][3] = (c0 + 1 <= r1g) ? Sacc[nt][3] * tsc : -INFINITY;
            }

            // ---- row max ----
            float mx0 = t[0][0], mx1 = t[0][2];
            #pragma unroll
            for (int nt = 0; nt < 4; nt++) {
                mx0 = fmaxf(mx0, fmaxf(t[nt][0], t[nt][1]));
                mx1 = fmaxf(mx1, fmaxf(t[nt][2], t[nt][3]));
            }
            mx0 = fmaxf(mx0, __shfl_xor_sync(0xFFFFFFFFu, mx0, 1));
            mx0 = fmaxf(mx0, __shfl_xor_sync(0xFFFFFFFFu, mx0, 2));
            mx1 = fmaxf(mx1, __shfl_xor_sync(0xFFFFFFFFu, mx1, 1));
            mx1 = fmaxf(mx1, __shfl_xor_sync(0xFFFFFFFFu, mx1, 2));

            float mn0 = fmaxf(m0, mx0);
            float mn1 = fmaxf(m1, mx1);
            float al0 = exp2f(m0 - mn0);
            float al1 = exp2f(m1 - mn1);
            m0 = mn0; m1 = mn1;

            // ---- p = exp2(t - m), tf32-rounded; accumulate l ----
            float p[4][4];
            float ps0 = 0.f, ps1 = 0.f;
            #pragma unroll
            for (int nt = 0; nt < 4; nt++) {
                p[nt][0] = to_tf32(exp2f(t[nt][0] - m0));
                p[nt][1] = to_tf32(exp2f(t[nt][1] - m0));
                p[nt][2] = to_tf32(exp2f(t[nt][2] - m1));
                p[nt][3] = to_tf32(exp2f(t[nt][3] - m1));
                ps0 += p[nt][0] + p[nt][1];
                ps1 += p[nt][2] + p[nt][3];
            }
            ps0 += __shfl_xor_sync(0xFFFFFFFFu, ps0, 1);
            ps0 += __shfl_xor_sync(0xFFFFFFFFu, ps0, 2);
            ps1 += __shfl_xor_sync(0xFFFFFFFFu, ps1, 1);
            ps1 += __shfl_xor_sync(0xFFFFFFFFu, ps1, 2);
            l0 = l0 * al0 + ps0;
            l1 = l1 * al1 + ps1;

            #pragma unroll
            for (int nt = 0; nt < 8; nt++) {
                Oacc[nt][0] *= al0; Oacc[nt][1] *= al0;
                Oacc[nt][2] *= al1; Oacc[nt][3] *= al1;
            }

            // ---- p accum-layout -> PV A-fragments via quad shfl ----
            uint32_t Pf[4][4];
            #pragma unroll
            for (int g = 0; g < 4; g++) {
                float q00 = __shfl_sync(0xFFFFFFFFu, p[g][0], j0sl);
                float q01 = __shfl_sync(0xFFFFFFFFu, p[g][1], j0sl);
                float q10 = __shfl_sync(0xFFFFFFFFu, p[g][2], j0sl);
                float q11 = __shfl_sync(0xFFFFFFFFu, p[g][3], j0sl);
                float q20 = __shfl_sync(0xFFFFFFFFu, p[g][0], j2sl);
                float q21 = __shfl_sync(0xFFFFFFFFu, p[g][1], j2sl);
                float q30 = __shfl_sync(0xFFFFFFFFu, p[g][2], j2sl);
                float q31 = __shfl_sync(0xFFFFFFFFu, p[g][3], j2sl);
                Pf[g][0] = __float_as_uint(oddc ? q01 : q00);
                Pf[g][1] = __float_as_uint(oddc ? q11 : q10);
                Pf[g][2] = __float_as_uint(oddc ? q21 : q20);
                Pf[g][3] = __float_as_uint(oddc ? q31 : q30);
            }

            // ---- O += P V ----
            #pragma unroll
            for (int g = 0; g < 4; g++) {
                #pragma unroll
                for (int nt = 0; nt < 8; nt++) {
                    uint32_t b0 = __float_as_uint(Vs[(kb + g * 8 + fk    ) * VSTR + nt * 8 + fr]);
                    uint32_t b1 = __float_as_uint(Vs[(kb + g * 8 + fk + 4) * VSTR + nt * 8 + fr]);
                    mma_tf32(Oacc[nt], Pf[g][0], Pf[g][1], Pf[g][2], Pf[g][3], b0, b1);
                }
            }
        }
        __syncthreads();
    }

    // ---- epilogue: normalize, tf32-round (feeds O-proj), write ----
    const int b = bh >> 4, h = bh & 15;
    const float inv0 = 1.f / l0;
    const float inv1 = 1.f / l1;
    float* O0 = O + ((size_t)(b * SS + r0g)) * DM + h * HD;
    float* O1 = O + ((size_t)(b * SS + r1g)) * DM + h * HD;
    #pragma unroll
    for (int nt = 0; nt < 8; nt++) {
        int d = nt * 8 + 2 * fk;
        *(float2*)(O0 + d) = make_float2(to_tf32(Oacc[nt][0] * inv0),
                                         to_tf32(Oacc[nt][1] * inv0));
        *(float2*)(O1 + d) = make_float2(to_tf32(Oacc[nt][2] * inv1),
                                         to_tf32(Oacc[nt][3] * inv1));
    }
}

// ---------------------------------------------------------------------------
extern "C" void kernel_launch(void* const* d_in, const int* in_sizes, int n_in,
                              void* d_out, int out_size)
{
    const float* x  = (const float*)d_in[0];
    const float* Wq = (const float*)d_in[1];
    const float* bq = (const float*)d_in[2];
    const float* Wk = (const float*)d_in[3];
    const float* bk = (const float*)d_in[4];
    const float* Wv = (const float*)d_in[5];
    const float* bv = (const float*)d_in[6];
    const float* Wo = (const float*)d_in[7];
    const float* bo = (const float*)d_in[8];

    float *qp, *kp, *vp, *ap, *xc, *wc;
    cudaGetSymbolAddress((void**)&qp, g_Q);
    cudaGetSymbolAddress((void**)&kp, g_K);
    cudaGetSymbolAddress((void**)&vp, g_V);
    cudaGetSymbolAddress((void**)&ap, g_att);
    cudaGetSymbolAddress((void**)&xc, g_xc);
    cudaGetSymbolAddress((void**)&wc, g_Wc);

    cudaFuncSetAttribute(gemm_tf32_pipe,
        cudaFuncAttributeMaxDynamicSharedMemorySize, GEMM_SMEM);
    cudaFuncSetAttribute(attn_tc,
        cudaFuncAttributeMaxDynamicSharedMemorySize, ATTN_SMEM);

    // prep: tf32-round inputs
    cvt_x_kernel<<<MROWS * DM / 1024, 256>>>(x, xc);
    cvt_w_kernel<<<dim3(DM * DM / 1024, 4), 256>>>(Wq, Wk, Wv, Wo, wc);

    dim3 gg(DM / 128, MROWS / 128);   // (8, 32)
    gemm_tf32_pipe<<<gg, 256, GEMM_SMEM>>>(xc, wc + 0*DM*DM, bq, qp, MROWS, DM, DM, 1, 1);
    gemm_tf32_pipe<<<gg, 256, GEMM_SMEM>>>(xc, wc + 1*DM*DM, bk, kp, MROWS, DM, DM, 1, 1);
    gemm_tf32_pipe<<<gg, 256, GEMM_SMEM>>>(xc, wc + 2*DM*DM, bv, vp, MROWS, DM, DM, 1, 1);

    attn_tc<<<dim3(SS / ABQ, BB * NH), 256, ATTN_SMEM>>>(qp, kp, vp, ap);

    gemm_tf32_pipe<<<gg, 256, GEMM_SMEM>>>(ap, wc + 3*DM*DM, bo, (float*)d_out, MROWS, DM, DM, 0, 0);
}

// round 9
// speedup vs baseline: 4.7608x; 1.0975x over previous
#include <cuda_runtime.h>
#include <math.h>
#include <stdint.h>

// Problem constants
#define BB 2
#define SS 2048
#define DM 1024
#define NH 16
#define HD 64
#define MROWS (BB*SS)        // 4096

// Scratch (device globals; no allocations allowed)
__device__ float g_Q[BB*NH*SS*HD];     // [b,h,s,d]  (tf32-rounded values)
__device__ float g_K[BB*NH*SS*HD];
__device__ float g_V[BB*NH*SS*HD];
__device__ float g_att[BB*SS*DM];      // [b,s, h*64+d] (tf32-rounded)
__device__ float g_xc[MROWS*DM];       // tf32-rounded x
__device__ float g_Wc[4*DM*DM];        // tf32-rounded Wq,Wk,Wv,Wo

// ---------------------------------------------------------------------------
// helpers
// ---------------------------------------------------------------------------
__device__ __forceinline__ float to_tf32(float x) {
    uint32_t u = __float_as_uint(x), y;
    asm("cvt.rna.tf32.f32 %0, %1;" : "=r"(y) : "r"(u));
    return __uint_as_float(y);
}

__device__ __forceinline__ void mma_tf32(float c[4],
    uint32_t a0, uint32_t a1, uint32_t a2, uint32_t a3,
    uint32_t b0, uint32_t b1)
{
    asm volatile(
        "mma.sync.aligned.m16n8k8.row.col.f32.tf32.tf32.f32 "
        "{%0,%1,%2,%3}, {%4,%5,%6,%7}, {%8,%9}, {%0,%1,%2,%3};"
        : "+f"(c[0]), "+f"(c[1]), "+f"(c[2]), "+f"(c[3])
        : "r"(a0), "r"(a1), "r"(a2), "r"(a3), "r"(b0), "r"(b1));
}

__device__ __forceinline__ uint32_t smem_u32(const void* p) {
    uint32_t a;
    asm("{ .reg .u64 t; cvta.to.shared.u64 t, %1; cvt.u32.u64 %0, t; }"
        : "=r"(a) : "l"(p));
    return a;
}

#define CP16(dst, src) \
    asm volatile("cp.async.cg.shared.global [%0], [%1], 16;\n" \
                 :: "r"(dst), "l"(src))
#define CP_COMMIT() asm volatile("cp.async.commit_group;\n")
#define CP_WAIT0()  asm volatile("cp.async.wait_group 0;\n")
#define CP_WAIT1()  asm volatile("cp.async.wait_group 1;\n")

// ---------------------------------------------------------------------------
// prep: tf32-round x and the four weight matrices into scratch
// ---------------------------------------------------------------------------
__global__ __launch_bounds__(256) void cvt_x_kernel(const float* __restrict__ s,
                                                    float* __restrict__ d)
{
    int i = (blockIdx.x * 256 + threadIdx.x) * 4;
    float4 v = *(const float4*)(s + i);
    v.x = to_tf32(v.x); v.y = to_tf32(v.y);
    v.z = to_tf32(v.z); v.w = to_tf32(v.w);
    *(float4*)(d + i) = v;
}

__global__ __launch_bounds__(256) void cvt_w_kernel(
    const float* __restrict__ w0, const float* __restrict__ w1,
    const float* __restrict__ w2, const float* __restrict__ w3,
    float* __restrict__ d)
{
    const float* s = (blockIdx.y == 0) ? w0 : (blockIdx.y == 1) ? w1
                   : (blockIdx.y == 2) ? w2 : w3;
    int i = (blockIdx.x * 256 + threadIdx.x) * 4;
    float4 v = *(const float4*)(s + i);
    v.x = to_tf32(v.x); v.y = to_tf32(v.y);
    v.z = to_tf32(v.z); v.w = to_tf32(v.w);
    *(float4*)(d + (size_t)blockIdx.y * DM * DM + i) = v;
}

// ---------------------------------------------------------------------------
// 3-stage cp.async tf32 GEMM body: C[4096,1024] = A @ W + bias
// 128x128 block tile, BK=32, 256 threads, ONE __syncthreads per k-tile.
// mma order identical to previous rounds (k ascending by 8) -> bitwise-same C.
// ---------------------------------------------------------------------------
#define GSTAGES 3
#define GBK 32
#define ASTRIDE 36
#define BSTRIDE 136
#define ASZ (128*ASTRIDE)      // floats per A stage
#define BSZ (GBK*BSTRIDE)      // floats per B stage
#define GEMM_SMEM ((GSTAGES*(ASZ+BSZ))*4)
#define GNT (DM/GBK)           // 32 k-tiles

template<int HSPLIT, int ROUND>
__device__ __forceinline__ void gemm_body(
    const float* __restrict__ A, const float* __restrict__ W,
    const float* __restrict__ bias, float* __restrict__ C)
{
    extern __shared__ float sm[];

    const int tid  = threadIdx.x;
    const int warp = tid >> 5;
    const int lane = tid & 31;
    const int wm   = (warp >> 2) * 64;
    const int wn   = (warp & 3) * 32;
    const int row0 = blockIdx.y * 128;
    const int col0 = blockIdx.x * 128;
    const int fr   = lane >> 2;
    const int fk   = lane & 3;

    // cp.async mappings: 4x16B for A, 4x16B for B, per thread per stage
    const int ar2 = tid >> 3;           // 0..31 (A row base, +32 per iter)
    const int ak2 = (tid & 7) * 4;      // 0..28 (A k col)
    const int br2 = tid >> 5;           // 0..7  (B k row base, +8 per iter)
    const int bc2 = (tid & 31) * 4;     // 0..124

    const uint32_t sbase = smem_u32(sm);

    float acc[4][4][4];
    #pragma unroll
    for (int i = 0; i < 4; i++)
        #pragma unroll
        for (int j = 0; j < 4; j++)
            #pragma unroll
            for (int r = 0; r < 4; r++) acc[i][j][r] = 0.f;

    // issue k-tile kt into smem slot s
    #define G_ISSUE(kt, s) do {                                              \
        uint32_t abase = sbase + (uint32_t)(s) * (ASZ * 4);                  \
        uint32_t bbase = sbase + (uint32_t)(GSTAGES * ASZ + (s) * BSZ) * 4;  \
        _Pragma("unroll")                                                    \
        for (int i = 0; i < 4; i++) {                                        \
            int row = ar2 + 32 * i;                                          \
            CP16(abase + (uint32_t)(row * ASTRIDE + ak2) * 4,                \
                 A + (size_t)(row0 + row) * DM + (kt) * GBK + ak2);          \
        }                                                                    \
        _Pragma("unroll")                                                    \
        for (int i = 0; i < 4; i++) {                                        \
            int kr = br2 + 8 * i;                                            \
            CP16(bbase + (uint32_t)(kr * BSTRIDE + bc2) * 4,                 \
                 W + (size_t)((kt) * GBK + kr) * DM + col0 + bc2);           \
        }                                                                    \
        CP_COMMIT();                                                         \
    } while (0)

    G_ISSUE(0, 0);
    G_ISSUE(1, 1);

    for (int kt = 0; kt < GNT; kt++) {
        const int cur = kt % GSTAGES;
        CP_WAIT1();            // k-tile kt landed (one newer group may pend)
        __syncthreads();       // single barrier per tile: also fences the
                               // upcoming write into slot read at iter kt-1
        if (kt + 2 < GNT) {
            G_ISSUE(kt + 2, (kt + 2) % GSTAGES);
        } else {
            CP_COMMIT();       // empty group keeps wait_group accounting uniform
        }

        const float* As = sm + cur * ASZ;                  // [128][ASTRIDE]
        const float* Bs = sm + GSTAGES * ASZ + cur * BSZ;  // [GBK][BSTRIDE]

        #pragma unroll
        for (int ks = 0; ks < GBK; ks += 8) {
            uint32_t af[4][4];
            uint32_t bf[4][2];
            #pragma unroll
            for (int mi = 0; mi < 4; mi++) {
                int r = wm + mi * 16 + fr;
                af[mi][0] = __float_as_uint(As[(r    ) * ASTRIDE + ks + fk    ]);
                af[mi][1] = __float_as_uint(As[(r + 8) * ASTRIDE + ks + fk    ]);
                af[mi][2] = __float_as_uint(As[(r    ) * ASTRIDE + ks + fk + 4]);
                af[mi][3] = __float_as_uint(As[(r + 8) * ASTRIDE + ks + fk + 4]);
            }
            #pragma unroll
            for (int ni = 0; ni < 4; ni++) {
                int c = wn + ni * 8 + fr;
                bf[ni][0] = __float_as_uint(Bs[(ks + fk    ) * BSTRIDE + c]);
                bf[ni][1] = __float_as_uint(Bs[(ks + fk + 4) * BSTRIDE + c]);
            }
            #pragma unroll
            for (int mi = 0; mi < 4; mi++)
                #pragma unroll
                for (int ni = 0; ni < 4; ni++)
                    mma_tf32(acc[mi][ni],
                             af[mi][0], af[mi][1], af[mi][2], af[mi][3],
                             bf[ni][0], bf[ni][1]);
        }
        // no trailing barrier: next iteration's barrier (post-wait) fences
        // slot reuse before any cp.async data for it can be consumed/written
    }

    // ---- epilogue ----
    #pragma unroll
    for (int mi = 0; mi < 4; mi++) {
        int r = row0 + wm + mi * 16 + fr;
        #pragma unroll
        for (int ni = 0; ni < 4; ni++) {
            int c = col0 + wn + ni * 8 + 2 * fk;
            float bb0 = bias[c], bb1 = bias[c + 1];
            float v0 = acc[mi][ni][0] + bb0, v1 = acc[mi][ni][1] + bb1;
            float v2 = acc[mi][ni][2] + bb0, v3 = acc[mi][ni][3] + bb1;
            if (ROUND) {
                v0 = to_tf32(v0); v1 = to_tf32(v1);
                v2 = to_tf32(v2); v3 = to_tf32(v3);
            }
            float2 v01 = make_float2(v0, v1);
            float2 v23 = make_float2(v2, v3);
            if (HSPLIT) {
                int h = c >> 6, d = c & 63;
                int b0i = r >> 11, s0 = r & 2047;
                size_t i0 = ((((size_t)b0i * NH + h) * SS + s0) * HD) + d;
                *(float2*)&C[i0] = v01;
                int r2 = r + 8;
                int b1i = r2 >> 11, s1 = r2 & 2047;
                size_t i1 = ((((size_t)b1i * NH + h) * SS + s1) * HD) + d;
                *(float2*)&C[i1] = v23;
            } else {
                *(float2*)&C[(size_t)r * DM + c]       = v01;
                *(float2*)&C[(size_t)(r + 8) * DM + c] = v23;
            }
        }
    }
    #undef G_ISSUE
}

// merged QKV: gridDim.z = 3 selects weight/bias/output
__global__ __launch_bounds__(256, 2) void gemm_qkv(
    const float* __restrict__ A, const float* __restrict__ Wbase,
    const float* __restrict__ b0, const float* __restrict__ b1,
    const float* __restrict__ b2,
    float* __restrict__ C0, float* __restrict__ C1, float* __restrict__ C2)
{
    const int z = blockIdx.z;
    const float* W    = Wbase + (size_t)z * DM * DM;
    const float* bias = (z == 0) ? b0 : (z == 1) ? b1 : b2;
    float*       C    = (z == 0) ? C0 : (z == 1) ? C1 : C2;
    gemm_body<1, 1>(A, W, bias, C);
}

__global__ __launch_bounds__(256, 2) void gemm_o(
    const float* __restrict__ A, const float* __restrict__ W,
    const float* __restrict__ bias, float* __restrict__ C)
{
    gemm_body<0, 0>(A, W, bias, C);
}

// ---------------------------------------------------------------------------
// Tensor-core flash attention (causal, tf32 mma both stages). Unchanged R8:
//  - inputs already tf32-rounded -> no cvt in load paths
//  - 2-stage double-buffered cp.async K/V loads
//  - K stride 68 / V stride 72 conflict-free fragment banks
//  - P in registers via quad shuffles; output written tf32-rounded
// ---------------------------------------------------------------------------
#define ABQ 128
#define LKEYS 64
#define KSTR 68
#define VSTR 72
#define KS_FL (LKEYS*KSTR)
#define VS_FL (LKEYS*VSTR)
#define ATTN_SMEM ((2*KS_FL + 2*VS_FL)*4)

__global__ __launch_bounds__(256) void attn_tc(
    const float* __restrict__ Q, const float* __restrict__ K,
    const float* __restrict__ V, float* __restrict__ O)
{
    extern __shared__ float sm[];
    // layout: K stage0 | K stage1 | V stage0 | V stage1

    const int bh   = blockIdx.y;
    const int qb   = gridDim.x - 1 - blockIdx.x;  // heavy blocks first
    const int q0   = qb * ABQ;
    const int tid  = threadIdx.x;
    const int warp = tid >> 5;
    const int lane = tid & 31;
    const int fr   = lane >> 2;
    const int fk   = lane & 3;
    const int wrow = warp * 16;

    const float* Qb = Q + (size_t)bh * SS * HD;
    const float* Kb = K + (size_t)bh * SS * HD;
    const float* Vb = V + (size_t)bh * SS * HD;

    uint32_t Qf[8][4];
    {
        const float* qr0 = Qb + (size_t)(q0 + wrow + fr) * HD;
        const float* qr1 = qr0 + 8 * HD;
        #pragma unroll
        for (int ks = 0; ks < 8; ks++) {
            Qf[ks][0] = __float_as_uint(qr0[ks * 8 + fk]);
            Qf[ks][1] = __float_as_uint(qr1[ks * 8 + fk]);
            Qf[ks][2] = __float_as_uint(qr0[ks * 8 + fk + 4]);
            Qf[ks][3] = __float_as_uint(qr1[ks * 8 + fk + 4]);
        }
    }

    float Oacc[8][4];
    #pragma unroll
    for (int nt = 0; nt < 8; nt++)
        #pragma unroll
        for (int r = 0; r < 4; r++) Oacc[nt][r] = 0.f;

    float m0 = -INFINITY, m1 = -INFINITY, l0 = 0.f, l1 = 0.f;
    const float tsc = 0.18033688f;     // (1/sqrt(64)) * log2(e)

    const int r0g = q0 + wrow + fr;
    const int r1g = r0g + 8;

    const int nload = (q0 + ABQ) / LKEYS;
    const int j0sl  = (lane & ~3) | (fk >> 1);
    const int j2sl  = j0sl + 2;
    const bool oddc = (fk & 1);

    const int lrow = tid >> 4;
    const int lcol = (tid & 15) * 4;
    const uint32_t sbase = smem_u32(sm);

    #define A_ISSUE(lt, s) do {                                              \
        const int kk0 = (lt) * LKEYS;                                        \
        uint32_t koff = sbase + (uint32_t)(s) * (KS_FL * 4);                 \
        uint32_t voff = sbase + (uint32_t)(2 * KS_FL + (s) * VS_FL) * 4;     \
        _Pragma("unroll")                                                    \
        for (int i = 0; i < 4; i++) {                                        \
            int row = lrow + i * 16;                                         \
            CP16(koff + (row * KSTR + lcol) * 4,                             \
                 Kb + (size_t)(kk0 + row) * HD + lcol);                      \
            CP16(voff + (row * VSTR + lcol) * 4,                             \
                 Vb + (size_t)(kk0 + row) * HD + lcol);                      \
        }                                                                    \
        CP_COMMIT();                                                         \
    } while (0)

    A_ISSUE(0, 0);

    for (int lt = 0; lt < nload; lt++) {
        const int k0  = lt * LKEYS;
        const int buf = lt & 1;
        CP_WAIT0();
        __syncthreads();
        if (lt + 1 < nload) A_ISSUE(lt + 1, buf ^ 1);

        const float* Ks = sm + buf * KS_FL;
        const float* Vs = sm + (2 * KS_FL + buf * VS_FL);

        #pragma unroll
        for (int half = 0; half < 2; half++) {
            const int kh = k0 + half * 32;
            if (kh > q0 + wrow + 15) continue;
            const int kb = half * 32;

            float Sacc[4][4];
            #pragma unroll
            for (int nt = 0; nt < 4; nt++)
                #pragma unroll
                for (int r = 0; r < 4; r++) Sacc[nt][r] = 0.f;

            #pragma unroll
            for (int ks = 0; ks < 8; ks++) {
                uint32_t bf[4][2];
                #pragma unroll
                for (int nt = 0; nt < 4; nt++) {
                    bf[nt][0] = __float_as_uint(Ks[(kb + nt * 8 + fr) * KSTR + ks * 8 + fk    ]);
                    bf[nt][1] = __float_as_uint(Ks[(kb + nt * 8 + fr) * KSTR + ks * 8 + fk + 4]);
                }
                #pragma unroll
                for (int nt = 0; nt < 4; nt++)
                    mma_tf32(Sacc[nt], Qf[ks][0], Qf[ks][1], Qf[ks][2], Qf[ks][3],
                             bf[nt][0], bf[nt][1]);
            }

            float t[4][4];
            #pragma unroll
            for (int nt = 0; nt < 4; nt++) {
                int c0 = kh + nt * 8 + 2 * fk;
                t[nt][0] = (c0     <= r0g) ? Sacc[nt][0] * tsc : -INFINITY;
                t[nt][1] = (c0 + 1 <= r0g) ? Sacc[nt][1] * tsc : -INFINITY;
                t[nt][2] = (c0     <= r1g) ? Sacc[nt][2] * tsc : -INFINITY;
                t[nt][3] = (c0 + 1 <= r1g) ? Sacc[nt][3] * tsc : -INFINITY;
            }

            float mx0 = t[0][0], mx1 = t[0][2];
            #pragma unroll
            for (int nt = 0; nt < 4; nt++) {
                mx0 = fmaxf(mx0, fmaxf(t[nt][0], t[nt][1]));
                mx1 = fmaxf(mx1, fmaxf(t[nt][2], t[nt][3]));
            }
            mx0 = fmaxf(mx0, __shfl_xor_sync(0xFFFFFFFFu, mx0, 1));
            mx0 = fmaxf(mx0, __shfl_xor_sync(0xFFFFFFFFu, mx0, 2));
            mx1 = fmaxf(mx1, __shfl_xor_sync(0xFFFFFFFFu, mx1, 1));
            mx1 = fmaxf(mx1, __shfl_xor_sync(0xFFFFFFFFu, mx1, 2));

            float mn0 = fmaxf(m0, mx0);
            float mn1 = fmaxf(m1, mx1);
            float al0 = exp2f(m0 - mn0);
            float al1 = exp2f(m1 - mn1);
            m0 = mn0; m1 = mn1;

            float p[4][4];
            float ps0 = 0.f, ps1 = 0.f;
            #pragma unroll
            for (int nt = 0; nt < 4; nt++) {
                p[nt][0] = to_tf32(exp2f(t[nt][0] - m0));
                p[nt][1] = to_tf32(exp2f(t[nt][1] - m0));
                p[nt][2] = to_tf32(exp2f(t[nt][2] - m1));
                p[nt][3] = to_tf32(exp2f(t[nt][3] - m1));
                ps0 += p[nt][0] + p[nt][1];
                ps1 += p[nt][2] + p[nt][3];
            }
            ps0 += __shfl_xor_sync(0xFFFFFFFFu, ps0, 1);
            ps0 += __shfl_xor_sync(0xFFFFFFFFu, ps0, 2);
            ps1 += __shfl_xor_sync(0xFFFFFFFFu, ps1, 1);
            ps1 += __shfl_xor_sync(0xFFFFFFFFu, ps1, 2);
            l0 = l0 * al0 + ps0;
            l1 = l1 * al1 + ps1;

            #pragma unroll
            for (int nt = 0; nt < 8; nt++) {
                Oacc[nt][0] *= al0; Oacc[nt][1] *= al0;
                Oacc[nt][2] *= al1; Oacc[nt][3] *= al1;
            }

            uint32_t Pf[4][4];
            #pragma unroll
            for (int g = 0; g < 4; g++) {
                float q00 = __shfl_sync(0xFFFFFFFFu, p[g][0], j0sl);
                float q01 = __shfl_sync(0xFFFFFFFFu, p[g][1], j0sl);
                float q10 = __shfl_sync(0xFFFFFFFFu, p[g][2], j0sl);
                float q11 = __shfl_sync(0xFFFFFFFFu, p[g][3], j0sl);
                float q20 = __shfl_sync(0xFFFFFFFFu, p[g][0], j2sl);
                float q21 = __shfl_sync(0xFFFFFFFFu, p[g][1], j2sl);
                float q30 = __shfl_sync(0xFFFFFFFFu, p[g][2], j2sl);
                float q31 = __shfl_sync(0xFFFFFFFFu, p[g][3], j2sl);
                Pf[g][0] = __float_as_uint(oddc ? q01 : q00);
                Pf[g][1] = __float_as_uint(oddc ? q11 : q10);
                Pf[g][2] = __float_as_uint(oddc ? q21 : q20);
                Pf[g][3] = __float_as_uint(oddc ? q31 : q30);
            }

            #pragma unroll
            for (int g = 0; g < 4; g++) {
                #pragma unroll
                for (int nt = 0; nt < 8; nt++) {
                    uint32_t b0 = __float_as_uint(Vs[(kb + g * 8 + fk    ) * VSTR + nt * 8 + fr]);
                    uint32_t b1 = __float_as_uint(Vs[(kb + g * 8 + fk + 4) * VSTR + nt * 8 + fr]);
                    mma_tf32(Oacc[nt], Pf[g][0], Pf[g][1], Pf[g][2], Pf[g][3], b0, b1);
                }
            }
        }
        __syncthreads();
    }

    const int b = bh >> 4, h = bh & 15;
    const float inv0 = 1.f / l0;
    const float inv1 = 1.f / l1;
    float* O0 = O + ((size_t)(b * SS + r0g)) * DM + h * HD;
    float* O1 = O + ((size_t)(b * SS + r1g)) * DM + h * HD;
    #pragma unroll
    for (int nt = 0; nt < 8; nt++) {
        int d = nt * 8 + 2 * fk;
        *(float2*)(O0 + d) = make_float2(to_tf32(Oacc[nt][0] * inv0),
                                         to_tf32(Oacc[nt][1] * inv0));
        *(float2*)(O1 + d) = make_float2(to_tf32(Oacc[nt][2] * inv1),
                                         to_tf32(Oacc[nt][3] * inv1));
    }
}

// ---------------------------------------------------------------------------
extern "C" void kernel_launch(void* const* d_in, const int* in_sizes, int n_in,
                              void* d_out, int out_size)
{
    const float* x  = (const float*)d_in[0];
    const float* Wq = (const float*)d_in[1];
    const float* bq = (const float*)d_in[2];
    const float* Wk = (const float*)d_in[3];
    const float* bk = (const float*)d_in[4];
    const float* Wv = (const float*)d_in[5];
    const float* bv = (const float*)d_in[6];
    const float* Wo = (const float*)d_in[7];
    const float* bo = (const float*)d_in[8];

    float *qp, *kp, *vp, *ap, *xc, *wc;
    cudaGetSymbolAddress((void**)&qp, g_Q);
    cudaGetSymbolAddress((void**)&kp, g_K);
    cudaGetSymbolAddress((void**)&vp, g_V);
    cudaGetSymbolAddress((void**)&ap, g_att);
    cudaGetSymbolAddress((void**)&xc, g_xc);
    cudaGetSymbolAddress((void**)&wc, g_Wc);

    cudaFuncSetAttribute(gemm_qkv,
        cudaFuncAttributeMaxDynamicSharedMemorySize, GEMM_SMEM);
    cudaFuncSetAttribute(gemm_o,
        cudaFuncAttributeMaxDynamicSharedMemorySize, GEMM_SMEM);
    cudaFuncSetAttribute(attn_tc,
        cudaFuncAttributeMaxDynamicSharedMemorySize, ATTN_SMEM);

    // prep: tf32-round inputs
    cvt_x_kernel<<<MROWS * DM / 1024, 256>>>(x, xc);
    cvt_w_kernel<<<dim3(DM * DM / 1024, 4), 256>>>(Wq, Wk, Wv, Wo, wc);

    dim3 gqkv(DM / 128, MROWS / 128, 3);   // (8, 32, 3)
    gemm_qkv<<<gqkv, 256, GEMM_SMEM>>>(xc, wc, bq, bk, bv, qp, kp, vp);

    attn_tc<<<dim3(SS / ABQ, BB * NH), 256, ATTN_SMEM>>>(qp, kp, vp, ap);

    dim3 go(DM / 128, MROWS / 128);        // (8, 32)
    gemm_o<<<go, 256, GEMM_SMEM>>>(ap, wc + 3*DM*DM, bo, (float*)d_out);
}

// round 10
// speedup vs baseline: 5.5351x; 1.1627x over previous
#include <cuda_runtime.h>
#include <cuda_fp16.h>
#include <math.h>
#include <stdint.h>

// Problem constants
#define BB 2
#define SS 2048
#define DM 1024
#define NH 16
#define HD 64
#define MROWS (BB*SS)        // 4096

// Scratch (device globals; no allocations allowed)
__device__ __half g_Qh[BB*NH*SS*HD];   // [b,h,s,d] fp16
__device__ __half g_Kh[BB*NH*SS*HD];   // [b,h,s,d] fp16
__device__ __half g_Vt[BB*NH*HD*SS];   // [b,h,d,s] fp16 (transposed)
__device__ float  g_att[BB*SS*DM];     // [b,s, h*64+d] (tf32-rounded)
__device__ float  g_xc[MROWS*DM];      // tf32-rounded x
__device__ float  g_Wc[4*DM*DM];       // tf32-rounded Wq,Wk,Wv,Wo

// ---------------------------------------------------------------------------
// helpers
// ---------------------------------------------------------------------------
__device__ __forceinline__ float to_tf32(float x) {
    uint32_t u = __float_as_uint(x), y;
    asm("cvt.rna.tf32.f32 %0, %1;" : "=r"(y) : "r"(u));
    return __uint_as_float(y);
}

__device__ __forceinline__ void mma_tf32(float c[4],
    uint32_t a0, uint32_t a1, uint32_t a2, uint32_t a3,
    uint32_t b0, uint32_t b1)
{
    asm volatile(
        "mma.sync.aligned.m16n8k8.row.col.f32.tf32.tf32.f32 "
        "{%0,%1,%2,%3}, {%4,%5,%6,%7}, {%8,%9}, {%0,%1,%2,%3};"
        : "+f"(c[0]), "+f"(c[1]), "+f"(c[2]), "+f"(c[3])
        : "r"(a0), "r"(a1), "r"(a2), "r"(a3), "r"(b0), "r"(b1));
}

__device__ __forceinline__ void mma_f16(float c[4],
    uint32_t a0, uint32_t a1, uint32_t a2, uint32_t a3,
    uint32_t b0, uint32_t b1)
{
    asm volatile(
        "mma.sync.aligned.m16n8k16.row.col.f32.f16.f16.f32 "
        "{%0,%1,%2,%3}, {%4,%5,%6,%7}, {%8,%9}, {%0,%1,%2,%3};"
        : "+f"(c[0]), "+f"(c[1]), "+f"(c[2]), "+f"(c[3])
        : "r"(a0), "r"(a1), "r"(a2), "r"(a3), "r"(b0), "r"(b1));
}

__device__ __forceinline__ uint32_t smem_u32(const void* p) {
    uint32_t a;
    asm("{ .reg .u64 t; cvta.to.shared.u64 t, %1; cvt.u32.u64 %0, t; }"
        : "=r"(a) : "l"(p));
    return a;
}

#define CP16(dst, src) \
    asm volatile("cp.async.cg.shared.global [%0], [%1], 16;\n" \
                 :: "r"(dst), "l"(src))
#define CP_COMMIT() asm volatile("cp.async.commit_group;\n")
#define CP_WAIT0()  asm volatile("cp.async.wait_group 0;\n")
#define CP_WAIT1()  asm volatile("cp.async.wait_group 1;\n")

// ---------------------------------------------------------------------------
// prep: tf32-round x and the four weight matrices into scratch
// ---------------------------------------------------------------------------
__global__ __launch_bounds__(256) void cvt_x_kernel(const float* __restrict__ s,
                                                    float* __restrict__ d)
{
    int i = (blockIdx.x * 256 + threadIdx.x) * 4;
    float4 v = *(const float4*)(s + i);
    v.x = to_tf32(v.x); v.y = to_tf32(v.y);
    v.z = to_tf32(v.z); v.w = to_tf32(v.w);
    *(float4*)(d + i) = v;
}

__global__ __launch_bounds__(256) void cvt_w_kernel(
    const float* __restrict__ w0, const float* __restrict__ w1,
    const float* __restrict__ w2, const float* __restrict__ w3,
    float* __restrict__ d)
{
    const float* s = (blockIdx.y == 0) ? w0 : (blockIdx.y == 1) ? w1
                   : (blockIdx.y == 2) ? w2 : w3;
    int i = (blockIdx.x * 256 + threadIdx.x) * 4;
    float4 v = *(const float4*)(s + i);
    v.x = to_tf32(v.x); v.y = to_tf32(v.y);
    v.z = to_tf32(v.z); v.w = to_tf32(v.w);
    *(float4*)(d + (size_t)blockIdx.y * DM * DM + i) = v;
}

// ---------------------------------------------------------------------------
// 3-stage cp.async tf32 GEMM body: C[4096,1024] = A @ W + bias
// 128x128 tile, BK=32, 256 threads, one __syncthreads per k-tile.
// OUTMODE: 0 = fp32 row-major (final out); 1 = fp16 [b,h,s,d] (Q,K);
//          2 = fp16 [b,h,d,s] transposed (V).
// ---------------------------------------------------------------------------
#define GSTAGES 3
#define GBK 32
#define ASTRIDE 36
#define BSTRIDE 136
#define ASZ (128*ASTRIDE)
#define BSZ (GBK*BSTRIDE)
#define GEMM_SMEM ((GSTAGES*(ASZ+BSZ))*4)
#define GNT (DM/GBK)           // 32 k-tiles

template<int OUTMODE>
__device__ __forceinline__ void gemm_body(
    const float* __restrict__ A, const float* __restrict__ W,
    const float* __restrict__ bias, void* __restrict__ Cv)
{
    extern __shared__ float sm[];

    const int tid  = threadIdx.x;
    const int warp = tid >> 5;
    const int lane = tid & 31;
    const int wm   = (warp >> 2) * 64;
    const int wn   = (warp & 3) * 32;
    const int row0 = blockIdx.y * 128;
    const int col0 = blockIdx.x * 128;
    const int fr   = lane >> 2;
    const int fk   = lane & 3;

    const int ar2 = tid >> 3;
    const int ak2 = (tid & 7) * 4;
    const int br2 = tid >> 5;
    const int bc2 = (tid & 31) * 4;

    const uint32_t sbase = smem_u32(sm);

    float acc[4][4][4];
    #pragma unroll
    for (int i = 0; i < 4; i++)
        #pragma unroll
        for (int j = 0; j < 4; j++)
            #pragma unroll
            for (int r = 0; r < 4; r++) acc[i][j][r] = 0.f;

    #define G_ISSUE(kt, s) do {                                              \
        uint32_t abase = sbase + (uint32_t)(s) * (ASZ * 4);                  \
        uint32_t bbase = sbase + (uint32_t)(GSTAGES * ASZ + (s) * BSZ) * 4;  \
        _Pragma("unroll")                                                    \
        for (int i = 0; i < 4; i++) {                                        \
            int row = ar2 + 32 * i;                                          \
            CP16(abase + (uint32_t)(row * ASTRIDE + ak2) * 4,                \
                 A + (size_t)(row0 + row) * DM + (kt) * GBK + ak2);          \
        }                                                                    \
        _Pragma("unroll")                                                    \
        for (int i = 0; i < 4; i++) {                                        \
            int kr = br2 + 8 * i;                                            \
            CP16(bbase + (uint32_t)(kr * BSTRIDE + bc2) * 4,                 \
                 W + (size_t)((kt) * GBK + kr) * DM + col0 + bc2);           \
        }                                                                    \
        CP_COMMIT();                                                         \
    } while (0)

    G_ISSUE(0, 0);
    G_ISSUE(1, 1);

    for (int kt = 0; kt < GNT; kt++) {
        const int cur = kt % GSTAGES;
        CP_WAIT1();
        __syncthreads();
        if (kt + 2 < GNT) {
            G_ISSUE(kt + 2, (kt + 2) % GSTAGES);
        } else {
            CP_COMMIT();
        }

        const float* As = sm + cur * ASZ;
        const float* Bs = sm + GSTAGES * ASZ + cur * BSZ;

        #pragma unroll
        for (int ks = 0; ks < GBK; ks += 8) {
            uint32_t af[4][4];
            uint32_t bf[4][2];
            #pragma unroll
            for (int mi = 0; mi < 4; mi++) {
                int r = wm + mi * 16 + fr;
                af[mi][0] = __float_as_uint(As[(r    ) * ASTRIDE + ks + fk    ]);
                af[mi][1] = __float_as_uint(As[(r + 8) * ASTRIDE + ks + fk    ]);
                af[mi][2] = __float_as_uint(As[(r    ) * ASTRIDE + ks + fk + 4]);
                af[mi][3] = __float_as_uint(As[(r + 8) * ASTRIDE + ks + fk + 4]);
            }
            #pragma unroll
            for (int ni = 0; ni < 4; ni++) {
                int c = wn + ni * 8 + fr;
                bf[ni][0] = __float_as_uint(Bs[(ks + fk    ) * BSTRIDE + c]);
                bf[ni][1] = __float_as_uint(Bs[(ks + fk + 4) * BSTRIDE + c]);
            }
            #pragma unroll
            for (int mi = 0; mi < 4; mi++)
                #pragma unroll
                for (int ni = 0; ni < 4; ni++)
                    mma_tf32(acc[mi][ni],
                             af[mi][0], af[mi][1], af[mi][2], af[mi][3],
                             bf[ni][0], bf[ni][1]);
        }
    }

    // ---- epilogue ----
    #pragma unroll
    for (int mi = 0; mi < 4; mi++) {
        int r = row0 + wm + mi * 16 + fr;
        #pragma unroll
        for (int ni = 0; ni < 4; ni++) {
            int c = col0 + wn + ni * 8 + 2 * fk;
            float bb0 = bias[c], bb1 = bias[c + 1];
            float v0 = acc[mi][ni][0] + bb0, v1 = acc[mi][ni][1] + bb1;
            float v2 = acc[mi][ni][2] + bb0, v3 = acc[mi][ni][3] + bb1;
            if (OUTMODE == 0) {
                float* C = (float*)Cv;
                *(float2*)&C[(size_t)r * DM + c]       = make_float2(v0, v1);
                *(float2*)&C[(size_t)(r + 8) * DM + c] = make_float2(v2, v3);
            } else if (OUTMODE == 1) {
                __half* C = (__half*)Cv;
                int h = c >> 6, d = c & 63;
                int b0i = r >> 11, s0 = r & 2047;
                size_t i0 = ((((size_t)b0i * NH + h) * SS + s0) * HD) + d;
                *(__half2*)&C[i0] = __floats2half2_rn(v0, v1);
                int r2 = r + 8;
                int b1i = r2 >> 11, s1 = r2 & 2047;
                size_t i1 = ((((size_t)b1i * NH + h) * SS + s1) * HD) + d;
                *(__half2*)&C[i1] = __floats2half2_rn(v2, v3);
            } else {
                __half* C = (__half*)Cv;       // [b,h,d,s]
                int h = c >> 6, d = c & 63;
                int b0i = r >> 11, s0 = r & 2047;
                int r2 = r + 8;
                int b1i = r2 >> 11, s1 = r2 & 2047;
                size_t base0 = (((size_t)b0i * NH + h) * HD);
                size_t base1 = (((size_t)b1i * NH + h) * HD);
                C[(base0 + d    ) * SS + s0] = __float2half_rn(v0);
                C[(base0 + d + 1) * SS + s0] = __float2half_rn(v1);
                C[(base1 + d    ) * SS + s1] = __float2half_rn(v2);
                C[(base1 + d + 1) * SS + s1] = __float2half_rn(v3);
            }
        }
    }
    #undef G_ISSUE
}

// Q and K projections (gridDim.z = 2)
__global__ __launch_bounds__(256, 2) void gemm_qk(
    const float* __restrict__ A, const float* __restrict__ Wbase,
    const float* __restrict__ b0, const float* __restrict__ b1,
    __half* __restrict__ C0, __half* __restrict__ C1)
{
    const int z = blockIdx.z;
    gemm_body<1>(A, Wbase + (size_t)z * DM * DM, z ? b1 : b0, z ? C1 : C0);
}

__global__ __launch_bounds__(256, 2) void gemm_v(
    const float* __restrict__ A, const float* __restrict__ W,
    const float* __restrict__ bias, __half* __restrict__ C)
{
    gemm_body<2>(A, W, bias, C);
}

__global__ __launch_bounds__(256, 2) void gemm_o(
    const float* __restrict__ A, const float* __restrict__ W,
    const float* __restrict__ bias, float* __restrict__ C)
{
    gemm_body<0>(A, W, bias, C);
}

// ---------------------------------------------------------------------------
// fp16 tensor-core flash attention (causal), m16n8k16, fp32 accum.
//  - Q,K in [b,h,s,d] fp16; V in [b,h,d,s] fp16 (transposed)
//  - smem strides 72 halves (36 words = 4 mod 32 -> conflict-free fragments)
//  - P pack: accumulator layout == fp16 A-fragment layout, zero shuffles
//  - 2-stage double-buffered cp.async K/V loads
// ---------------------------------------------------------------------------
#define ABQ 128
#define LKEYS 64
#define HSTR 72                       // halves per smem row
#define KSTAGE_H (LKEYS*HSTR)         // 4608 halves = 9216 B
#define ATTN_SMEM (4*KSTAGE_H*2)      // K0,K1,V0,V1 = 36864 B

__global__ __launch_bounds__(256) void attn_h(
    const __half* __restrict__ Q, const __half* __restrict__ K,
    const __half* __restrict__ Vt, float* __restrict__ O)
{
    extern __shared__ __half smh[];
    // layout: K stage0 | K stage1 | V stage0 | V stage1

    const int bh   = blockIdx.y;
    const int qb   = gridDim.x - 1 - blockIdx.x;  // heavy blocks first
    const int q0   = qb * ABQ;
    const int tid  = threadIdx.x;
    const int warp = tid >> 5;
    const int lane = tid & 31;
    const int fr   = lane >> 2;
    const int fk   = lane & 3;
    const int wrow = warp * 16;

    const __half* Qb  = Q  + (size_t)bh * SS * HD;
    const __half* Kb  = K  + (size_t)bh * SS * HD;
    const __half* Vtb = Vt + (size_t)bh * HD * SS;

    // Q fragments (fp16 packed), pinned in registers. 4 k-steps of 16.
    uint32_t Qf[4][4];
    {
        const __half* qr0 = Qb + (size_t)(q0 + wrow + fr) * HD;
        const __half* qr1 = qr0 + 8 * HD;
        #pragma unroll
        for (int ks = 0; ks < 4; ks++) {
            Qf[ks][0] = *(const uint32_t*)(qr0 + 16 * ks + 2 * fk);
            Qf[ks][1] = *(const uint32_t*)(qr1 + 16 * ks + 2 * fk);
            Qf[ks][2] = *(const uint32_t*)(qr0 + 16 * ks + 8 + 2 * fk);
            Qf[ks][3] = *(const uint32_t*)(qr1 + 16 * ks + 8 + 2 * fk);
        }
    }

    float Oacc[8][4];
    #pragma unroll
    for (int nt = 0; nt < 8; nt++)
        #pragma unroll
        for (int r = 0; r < 4; r++) Oacc[nt][r] = 0.f;

    float m0 = -INFINITY, m1 = -INFINITY, l0 = 0.f, l1 = 0.f;
    const float tsc = 0.18033688f;     // (1/sqrt(64)) * log2(e)

    const int r0g = q0 + wrow + fr;
    const int r1g = r0g + 8;

    const int nload = (q0 + ABQ) / LKEYS;

    // cp.async: per stage, K = 64 rows x 128B, V = 64 rows x 128B.
    // thread -> rows (tid>>3, +32), 16B chunk (tid&7)*16 within the row.
    const int crow = tid >> 3;           // 0..31
    const int coff = (tid & 7) * 8;      // halves: 0..56
    const uint32_t sbase = smem_u32(smh);

    #define A_ISSUE(lt, s) do {                                              \
        const int kk0 = (lt) * LKEYS;                                        \
        uint32_t koff = sbase + (uint32_t)(s) * (KSTAGE_H * 2);              \
        uint32_t voff = sbase + (uint32_t)((2 + (s)) * KSTAGE_H) * 2;        \
        _Pragma("unroll")                                                    \
        for (int i = 0; i < 2; i++) {                                        \
            int row = crow + 32 * i;                                         \
            CP16(koff + (uint32_t)(row * HSTR + coff) * 2,                   \
                 Kb + (size_t)(kk0 + row) * HD + coff);                      \
            CP16(voff + (uint32_t)(row * HSTR + coff) * 2,                   \
                 Vtb + (size_t)row * SS + kk0 + coff);                       \
        }                                                                    \
        CP_COMMIT();                                                         \
    } while (0)

    A_ISSUE(0, 0);

    for (int lt = 0; lt < nload; lt++) {
        const int k0  = lt * LKEYS;
        const int buf = lt & 1;
        CP_WAIT0();
        __syncthreads();
        if (lt + 1 < nload) A_ISSUE(lt + 1, buf ^ 1);

        const __half* Ks = smh + buf * KSTAGE_H;
        const __half* Vs = smh + (2 + buf) * KSTAGE_H;

        #pragma unroll
        for (int half = 0; half < 2; half++) {
            const int kh = k0 + half * 32;
            if (kh > q0 + wrow + 15) continue;   // warp-uniform causal skip
            const int kb = half * 32;            // key offset within stage

            // ---- S = Q K^T (16 x 32 per warp, 4 k-steps x 4 n-tiles) ----
            float Sacc[4][4];
            #pragma unroll
            for (int nt = 0; nt < 4; nt++)
                #pragma unroll
                for (int r = 0; r < 4; r++) Sacc[nt][r] = 0.f;

            #pragma unroll
            for (int ks = 0; ks < 4; ks++) {
                #pragma unroll
                for (int nt = 0; nt < 4; nt++) {
                    const __half* kr = Ks + (kb + nt * 8 + fr) * HSTR + 16 * ks;
                    uint32_t b0 = *(const uint32_t*)(kr + 2 * fk);
                    uint32_t b1 = *(const uint32_t*)(kr + 8 + 2 * fk);
                    mma_f16(Sacc[nt], Qf[ks][0], Qf[ks][1], Qf[ks][2], Qf[ks][3],
                            b0, b1);
                }
            }

            // ---- mask + scale into log2 domain ----
            float t[4][4];
            #pragma unroll
            for (int nt = 0; nt < 4; nt++) {
                int c0 = kh + nt * 8 + 2 * fk;
                t[nt][0] = (c0     <= r0g) ? Sacc[nt][0] * tsc : -INFINITY;
                t[nt][1] = (c0 + 1 <= r0g) ? Sacc[nt][1] * tsc : -INFINITY;
                t[nt][2] = (c0     <= r1g) ? Sacc[nt][2] * tsc : -INFINITY;
                t[nt][3] = (c0 + 1 <= r1g) ? Sacc[nt][3] * tsc : -INFINITY;
            }

            // ---- row max ----
            float mx0 = t[0][0], mx1 = t[0][2];
            #pragma unroll
            for (int nt = 0; nt < 4; nt++) {
                mx0 = fmaxf(mx0, fmaxf(t[nt][0], t[nt][1]));
                mx1 = fmaxf(mx1, fmaxf(t[nt][2], t[nt][3]));
            }
            mx0 = fmaxf(mx0, __shfl_xor_sync(0xFFFFFFFFu, mx0, 1));
            mx0 = fmaxf(mx0, __shfl_xor_sync(0xFFFFFFFFu, mx0, 2));
            mx1 = fmaxf(mx1, __shfl_xor_sync(0xFFFFFFFFu, mx1, 1));
            mx1 = fmaxf(mx1, __shfl_xor_sync(0xFFFFFFFFu, mx1, 2));

            float mn0 = fmaxf(m0, mx0);
            float mn1 = fmaxf(m1, mx1);
            float al0 = exp2f(m0 - mn0);
            float al1 = exp2f(m1 - mn1);
            m0 = mn0; m1 = mn1;

            // ---- p = exp2(t - m); fp16 pack IS the A-fragment layout ----
            uint32_t P01[4], P23[4];
            float ps0 = 0.f, ps1 = 0.f;
            #pragma unroll
            for (int nt = 0; nt < 4; nt++) {
                __half2 h01 = __floats2half2_rn(exp2f(t[nt][0] - m0),
                                                exp2f(t[nt][1] - m0));
                __half2 h23 = __floats2half2_rn(exp2f(t[nt][2] - m1),
                                                exp2f(t[nt][3] - m1));
                float2 f01 = __half22float2(h01);
                float2 f23 = __half22float2(h23);
                ps0 += f01.x + f01.y;
                ps1 += f23.x + f23.y;
                P01[nt] = *(const uint32_t*)&h01;
                P23[nt] = *(const uint32_t*)&h23;
            }
            ps0 += __shfl_xor_sync(0xFFFFFFFFu, ps0, 1);
            ps0 += __shfl_xor_sync(0xFFFFFFFFu, ps0, 2);
            ps1 += __shfl_xor_sync(0xFFFFFFFFu, ps1, 1);
            ps1 += __shfl_xor_sync(0xFFFFFFFFu, ps1, 2);
            l0 = l0 * al0 + ps0;
            l1 = l1 * al1 + ps1;

            #pragma unroll
            for (int nt = 0; nt < 8; nt++) {
                Oacc[nt][0] *= al0; Oacc[nt][1] *= al0;
                Oacc[nt][2] *= al1; Oacc[nt][3] *= al1;
            }

            // ---- O += P V  (2 k-steps of 16 keys, 8 d-tiles) ----
            #pragma unroll
            for (int kst = 0; kst < 2; kst++) {
                uint32_t a0 = P01[2 * kst];
                uint32_t a1 = P23[2 * kst];
                uint32_t a2 = P01[2 * kst + 1];
                uint32_t a3 = P23[2 * kst + 1];
                #pragma unroll
                for (int nt = 0; nt < 8; nt++) {
                    const __half* vr = Vs + (nt * 8 + fr) * HSTR + kb + 16 * kst;
                    uint32_t b0 = *(const uint32_t*)(vr + 2 * fk);
                    uint32_t b1 = *(const uint32_t*)(vr + 8 + 2 * fk);
                    mma_f16(Oacc[nt], a0, a1, a2, a3, b0, b1);
                }
            }
        }
        __syncthreads();
    }

    // ---- epilogue: normalize, tf32-round (feeds O-proj), write ----
    const int b = bh >> 4, h = bh & 15;
    const float inv0 = 1.f / l0;
    const float inv1 = 1.f / l1;
    float* O0 = O + ((size_t)(b * SS + r0g)) * DM + h * HD;
    float* O1 = O + ((size_t)(b * SS + r1g)) * DM + h * HD;
    #pragma unroll
    for (int nt = 0; nt < 8; nt++) {
        int d = nt * 8 + 2 * fk;
        *(float2*)(O0 + d) = make_float2(to_tf32(Oacc[nt][0] * inv0),
                                         to_tf32(Oacc[nt][1] * inv0));
        *(float2*)(O1 + d) = make_float2(to_tf32(Oacc[nt][2] * inv1),
                                         to_tf32(Oacc[nt][3] * inv1));
    }
}

// ---------------------------------------------------------------------------
extern "C" void kernel_launch(void* const* d_in, const int* in_sizes, int n_in,
                              void* d_out, int out_size)
{
    const float* x  = (const float*)d_in[0];
    const float* Wq = (const float*)d_in[1];
    const float* bq = (const float*)d_in[2];
    const float* Wk = (const float*)d_in[3];
    const float* bk = (const float*)d_in[4];
    const float* Wv = (const float*)d_in[5];
    const float* bv = (const float*)d_in[6];
    const float* Wo = (const float*)d_in[7];
    const float* bo = (const float*)d_in[8];

    __half *qp, *kp, *vp;
    float *ap, *xc, *wc;
    cudaGetSymbolAddress((void**)&qp, g_Qh);
    cudaGetSymbolAddress((void**)&kp, g_Kh);
    cudaGetSymbolAddress((void**)&vp, g_Vt);
    cudaGetSymbolAddress((void**)&ap, g_att);
    cudaGetSymbolAddress((void**)&xc, g_xc);
    cudaGetSymbolAddress((void**)&wc, g_Wc);

    cudaFuncSetAttribute(gemm_qk,
        cudaFuncAttributeMaxDynamicSharedMemorySize, GEMM_SMEM);
    cudaFuncSetAttribute(gemm_v,
        cudaFuncAttributeMaxDynamicSharedMemorySize, GEMM_SMEM);
    cudaFuncSetAttribute(gemm_o,
        cudaFuncAttributeMaxDynamicSharedMemorySize, GEMM_SMEM);
    cudaFuncSetAttribute(attn_h,
        cudaFuncAttributeMaxDynamicSharedMemorySize, ATTN_SMEM);

    // prep: tf32-round inputs
    cvt_x_kernel<<<MROWS * DM / 1024, 256>>>(x, xc);
    cvt_w_kernel<<<dim3(DM * DM / 1024, 4), 256>>>(Wq, Wk, Wv, Wo, wc);

    dim3 gqk(DM / 128, MROWS / 128, 2);    // (8, 32, 2)
    gemm_qk<<<gqk, 256, GEMM_SMEM>>>(xc, wc, bq, bk, qp, kp);
    dim3 gv(DM / 128, MROWS / 128);        // (8, 32)
    gemm_v<<<gv, 256, GEMM_SMEM>>>(xc, wc + 2*DM*DM, bv, vp);

    attn_h<<<dim3(SS / ABQ, BB * NH), 256, ATTN_SMEM>>>(qp, kp, vp, ap);

    gemm_o<<<gv, 256, GEMM_SMEM>>>(ap, wc + 3*DM*DM, bo, (float*)d_out);
}

// round 11
// speedup vs baseline: 7.8510x; 1.4184x over previous
#include <cuda_runtime.h>
#include <cuda_fp16.h>
#include <math.h>
#include <stdint.h>

// Problem constants
#define BB 2
#define SS 2048
#define DM 1024
#define NH 16
#define HD 64
#define MROWS (BB*SS)        // 4096

// Scratch (device globals; no allocations allowed)
__device__ __half g_xh[MROWS*DM];      // fp16 x            [m][k]
__device__ __half g_Wt[4*DM*DM];       // fp16 W^T          [n][k] x4
__device__ __half g_Qh[BB*NH*SS*HD];   // [b,h,s,d] fp16
__device__ __half g_Kh[BB*NH*SS*HD];   // [b,h,s,d] fp16
__device__ __half g_Vt[BB*NH*HD*SS];   // [b,h,d,s] fp16 (transposed)
__device__ __half g_att[BB*SS*DM];     // [b,s, h*64+d] fp16

// ---------------------------------------------------------------------------
// helpers
// ---------------------------------------------------------------------------
__device__ __forceinline__ void mma_f16(float c[4],
    uint32_t a0, uint32_t a1, uint32_t a2, uint32_t a3,
    uint32_t b0, uint32_t b1)
{
    asm volatile(
        "mma.sync.aligned.m16n8k16.row.col.f32.f16.f16.f32 "
        "{%0,%1,%2,%3}, {%4,%5,%6,%7}, {%8,%9}, {%0,%1,%2,%3};"
        : "+f"(c[0]), "+f"(c[1]), "+f"(c[2]), "+f"(c[3])
        : "r"(a0), "r"(a1), "r"(a2), "r"(a3), "r"(b0), "r"(b1));
}

__device__ __forceinline__ uint32_t smem_u32(const void* p) {
    uint32_t a;
    asm("{ .reg .u64 t; cvta.to.shared.u64 t, %1; cvt.u32.u64 %0, t; }"
        : "=r"(a) : "l"(p));
    return a;
}

#define CP16(dst, src) \
    asm volatile("cp.async.cg.shared.global [%0], [%1], 16;\n" \
                 :: "r"(dst), "l"(src))
#define CP_COMMIT() asm volatile("cp.async.commit_group;\n")
#define CP_WAIT0()  asm volatile("cp.async.wait_group 0;\n")
#define CP_WAIT1()  asm volatile("cp.async.wait_group 1;\n")

// ---------------------------------------------------------------------------
// prep: x -> fp16 (same layout); W -> fp16 transposed [n][k]
// ---------------------------------------------------------------------------
__global__ __launch_bounds__(256) void cvt_x_h(const float* __restrict__ s,
                                               __half* __restrict__ d)
{
    int i = (blockIdx.x * 256 + threadIdx.x) * 4;
    float4 v = *(const float4*)(s + i);
    *(__half2*)(d + i)     = __floats2half2_rn(v.x, v.y);
    *(__half2*)(d + i + 2) = __floats2half2_rn(v.z, v.w);
}

__global__ __launch_bounds__(256) void cvt_w_t(
    const float* __restrict__ w0, const float* __restrict__ w1,
    const float* __restrict__ w2, const float* __restrict__ w3,
    __half* __restrict__ d)
{
    __shared__ float t[32][33];
    const int z = blockIdx.z;
    const float* s = (z == 0) ? w0 : (z == 1) ? w1 : (z == 2) ? w2 : w3;
    const int k0 = blockIdx.y * 32;
    const int n0 = blockIdx.x * 32;
    const int tx = threadIdx.x & 31;
    const int ty = threadIdx.x >> 5;     // 0..7
    #pragma unroll
    for (int i = 0; i < 4; i++)
        t[ty + 8 * i][tx] = s[(size_t)(k0 + ty + 8 * i) * DM + n0 + tx];
    __syncthreads();
    __half* dz = d + (size_t)z * DM * DM;
    #pragma unroll
    for (int i = 0; i < 4; i++)
        dz[(size_t)(n0 + ty + 8 * i) * DM + k0 + tx] =
            __float2half_rn(t[tx][ty + 8 * i]);
}

// ---------------------------------------------------------------------------
// 3-stage cp.async fp16 GEMM body: C[4096,1024] = A @ W + bias
// A fp16 [m][k]; Wt fp16 [n][k] (pre-transposed). 128x128 tile, BK=64,
// 256 threads, m16n8k16 f16 mma with fp32 accum, 1 barrier per k-tile.
// OUTMODE: 0 = fp32 row-major; 1 = fp16 [b,h,s,d] (Q,K);
//          2 = fp16 [b,h,d,s] transposed (V).
// ---------------------------------------------------------------------------
#define GSTAGES 3
#define GBK 64
#define HST 72                   // halves per smem row (64 + 8 pad)
#define STAGE_H (128*HST)        // halves per A or B stage (9216)
#define GEMM_SMEM (GSTAGES*2*STAGE_H*2)   // 110592 B
#define GNT (DM/GBK)             // 16 k-tiles

template<int OUTMODE>
__device__ __forceinline__ void gemm_body(
    const __half* __restrict__ A, const __half* __restrict__ Wt,
    const float* __restrict__ bias, void* __restrict__ Cv)
{
    extern __shared__ __half smh[];
    // layout: A0 | A1 | A2 | B0 | B1 | B2

    const int tid  = threadIdx.x;
    const int warp = tid >> 5;
    const int lane = tid & 31;
    const int wm   = (warp >> 2) * 64;
    const int wn   = (warp & 3) * 32;
    const int row0 = blockIdx.y * 128;
    const int col0 = blockIdx.x * 128;
    const int fr   = lane >> 2;
    const int fk   = lane & 3;

    const uint32_t sbase = smem_u32(smh);

    float acc[4][4][4];
    #pragma unroll
    for (int i = 0; i < 4; i++)
        #pragma unroll
        for (int j = 0; j < 4; j++)
            #pragma unroll
            for (int r = 0; r < 4; r++) acc[i][j][r] = 0.f;

    // cp.async: per stage A = 128 rows x 128B, B = 128 rows x 128B.
    // 1024 16B-chunks each; thread does 4 A-chunks + 4 B-chunks.
    #define G_ISSUE(kt, s) do {                                              \
        uint32_t abase = sbase + (uint32_t)(s) * (STAGE_H * 2);              \
        uint32_t bbase = sbase + (uint32_t)((GSTAGES + (s)) * STAGE_H) * 2;  \
        _Pragma("unroll")                                                    \
        for (int i = 0; i < 4; i++) {                                        \
            int chunk = tid + 256 * i;                                       \
            int row  = chunk >> 3;                                           \
            int coff = (chunk & 7) * 8;                                      \
            CP16(abase + (uint32_t)(row * HST + coff) * 2,                   \
                 A  + (size_t)(row0 + row) * DM + (kt) * GBK + coff);        \
            CP16(bbase + (uint32_t)(row * HST + coff) * 2,                   \
                 Wt + (size_t)(col0 + row) * DM + (kt) * GBK + coff);        \
        }                                                                    \
        CP_COMMIT();                                                         \
    } while (0)

    G_ISSUE(0, 0);
    G_ISSUE(1, 1);

    for (int kt = 0; kt < GNT; kt++) {
        const int cur = kt % GSTAGES;
        CP_WAIT1();            // k-tile kt landed (one newer group may pend)
        __syncthreads();       // single barrier also fences slot reuse
        if (kt + 2 < GNT) {
            G_ISSUE(kt + 2, (kt + 2) % GSTAGES);
        } else {
            CP_COMMIT();       // keep wait_group accounting uniform
        }

        const __half* As = smh + cur * STAGE_H;
        const __half* Bs = smh + (GSTAGES + cur) * STAGE_H;

        #pragma unroll
        for (int ks = 0; ks < 4; ks++) {     // 4 k-steps of 16
            uint32_t af[4][4];
            uint32_t bf[4][2];
            #pragma unroll
            for (int mi = 0; mi < 4; mi++) {
                const __half* ar0 = As + (wm + mi * 16 + fr) * HST + 16 * ks;
                const __half* ar1 = ar0 + 8 * HST;
                af[mi][0] = *(const uint32_t*)(ar0 + 2 * fk);
                af[mi][1] = *(const uint32_t*)(ar1 + 2 * fk);
                af[mi][2] = *(const uint32_t*)(ar0 + 8 + 2 * fk);
                af[mi][3] = *(const uint32_t*)(ar1 + 8 + 2 * fk);
            }
            #pragma unroll
            for (int ni = 0; ni < 4; ni++) {
                const __half* br = Bs + (wn + ni * 8 + fr) * HST + 16 * ks;
                bf[ni][0] = *(const uint32_t*)(br + 2 * fk);
                bf[ni][1] = *(const uint32_t*)(br + 8 + 2 * fk);
            }
            #pragma unroll
            for (int mi = 0; mi < 4; mi++)
                #pragma unroll
                for (int ni = 0; ni < 4; ni++)
                    mma_f16(acc[mi][ni],
                            af[mi][0], af[mi][1], af[mi][2], af[mi][3],
                            bf[ni][0], bf[ni][1]);
        }
    }

    // ---- epilogue ----
    #pragma unroll
    for (int mi = 0; mi < 4; mi++) {
        int r = row0 + wm + mi * 16 + fr;
        #pragma unroll
        for (int ni = 0; ni < 4; ni++) {
            int c = col0 + wn + ni * 8 + 2 * fk;
            float bb0 = bias[c], bb1 = bias[c + 1];
            float v0 = acc[mi][ni][0] + bb0, v1 = acc[mi][ni][1] + bb1;
            float v2 = acc[mi][ni][2] + bb0, v3 = acc[mi][ni][3] + bb1;
            if (OUTMODE == 0) {
                float* C = (float*)Cv;
                *(float2*)&C[(size_t)r * DM + c]       = make_float2(v0, v1);
                *(float2*)&C[(size_t)(r + 8) * DM + c] = make_float2(v2, v3);
            } else if (OUTMODE == 1) {
                __half* C = (__half*)Cv;
                int h = c >> 6, d = c & 63;
                int b0i = r >> 11, s0 = r & 2047;
                size_t i0 = ((((size_t)b0i * NH + h) * SS + s0) * HD) + d;
                *(__half2*)&C[i0] = __floats2half2_rn(v0, v1);
                int r2 = r + 8;
                int b1i = r2 >> 11, s1 = r2 & 2047;
                size_t i1 = ((((size_t)b1i * NH + h) * SS + s1) * HD) + d;
                *(__half2*)&C[i1] = __floats2half2_rn(v2, v3);
            } else {
                __half* C = (__half*)Cv;       // [b,h,d,s]
                int h = c >> 6, d = c & 63;
                int b0i = r >> 11, s0 = r & 2047;
                int r2 = r + 8;
                int b1i = r2 >> 11, s1 = r2 & 2047;
                size_t base0 = (((size_t)b0i * NH + h) * HD);
                size_t base1 = (((size_t)b1i * NH + h) * HD);
                C[(base0 + d    ) * SS + s0] = __float2half_rn(v0);
                C[(base0 + d + 1) * SS + s0] = __float2half_rn(v1);
                C[(base1 + d    ) * SS + s1] = __float2half_rn(v2);
                C[(base1 + d + 1) * SS + s1] = __float2half_rn(v3);
            }
        }
    }
    #undef G_ISSUE
}

// merged QKV: gridDim.z = 3; z<2 -> head-split fp16 (Q,K), z=2 -> V transposed
__global__ __launch_bounds__(256, 2) void gemm_qkv(
    const __half* __restrict__ A, const __half* __restrict__ Wt,
    const float* __restrict__ b0, const float* __restrict__ b1,
    const float* __restrict__ b2,
    __half* __restrict__ C0, __half* __restrict__ C1, __half* __restrict__ C2)
{
    const int z = blockIdx.z;
    const __half* W = Wt + (size_t)z * DM * DM;
    if (z == 2) {
        gemm_body<2>(A, W, b2, C2);
    } else {
        gemm_body<1>(A, W, z ? b1 : b0, z ? C1 : C0);
    }
}

__global__ __launch_bounds__(256, 2) void gemm_o(
    const __half* __restrict__ A, const __half* __restrict__ Wt,
    const float* __restrict__ bias, float* __restrict__ C)
{
    gemm_body<0>(A, Wt, bias, C);
}

// ---------------------------------------------------------------------------
// fp16 tensor-core flash attention (causal), m16n8k16, fp32 accum.
// Unchanged from R10 except the epilogue writes fp16 (feeds fp16 O-proj).
// ---------------------------------------------------------------------------
#define ABQ 128
#define LKEYS 64
#define HSTR 72
#define KSTAGE_H (LKEYS*HSTR)
#define ATTN_SMEM (4*KSTAGE_H*2)      // 36864 B

__global__ __launch_bounds__(256) void attn_h(
    const __half* __restrict__ Q, const __half* __restrict__ K,
    const __half* __restrict__ Vt, __half* __restrict__ O)
{
    extern __shared__ __half smh[];
    // layout: K stage0 | K stage1 | V stage0 | V stage1

    const int bh   = blockIdx.y;
    const int qb   = gridDim.x - 1 - blockIdx.x;  // heavy blocks first
    const int q0   = qb * ABQ;
    const int tid  = threadIdx.x;
    const int warp = tid >> 5;
    const int lane = tid & 31;
    const int fr   = lane >> 2;
    const int fk   = lane & 3;
    const int wrow = warp * 16;

    const __half* Qb  = Q  + (size_t)bh * SS * HD;
    const __half* Kb  = K  + (size_t)bh * SS * HD;
    const __half* Vtb = Vt + (size_t)bh * HD * SS;

    uint32_t Qf[4][4];
    {
        const __half* qr0 = Qb + (size_t)(q0 + wrow + fr) * HD;
        const __half* qr1 = qr0 + 8 * HD;
        #pragma unroll
        for (int ks = 0; ks < 4; ks++) {
            Qf[ks][0] = *(const uint32_t*)(qr0 + 16 * ks + 2 * fk);
            Qf[ks][1] = *(const uint32_t*)(qr1 + 16 * ks + 2 * fk);
            Qf[ks][2] = *(const uint32_t*)(qr0 + 16 * ks + 8 + 2 * fk);
            Qf[ks][3] = *(const uint32_t*)(qr1 + 16 * ks + 8 + 2 * fk);
        }
    }

    float Oacc[8][4];
    #pragma unroll
    for (int nt = 0; nt < 8; nt++)
        #pragma unroll
        for (int r = 0; r < 4; r++) Oacc[nt][r] = 0.f;

    float m0 = -INFINITY, m1 = -INFINITY, l0 = 0.f, l1 = 0.f;
    const float tsc = 0.18033688f;     // (1/sqrt(64)) * log2(e)

    const int r0g = q0 + wrow + fr;
    const int r1g = r0g + 8;

    const int nload = (q0 + ABQ) / LKEYS;

    const int crow = tid >> 3;           // 0..31
    const int coff = (tid & 7) * 8;      // halves
    const uint32_t sbase = smem_u32(smh);

    #define A_ISSUE(lt, s) do {                                              \
        const int kk0 = (lt) * LKEYS;                                        \
        uint32_t koff = sbase + (uint32_t)(s) * (KSTAGE_H * 2);              \
        uint32_t voff = sbase + (uint32_t)((2 + (s)) * KSTAGE_H) * 2;        \
        _Pragma("unroll")                                                    \
        for (int i = 0; i < 2; i++) {                                        \
            int row = crow + 32 * i;                                         \
            CP16(koff + (uint32_t)(row * HSTR + coff) * 2,                   \
                 Kb + (size_t)(kk0 + row) * HD + coff);                      \
            CP16(voff + (uint32_t)(row * HSTR + coff) * 2,                   \
                 Vtb + (size_t)row * SS + kk0 + coff);                       \
        }                                                                    \
        CP_COMMIT();                                                         \
    } while (0)

    A_ISSUE(0, 0);

    for (int lt = 0; lt < nload; lt++) {
        const int k0  = lt * LKEYS;
        const int buf = lt & 1;
        CP_WAIT0();
        __syncthreads();
        if (lt + 1 < nload) A_ISSUE(lt + 1, buf ^ 1);

        const __half* Ks = smh + buf * KSTAGE_H;
        const __half* Vs = smh + (2 + buf) * KSTAGE_H;

        #pragma unroll
        for (int half = 0; half < 2; half++) {
            const int kh = k0 + half * 32;
            if (kh > q0 + wrow + 15) continue;
            const int kb = half * 32;

            float Sacc[4][4];
            #pragma unroll
            for (int nt = 0; nt < 4; nt++)
                #pragma unroll
                for (int r = 0; r < 4; r++) Sacc[nt][r] = 0.f;

            #pragma unroll
            for (int ks = 0; ks < 4; ks++) {
                #pragma unroll
                for (int nt = 0; nt < 4; nt++) {
                    const __half* kr = Ks + (kb + nt * 8 + fr) * HSTR + 16 * ks;
                    uint32_t b0 = *(const uint32_t*)(kr + 2 * fk);
                    uint32_t b1 = *(const uint32_t*)(kr + 8 + 2 * fk);
                    mma_f16(Sacc[nt], Qf[ks][0], Qf[ks][1], Qf[ks][2], Qf[ks][3],
                            b0, b1);
                }
            }

            float t[4][4];
            #pragma unroll
            for (int nt = 0; nt < 4; nt++) {
                int c0 = kh + nt * 8 + 2 * fk;
                t[nt][0] = (c0     <= r0g) ? Sacc[nt][0] * tsc : -INFINITY;
                t[nt][1] = (c0 + 1 <= r0g) ? Sacc[nt][1] * tsc : -INFINITY;
                t[nt][2] = (c0     <= r1g) ? Sacc[nt][2] * tsc : -INFINITY;
                t[nt][3] = (c0 + 1 <= r1g) ? Sacc[nt][3] * tsc : -INFINITY;
            }

            float mx0 = t[0][0], mx1 = t[0][2];
            #pragma unroll
            for (int nt = 0; nt < 4; nt++) {
                mx0 = fmaxf(mx0, fmaxf(t[nt][0], t[nt][1]));
                mx1 = fmaxf(mx1, fmaxf(t[nt][2], t[nt][3]));
            }
            mx0 = fmaxf(mx0, __shfl_xor_sync(0xFFFFFFFFu, mx0, 1));
            mx0 = fmaxf(mx0, __shfl_xor_sync(0xFFFFFFFFu, mx0, 2));
            mx1 = fmaxf(mx1, __shfl_xor_sync(0xFFFFFFFFu, mx1, 1));
            mx1 = fmaxf(mx1, __shfl_xor_sync(0xFFFFFFFFu, mx1, 2));

            float mn0 = fmaxf(m0, mx0);
            float mn1 = fmaxf(m1, mx1);
            float al0 = exp2f(m0 - mn0);
            float al1 = exp2f(m1 - mn1);
            m0 = mn0; m1 = mn1;

            uint32_t P01[4], P23[4];
            float ps0 = 0.f, ps1 = 0.f;
            #pragma unroll
            for (int nt = 0; nt < 4; nt++) {
                __half2 h01 = __floats2half2_rn(exp2f(t[nt][0] - m0),
                                                exp2f(t[nt][1] - m0));
                __half2 h23 = __floats2half2_rn(exp2f(t[nt][2] - m1),
                                                exp2f(t[nt][3] - m1));
                float2 f01 = __half22float2(h01);
                float2 f23 = __half22float2(h23);
                ps0 += f01.x + f01.y;
                ps1 += f23.x + f23.y;
                P01[nt] = *(const uint32_t*)&h01;
                P23[nt] = *(const uint32_t*)&h23;
            }
            ps0 += __shfl_xor_sync(0xFFFFFFFFu, ps0, 1);
            ps0 += __shfl_xor_sync(0xFFFFFFFFu, ps0, 2);
            ps1 += __shfl_xor_sync(0xFFFFFFFFu, ps1, 1);
            ps1 += __shfl_xor_sync(0xFFFFFFFFu, ps1, 2);
            l0 = l0 * al0 + ps0;
            l1 = l1 * al1 + ps1;

            #pragma unroll
            for (int nt = 0; nt < 8; nt++) {
                Oacc[nt][0] *= al0; Oacc[nt][1] *= al0;
                Oacc[nt][2] *= al1; Oacc[nt][3] *= al1;
            }

            #pragma unroll
            for (int kst = 0; kst < 2; kst++) {
                uint32_t a0 = P01[2 * kst];
                uint32_t a1 = P23[2 * kst];
                uint32_t a2 = P01[2 * kst + 1];
                uint32_t a3 = P23[2 * kst + 1];
                #pragma unroll
                for (int nt = 0; nt < 8; nt++) {
                    const __half* vr = Vs + (nt * 8 + fr) * HSTR + kb + 16 * kst;
                    uint32_t b0 = *(const uint32_t*)(vr + 2 * fk);
                    uint32_t b1 = *(const uint32_t*)(vr + 8 + 2 * fk);
                    mma_f16(Oacc[nt], a0, a1, a2, a3, b0, b1);
                }
            }
        }
        __syncthreads();
    }

    // ---- epilogue: normalize, write fp16 [b, s, h*64+d] ----
    const int b = bh >> 4, h = bh & 15;
    const float inv0 = 1.f / l0;
    const float inv1 = 1.f / l1;
    __half* O0 = O + ((size_t)(b * SS + r0g)) * DM + h * HD;
    __half* O1 = O + ((size_t)(b * SS + r1g)) * DM + h * HD;
    #pragma unroll
    for (int nt = 0; nt < 8; nt++) {
        int d = nt * 8 + 2 * fk;
        *(__half2*)(O0 + d) = __floats2half2_rn(Oacc[nt][0] * inv0,
                                                Oacc[nt][1] * inv0);
        *(__half2*)(O1 + d) = __floats2half2_rn(Oacc[nt][2] * inv1,
                                                Oacc[nt][3] * inv1);
    }
}

// ---------------------------------------------------------------------------
extern "C" void kernel_launch(void* const* d_in, const int* in_sizes, int n_in,
                              void* d_out, int out_size)
{
    const float* x  = (const float*)d_in[0];
    const float* Wq = (const float*)d_in[1];
    const float* bq = (const float*)d_in[2];
    const float* Wk = (const float*)d_in[3];
    const float* bk = (const float*)d_in[4];
    const float* Wv = (const float*)d_in[5];
    const float* bv = (const float*)d_in[6];
    const float* Wo = (const float*)d_in[7];
    const float* bo = (const float*)d_in[8];

    __half *xh, *wt, *qp, *kp, *vp, *ap;
    cudaGetSymbolAddress((void**)&xh, g_xh);
    cudaGetSymbolAddress((void**)&wt, g_Wt);
    cudaGetSymbolAddress((void**)&qp, g_Qh);
    cudaGetSymbolAddress((void**)&kp, g_Kh);
    cudaGetSymbolAddress((void**)&vp, g_Vt);
    cudaGetSymbolAddress((void**)&ap, g_att);

    cudaFuncSetAttribute(gemm_qkv,
        cudaFuncAttributeMaxDynamicSharedMemorySize, GEMM_SMEM);
    cudaFuncSetAttribute(gemm_o,
        cudaFuncAttributeMaxDynamicSharedMemorySize, GEMM_SMEM);
    cudaFuncSetAttribute(attn_h,
        cudaFuncAttributeMaxDynamicSharedMemorySize, ATTN_SMEM);

    // prep: fp16 conversions (+ weight transpose)
    cvt_x_h<<<MROWS * DM / 1024, 256>>>(x, xh);
    cvt_w_t<<<dim3(DM / 32, DM / 32, 4), 256>>>(Wq, Wk, Wv, Wo, wt);

    dim3 gqkv(DM / 128, MROWS / 128, 3);   // (8, 32, 3)
    gemm_qkv<<<gqkv, 256, GEMM_SMEM>>>(xh, wt, bq, bk, bv, qp, kp, vp);

    attn_h<<<dim3(SS / ABQ, BB * NH), 256, ATTN_SMEM>>>(qp, kp, vp, ap);

    dim3 go(DM / 128, MROWS / 128);        // (8, 32)
    gemm_o<<<go, 256, GEMM_SMEM>>>(ap, wt + (size_t)3*DM*DM, bo, (float*)d_out);
}

// round 12
// speedup vs baseline: 9.1368x; 1.1638x over previous
#include <cuda_runtime.h>
#include <cuda_fp16.h>
#include <math.h>
#include <stdint.h>

// Problem constants
#define BB 2
#define SS 2048
#define DM 1024
#define NH 16
#define HD 64
#define MROWS (BB*SS)        // 4096

// Scratch (device globals; no allocations allowed)
__device__ __half g_xh[MROWS*DM];      // fp16 x            [m][k]
__device__ __half g_Wt[4*DM*DM];       // fp16 W^T          [n][k] x4
__device__ __half g_Qh[BB*NH*SS*HD];   // [b,h,s,d] fp16
__device__ __half g_Kh[BB*NH*SS*HD];   // [b,h,s,d] fp16
__device__ __half g_Vt[BB*NH*HD*SS];   // [b,h,d,s] fp16 (transposed)
__device__ __half g_att[BB*SS*DM];     // [b,s, h*64+d] fp16

// ---------------------------------------------------------------------------
// helpers
// ---------------------------------------------------------------------------
__device__ __forceinline__ void mma_f16(float c[4],
    uint32_t a0, uint32_t a1, uint32_t a2, uint32_t a3,
    uint32_t b0, uint32_t b1)
{
    asm volatile(
        "mma.sync.aligned.m16n8k16.row.col.f32.f16.f16.f32 "
        "{%0,%1,%2,%3}, {%4,%5,%6,%7}, {%8,%9}, {%0,%1,%2,%3};"
        : "+f"(c[0]), "+f"(c[1]), "+f"(c[2]), "+f"(c[3])
        : "r"(a0), "r"(a1), "r"(a2), "r"(a3), "r"(b0), "r"(b1));
}

__device__ __forceinline__ uint32_t smem_u32(const void* p) {
    uint32_t a;
    asm("{ .reg .u64 t; cvta.to.shared.u64 t, %1; cvt.u32.u64 %0, t; }"
        : "=r"(a) : "l"(p));
    return a;
}

#define LDSM4(r0, r1, r2, r3, addr) \
    asm volatile("ldmatrix.sync.aligned.m8n8.x4.shared.b16 {%0,%1,%2,%3}, [%4];" \
                 : "=r"(r0), "=r"(r1), "=r"(r2), "=r"(r3) : "r"(addr))

#define CP16(dst, src) \
    asm volatile("cp.async.cg.shared.global [%0], [%1], 16;\n" \
                 :: "r"(dst), "l"(src))
#define CP_COMMIT() asm volatile("cp.async.commit_group;\n")
#define CP_WAIT0()  asm volatile("cp.async.wait_group 0;\n")
#define CP_WAIT1()  asm volatile("cp.async.wait_group 1;\n")

// ---------------------------------------------------------------------------
// prep: x -> fp16 (same layout); W -> fp16 transposed [n][k]
// ---------------------------------------------------------------------------
__global__ __launch_bounds__(256) void cvt_x_h(const float* __restrict__ s,
                                               __half* __restrict__ d)
{
    int i = (blockIdx.x * 256 + threadIdx.x) * 4;
    float4 v = *(const float4*)(s + i);
    *(__half2*)(d + i)     = __floats2half2_rn(v.x, v.y);
    *(__half2*)(d + i + 2) = __floats2half2_rn(v.z, v.w);
}

__global__ __launch_bounds__(256) void cvt_w_t(
    const float* __restrict__ w0, const float* __restrict__ w1,
    const float* __restrict__ w2, const float* __restrict__ w3,
    __half* __restrict__ d)
{
    __shared__ float t[32][33];
    const int z = blockIdx.z;
    const float* s = (z == 0) ? w0 : (z == 1) ? w1 : (z == 2) ? w2 : w3;
    const int k0 = blockIdx.y * 32;
    const int n0 = blockIdx.x * 32;
    const int tx = threadIdx.x & 31;
    const int ty = threadIdx.x >> 5;     // 0..7
    #pragma unroll
    for (int i = 0; i < 4; i++)
        t[ty + 8 * i][tx] = s[(size_t)(k0 + ty + 8 * i) * DM + n0 + tx];
    __syncthreads();
    __half* dz = d + (size_t)z * DM * DM;
    #pragma unroll
    for (int i = 0; i < 4; i++)
        dz[(size_t)(n0 + ty + 8 * i) * DM + k0 + tx] =
            __float2half_rn(t[tx][ty + 8 * i]);
}

// ---------------------------------------------------------------------------
// 3-stage cp.async fp16 GEMM body, ldmatrix fragments.
// A fp16 [m][k]; Wt fp16 [n][k]. 128x128 tile, BK=64, m16n8k16, fp32 accum.
// OUTMODE: 0 = fp32 row-major; 1 = fp16 [b,h,s,d]; 2 = fp16 [b,h,d,s].
// ---------------------------------------------------------------------------
#define GSTAGES 3
#define GBK 64
#define HST 72                   // halves per smem row (64 + 8 pad)
#define STAGE_H (128*HST)        // halves per A or B stage (9216)
#define GEMM_SMEM (GSTAGES*2*STAGE_H*2)   // 110592 B
#define GNT (DM/GBK)             // 16 k-tiles

template<int OUTMODE>
__device__ __forceinline__ void gemm_body(
    const __half* __restrict__ A, const __half* __restrict__ Wt,
    const float* __restrict__ bias, void* __restrict__ Cv)
{
    extern __shared__ __half smh[];
    // layout: A0 | A1 | A2 | B0 | B1 | B2

    const int tid  = threadIdx.x;
    const int warp = tid >> 5;
    const int lane = tid & 31;
    const int wm   = (warp >> 2) * 64;
    const int wn   = (warp & 3) * 32;
    const int row0 = blockIdx.y * 128;
    const int col0 = blockIdx.x * 128;
    const int fr   = lane >> 2;
    const int fk   = lane & 3;
    const int g    = lane >> 3;      // ldmatrix address group 0..3
    const int rr   = lane & 7;

    const uint32_t sbase = smem_u32(smh);

    // ldmatrix lane-address offsets (bytes), per mi / per ni-pair
    uint32_t aoff[4], boff[2];
    #pragma unroll
    for (int mi = 0; mi < 4; mi++)
        aoff[mi] = (uint32_t)((wm + mi * 16 + ((g & 1) << 3) + rr) * HST
                              + ((g >> 1) << 3)) * 2;
    #pragma unroll
    for (int p = 0; p < 2; p++)
        boff[p] = (uint32_t)((wn + p * 16 + ((g >> 1) << 3) + rr) * HST
                             + ((g & 1) << 3)) * 2;

    float acc[4][4][4];
    #pragma unroll
    for (int i = 0; i < 4; i++)
        #pragma unroll
        for (int j = 0; j < 4; j++)
            #pragma unroll
            for (int r = 0; r < 4; r++) acc[i][j][r] = 0.f;

    #define G_ISSUE(kt, s) do {                                              \
        uint32_t abase = sbase + (uint32_t)(s) * (STAGE_H * 2);              \
        uint32_t bbase = sbase + (uint32_t)((GSTAGES + (s)) * STAGE_H) * 2;  \
        _Pragma("unroll")                                                    \
        for (int i = 0; i < 4; i++) {                                        \
            int chunk = tid + 256 * i;                                       \
            int row  = chunk >> 3;                                           \
            int coff = (chunk & 7) * 8;                                      \
            CP16(abase + (uint32_t)(row * HST + coff) * 2,                   \
                 A  + (size_t)(row0 + row) * DM + (kt) * GBK + coff);        \
            CP16(bbase + (uint32_t)(row * HST + coff) * 2,                   \
                 Wt + (size_t)(col0 + row) * DM + (kt) * GBK + coff);        \
        }                                                                    \
        CP_COMMIT();                                                         \
    } while (0)

    G_ISSUE(0, 0);
    G_ISSUE(1, 1);

    for (int kt = 0; kt < GNT; kt++) {
        const int cur = kt % GSTAGES;
        CP_WAIT1();
        __syncthreads();
        if (kt + 2 < GNT) {
            G_ISSUE(kt + 2, (kt + 2) % GSTAGES);
        } else {
            CP_COMMIT();
        }

        const uint32_t abase = sbase + (uint32_t)cur * (STAGE_H * 2);
        const uint32_t bbase = sbase + (uint32_t)((GSTAGES + cur) * STAGE_H) * 2;

        #pragma unroll
        for (int ks = 0; ks < 4; ks++) {     // 4 k-steps of 16
            uint32_t af[4][4];
            uint32_t bf[2][4];
            #pragma unroll
            for (int mi = 0; mi < 4; mi++)
                LDSM4(af[mi][0], af[mi][1], af[mi][2], af[mi][3],
                      abase + aoff[mi] + 32 * ks);
            #pragma unroll
            for (int p = 0; p < 2; p++)
                LDSM4(bf[p][0], bf[p][1], bf[p][2], bf[p][3],
                      bbase + boff[p] + 32 * ks);
            #pragma unroll
            for (int mi = 0; mi < 4; mi++)
                #pragma unroll
                for (int ni = 0; ni < 4; ni++)
                    mma_f16(acc[mi][ni],
                            af[mi][0], af[mi][1], af[mi][2], af[mi][3],
                            bf[ni >> 1][(ni & 1) * 2],
                            bf[ni >> 1][(ni & 1) * 2 + 1]);
        }
    }

    // ---- epilogue ----
    #pragma unroll
    for (int mi = 0; mi < 4; mi++) {
        int r = row0 + wm + mi * 16 + fr;
        #pragma unroll
        for (int ni = 0; ni < 4; ni++) {
            int c = col0 + wn + ni * 8 + 2 * fk;
            float bb0 = bias[c], bb1 = bias[c + 1];
            float v0 = acc[mi][ni][0] + bb0, v1 = acc[mi][ni][1] + bb1;
            float v2 = acc[mi][ni][2] + bb0, v3 = acc[mi][ni][3] + bb1;
            if (OUTMODE == 0) {
                float* C = (float*)Cv;
                *(float2*)&C[(size_t)r * DM + c]       = make_float2(v0, v1);
                *(float2*)&C[(size_t)(r + 8) * DM + c] = make_float2(v2, v3);
            } else if (OUTMODE == 1) {
                __half* C = (__half*)Cv;
                int h = c >> 6, d = c & 63;
                int b0i = r >> 11, s0 = r & 2047;
                size_t i0 = ((((size_t)b0i * NH + h) * SS + s0) * HD) + d;
                *(__half2*)&C[i0] = __floats2half2_rn(v0, v1);
                int r2 = r + 8;
                int b1i = r2 >> 11, s1 = r2 & 2047;
                size_t i1 = ((((size_t)b1i * NH + h) * SS + s1) * HD) + d;
                *(__half2*)&C[i1] = __floats2half2_rn(v2, v3);
            } else {
                __half* C = (__half*)Cv;       // [b,h,d,s]
                int h = c >> 6, d = c & 63;
                int b0i = r >> 11, s0 = r & 2047;
                int r2 = r + 8;
                int b1i = r2 >> 11, s1 = r2 & 2047;
                size_t base0 = (((size_t)b0i * NH + h) * HD);
                size_t base1 = (((size_t)b1i * NH + h) * HD);
                C[(base0 + d    ) * SS + s0] = __float2half_rn(v0);
                C[(base0 + d + 1) * SS + s0] = __float2half_rn(v1);
                C[(base1 + d    ) * SS + s1] = __float2half_rn(v2);
                C[(base1 + d + 1) * SS + s1] = __float2half_rn(v3);
            }
        }
    }
    #undef G_ISSUE
}

__global__ __launch_bounds__(256, 2) void gemm_qkv(
    const __half* __restrict__ A, const __half* __restrict__ Wt,
    const float* __restrict__ b0, const float* __restrict__ b1,
    const float* __restrict__ b2,
    __half* __restrict__ C0, __half* __restrict__ C1, __half* __restrict__ C2)
{
    const int z = blockIdx.z;
    const __half* W = Wt + (size_t)z * DM * DM;
    if (z == 2) {
        gemm_body<2>(A, W, b2, C2);
    } else {
        gemm_body<1>(A, W, z ? b1 : b0, z ? C1 : C0);
    }
}

__global__ __launch_bounds__(256, 2) void gemm_o(
    const __half* __restrict__ A, const __half* __restrict__ Wt,
    const float* __restrict__ bias, float* __restrict__ C)
{
    gemm_body<0>(A, Wt, bias, C);
}

// ---------------------------------------------------------------------------
// fp16 flash attention (causal), m16n8k16, fp32 accum. R12:
//  - ldmatrix.x4 K/V fragment loads
//  - single 64-key softmax pass per stage (was 2 x 32)
//  - unmasked fast path for interior stages; rescale skipped when alpha==1
// ---------------------------------------------------------------------------
#define ABQ 128
#define LKEYS 64
#define HSTR 72
#define KSTAGE_H (LKEYS*HSTR)
#define ATTN_SMEM (4*KSTAGE_H*2)      // 36864 B

__global__ __launch_bounds__(256, 2) void attn_h(
    const __half* __restrict__ Q, const __half* __restrict__ K,
    const __half* __restrict__ Vt, __half* __restrict__ O)
{
    extern __shared__ __half smh[];
    // layout: K stage0 | K stage1 | V stage0 | V stage1

    const int bh   = blockIdx.y;
    const int qb   = gridDim.x - 1 - blockIdx.x;  // heavy blocks first
    const int q0   = qb * ABQ;
    const int tid  = threadIdx.x;
    const int warp = tid >> 5;
    const int lane = tid & 31;
    const int fr   = lane >> 2;
    const int fk   = lane & 3;
    const int g    = lane >> 3;
    const int rr   = lane & 7;
    const int wrow = warp * 16;

    const __half* Qb  = Q  + (size_t)bh * SS * HD;
    const __half* Kb  = K  + (size_t)bh * SS * HD;
    const __half* Vtb = Vt + (size_t)bh * HD * SS;

    uint32_t Qf[4][4];
    {
        const __half* qr0 = Qb + (size_t)(q0 + wrow + fr) * HD;
        const __half* qr1 = qr0 + 8 * HD;
        #pragma unroll
        for (int ks = 0; ks < 4; ks++) {
            Qf[ks][0] = *(const uint32_t*)(qr0 + 16 * ks + 2 * fk);
            Qf[ks][1] = *(const uint32_t*)(qr1 + 16 * ks + 2 * fk);
            Qf[ks][2] = *(const uint32_t*)(qr0 + 16 * ks + 8 + 2 * fk);
            Qf[ks][3] = *(const uint32_t*)(qr1 + 16 * ks + 8 + 2 * fk);
        }
    }

    float Oacc[8][4];
    #pragma unroll
    for (int nt = 0; nt < 8; nt++)
        #pragma unroll
        for (int r = 0; r < 4; r++) Oacc[nt][r] = 0.f;

    float m0 = -INFINITY, m1 = -INFINITY, l0 = 0.f, l1 = 0.f;
    const float tsc = 0.18033688f;     // (1/sqrt(64)) * log2(e)

    const int r0g = q0 + wrow + fr;
    const int r1g = r0g + 8;

    const int nload = (q0 + ABQ) / LKEYS;

    // ldmatrix lane offsets (bytes): K/V rows as n8k16 B-operand pairs
    uint32_t kvoff[4];
    #pragma unroll
    for (int p = 0; p < 4; p++)
        kvoff[p] = (uint32_t)((p * 16 + ((g >> 1) << 3) + rr) * HSTR
                              + ((g & 1) << 3)) * 2;

    const int crow = tid >> 3;           // 0..31
    const int coff = (tid & 7) * 8;      // halves
    const uint32_t sbase = smem_u32(smh);

    #define A_ISSUE(lt, s) do {                                              \
        const int kk0 = (lt) * LKEYS;                                        \
        uint32_t koff = sbase + (uint32_t)(s) * (KSTAGE_H * 2);              \
        uint32_t voff = sbase + (uint32_t)((2 + (s)) * KSTAGE_H) * 2;        \
        _Pragma("unroll")                                                    \
        for (int i = 0; i < 2; i++) {                                        \
            int row = crow + 32 * i;                                         \
            CP16(koff + (uint32_t)(row * HSTR + coff) * 2,                   \
                 Kb + (size_t)(kk0 + row) * HD + coff);                      \
            CP16(voff + (uint32_t)(row * HSTR + coff) * 2,                   \
                 Vtb + (size_t)row * SS + kk0 + coff);                       \
        }                                                                    \
        CP_COMMIT();                                                         \
    } while (0)

    A_ISSUE(0, 0);

    for (int lt = 0; lt < nload; lt++) {
        const int k0  = lt * LKEYS;
        const int buf = lt & 1;
        CP_WAIT0();
        __syncthreads();
        if (lt + 1 < nload) A_ISSUE(lt + 1, buf ^ 1);

        const bool active = (k0 <= q0 + wrow + 15);   // warp-uniform
        if (active) {
            const uint32_t kbase = sbase + (uint32_t)buf * (KSTAGE_H * 2);
            const uint32_t vbase = sbase + (uint32_t)((2 + buf) * KSTAGE_H) * 2;

            // ---- S = Q K^T over 64 keys (8 n-tiles) ----
            float Sacc[8][4];
            #pragma unroll
            for (int nt = 0; nt < 8; nt++)
                #pragma unroll
                for (int r = 0; r < 4; r++) Sacc[nt][r] = 0.f;

            #pragma unroll
            for (int ks = 0; ks < 4; ks++) {
                uint32_t kf[4][4];
                #pragma unroll
                for (int p = 0; p < 4; p++)
                    LDSM4(kf[p][0], kf[p][1], kf[p][2], kf[p][3],
                          kbase + kvoff[p] + 32 * ks);
                #pragma unroll
                for (int nt = 0; nt < 8; nt++)
                    mma_f16(Sacc[nt],
                            Qf[ks][0], Qf[ks][1], Qf[ks][2], Qf[ks][3],
                            kf[nt >> 1][(nt & 1) * 2],
                            kf[nt >> 1][(nt & 1) * 2 + 1]);
            }

            // ---- scale (+ mask only near diagonal) ----
            const bool full = (k0 + 63 <= q0 + wrow);  // warp-uniform
            if (full) {
                #pragma unroll
                for (int nt = 0; nt < 8; nt++) {
                    Sacc[nt][0] *= tsc; Sacc[nt][1] *= tsc;
                    Sacc[nt][2] *= tsc; Sacc[nt][3] *= tsc;
                }
            } else {
                #pragma unroll
                for (int nt = 0; nt < 8; nt++) {
                    int c0 = k0 + nt * 8 + 2 * fk;
                    Sacc[nt][0] = (c0     <= r0g) ? Sacc[nt][0] * tsc : -INFINITY;
                    Sacc[nt][1] = (c0 + 1 <= r0g) ? Sacc[nt][1] * tsc : -INFINITY;
                    Sacc[nt][2] = (c0     <= r1g) ? Sacc[nt][2] * tsc : -INFINITY;
                    Sacc[nt][3] = (c0 + 1 <= r1g) ? Sacc[nt][3] * tsc : -INFINITY;
                }
            }

            // ---- row max over 64 keys ----
            float mx0 = Sacc[0][0], mx1 = Sacc[0][2];
            #pragma unroll
            for (int nt = 0; nt < 8; nt++) {
                mx0 = fmaxf(mx0, fmaxf(Sacc[nt][0], Sacc[nt][1]));
                mx1 = fmaxf(mx1, fmaxf(Sacc[nt][2], Sacc[nt][3]));
            }
            mx0 = fmaxf(mx0, __shfl_xor_sync(0xFFFFFFFFu, mx0, 1));
            mx0 = fmaxf(mx0, __shfl_xor_sync(0xFFFFFFFFu, mx0, 2));
            mx1 = fmaxf(mx1, __shfl_xor_sync(0xFFFFFFFFu, mx1, 1));
            mx1 = fmaxf(mx1, __shfl_xor_sync(0xFFFFFFFFu, mx1, 2));

            float mn0 = fmaxf(m0, mx0);
            float mn1 = fmaxf(m1, mx1);
            float al0 = exp2f(m0 - mn0);
            float al1 = exp2f(m1 - mn1);
            m0 = mn0; m1 = mn1;

            // ---- p = exp2(S - m); fp16 pack IS the PV A-fragment layout ----
            uint32_t P01[8], P23[8];
            float ps0 = 0.f, ps1 = 0.f;
            #pragma unroll
            for (int nt = 0; nt < 8; nt++) {
                __half2 h01 = __floats2half2_rn(exp2f(Sacc[nt][0] - m0),
                                                exp2f(Sacc[nt][1] - m0));
                __half2 h23 = __floats2half2_rn(exp2f(Sacc[nt][2] - m1),
                                                exp2f(Sacc[nt][3] - m1));
                float2 f01 = __half22float2(h01);
                float2 f23 = __half22float2(h23);
                ps0 += f01.x + f01.y;
                ps1 += f23.x + f23.y;
                P01[nt] = *(const uint32_t*)&h01;
                P23[nt] = *(const uint32_t*)&h23;
            }
            ps0 += __shfl_xor_sync(0xFFFFFFFFu, ps0, 1);
            ps0 += __shfl_xor_sync(0xFFFFFFFFu, ps0, 2);
            ps1 += __shfl_xor_sync(0xFFFFFFFFu, ps1, 1);
            ps1 += __shfl_xor_sync(0xFFFFFFFFu, ps1, 2);
            l0 = l0 * al0 + ps0;
            l1 = l1 * al1 + ps1;

            // ---- rescale O only when the max actually moved ----
            if (!__all_sync(0xFFFFFFFFu, (al0 == 1.f) & (al1 == 1.f))) {
                #pragma unroll
                for (int nt = 0; nt < 8; nt++) {
                    Oacc[nt][0] *= al0; Oacc[nt][1] *= al0;
                    Oacc[nt][2] *= al1; Oacc[nt][3] *= al1;
                }
            }

            // ---- O += P V over 64 keys (4 k-steps, 8 d-tiles) ----
            #pragma unroll
            for (int kst = 0; kst < 4; kst++) {
                uint32_t vf[4][4];
                #pragma unroll
                for (int p = 0; p < 4; p++)
                    LDSM4(vf[p][0], vf[p][1], vf[p][2], vf[p][3],
                          vbase + kvoff[p] + 32 * kst);
                uint32_t a0 = P01[2 * kst];
                uint32_t a1 = P23[2 * kst];
                uint32_t a2 = P01[2 * kst + 1];
                uint32_t a3 = P23[2 * kst + 1];
                #pragma unroll
                for (int nt = 0; nt < 8; nt++)
                    mma_f16(Oacc[nt], a0, a1, a2, a3,
                            vf[nt >> 1][(nt & 1) * 2],
                            vf[nt >> 1][(nt & 1) * 2 + 1]);
            }
        }
        __syncthreads();
    }

    // ---- epilogue: normalize, write fp16 [b, s, h*64+d] ----
    const int b = bh >> 4, h = bh & 15;
    const float inv0 = 1.f / l0;
    const float inv1 = 1.f / l1;
    __half* O0 = O + ((size_t)(b * SS + r0g)) * DM + h * HD;
    __half* O1 = O + ((size_t)(b * SS + r1g)) * DM + h * HD;
    #pragma unroll
    for (int nt = 0; nt < 8; nt++) {
        int d = nt * 8 + 2 * fk;
        *(__half2*)(O0 + d) = __floats2half2_rn(Oacc[nt][0] * inv0,
                                                Oacc[nt][1] * inv0);
        *(__half2*)(O1 + d) = __floats2half2_rn(Oacc[nt][2] * inv1,
                                                Oacc[nt][3] * inv1);
    }
}

// ---------------------------------------------------------------------------
extern "C" void kernel_launch(void* const* d_in, const int* in_sizes, int n_in,
                              void* d_out, int out_size)
{
    const float* x  = (const float*)d_in[0];
    const float* Wq = (const float*)d_in[1];
    const float* bq = (const float*)d_in[2];
    const float* Wk = (const float*)d_in[3];
    const float* bk = (const float*)d_in[4];
    const float* Wv = (const float*)d_in[5];
    const float* bv = (const float*)d_in[6];
    const float* Wo = (const float*)d_in[7];
    const float* bo = (const float*)d_in[8];

    __half *xh, *wt, *qp, *kp, *vp, *ap;
    cudaGetSymbolAddress((void**)&xh, g_xh);
    cudaGetSymbolAddress((void**)&wt, g_Wt);
    cudaGetSymbolAddress((void**)&qp, g_Qh);
    cudaGetSymbolAddress((void**)&kp, g_Kh);
    cudaGetSymbolAddress((void**)&vp, g_Vt);
    cudaGetSymbolAddress((void**)&ap, g_att);

    cudaFuncSetAttribute(gemm_qkv,
        cudaFuncAttributeMaxDynamicSharedMemorySize, GEMM_SMEM);
    cudaFuncSetAttribute(gemm_o,
        cudaFuncAttributeMaxDynamicSharedMemorySize, GEMM_SMEM);
    cudaFuncSetAttribute(attn_h,
        cudaFuncAttributeMaxDynamicSharedMemorySize, ATTN_SMEM);

    // prep: fp16 conversions (+ weight transpose)
    cvt_x_h<<<MROWS * DM / 1024, 256>>>(x, xh);
    cvt_w_t<<<dim3(DM / 32, DM / 32, 4), 256>>>(Wq, Wk, Wv, Wo, wt);

    dim3 gqkv(DM / 128, MROWS / 128, 3);   // (8, 32, 3)
    gemm_qkv<<<gqkv, 256, GEMM_SMEM>>>(xh, wt, bq, bk, bv, qp, kp, vp);

    attn_h<<<dim3(SS / ABQ, BB * NH), 256, ATTN_SMEM>>>(qp, kp, vp, ap);

    dim3 go(DM / 128, MROWS / 128);        // (8, 32)
    gemm_o<<<go, 256, GEMM_SMEM>>>(ap, wt + (size_t)3*DM*DM, bo, (float*)d_out);
}

// round 13
// speedup vs baseline: 9.5228x; 1.0422x over previous
#include <cuda_runtime.h>
#include <cuda_fp16.h>
#include <math.h>
#include <stdint.h>

// Problem constants
#define BB 2
#define SS 2048
#define DM 1024
#define NH 16
#define HD 64
#define MROWS (BB*SS)        // 4096

// Scratch (device globals; no allocations allowed)
__device__ __half g_xh[MROWS*DM];      // fp16 x            [m][k]
__device__ __half g_Wt[4*DM*DM];       // fp16 W^T          [n][k] x4
__device__ __half g_Qh[BB*NH*SS*HD];   // [b,h,s,d] fp16
__device__ __half g_Kh[BB*NH*SS*HD];   // [b,h,s,d] fp16
__device__ __half g_Vt[BB*NH*HD*SS];   // [b,h,d,s] fp16 (transposed)
__device__ __half g_att[BB*SS*DM];     // [b,s, h*64+d] fp16

// ---------------------------------------------------------------------------
// helpers
// ---------------------------------------------------------------------------
__device__ __forceinline__ void mma_f16(float c[4],
    uint32_t a0, uint32_t a1, uint32_t a2, uint32_t a3,
    uint32_t b0, uint32_t b1)
{
    asm volatile(
        "mma.sync.aligned.m16n8k16.row.col.f32.f16.f16.f32 "
        "{%0,%1,%2,%3}, {%4,%5,%6,%7}, {%8,%9}, {%0,%1,%2,%3};"
        : "+f"(c[0]), "+f"(c[1]), "+f"(c[2]), "+f"(c[3])
        : "r"(a0), "r"(a1), "r"(a2), "r"(a3), "r"(b0), "r"(b1));
}

__device__ __forceinline__ uint32_t smem_u32(const void* p) {
    uint32_t a;
    asm("{ .reg .u64 t; cvta.to.shared.u64 t, %1; cvt.u32.u64 %0, t; }"
        : "=r"(a) : "l"(p));
    return a;
}

__device__ __forceinline__ uint32_t ex2_f16x2(uint32_t x) {
    uint32_t y;
    asm("ex2.approx.f16x2 %0, %1;" : "=r"(y) : "r"(x));
    return y;
}

#define LDSM4(r0, r1, r2, r3, addr) \
    asm volatile("ldmatrix.sync.aligned.m8n8.x4.shared.b16 {%0,%1,%2,%3}, [%4];" \
                 : "=r"(r0), "=r"(r1), "=r"(r2), "=r"(r3) : "r"(addr))

#define CP16(dst, src) \
    asm volatile("cp.async.cg.shared.global [%0], [%1], 16;\n" \
                 :: "r"(dst), "l"(src))
#define CP_COMMIT() asm volatile("cp.async.commit_group;\n")
#define CP_WAIT0()  asm volatile("cp.async.wait_group 0;\n")
#define CP_WAIT1()  asm volatile("cp.async.wait_group 1;\n")

// ---------------------------------------------------------------------------
// prep: x -> fp16 (same layout); W -> fp16 transposed [n][k]
// ---------------------------------------------------------------------------
__global__ __launch_bounds__(256) void cvt_x_h(const float* __restrict__ s,
                                               __half* __restrict__ d)
{
    int i = (blockIdx.x * 256 + threadIdx.x) * 4;
    float4 v = *(const float4*)(s + i);
    *(__half2*)(d + i)     = __floats2half2_rn(v.x, v.y);
    *(__half2*)(d + i + 2) = __floats2half2_rn(v.z, v.w);
}

__global__ __launch_bounds__(256) void cvt_w_t(
    const float* __restrict__ w0, const float* __restrict__ w1,
    const float* __restrict__ w2, const float* __restrict__ w3,
    __half* __restrict__ d)
{
    __shared__ float t[32][33];
    const int z = blockIdx.z;
    const float* s = (z == 0) ? w0 : (z == 1) ? w1 : (z == 2) ? w2 : w3;
    const int k0 = blockIdx.y * 32;
    const int n0 = blockIdx.x * 32;
    const int tx = threadIdx.x & 31;
    const int ty = threadIdx.x >> 5;     // 0..7
    #pragma unroll
    for (int i = 0; i < 4; i++)
        t[ty + 8 * i][tx] = s[(size_t)(k0 + ty + 8 * i) * DM + n0 + tx];
    __syncthreads();
    __half* dz = d + (size_t)z * DM * DM;
    #pragma unroll
    for (int i = 0; i < 4; i++)
        dz[(size_t)(n0 + ty + 8 * i) * DM + k0 + tx] =
            __float2half_rn(t[tx][ty + 8 * i]);
}

// ---------------------------------------------------------------------------
// 3-stage cp.async fp16 GEMM body, ldmatrix fragments.  (unchanged R12)
// A fp16 [m][k]; Wt fp16 [n][k]. 128x128 tile, BK=64, m16n8k16, fp32 accum.
// OUTMODE: 0 = fp32 row-major; 1 = fp16 [b,h,s,d]; 2 = fp16 [b,h,d,s].
// ---------------------------------------------------------------------------
#define GSTAGES 3
#define GBK 64
#define HST 72                   // halves per smem row (64 + 8 pad)
#define STAGE_H (128*HST)        // halves per A or B stage (9216)
#define GEMM_SMEM (GSTAGES*2*STAGE_H*2)   // 110592 B
#define GNT (DM/GBK)             // 16 k-tiles

template<int OUTMODE>
__device__ __forceinline__ void gemm_body(
    const __half* __restrict__ A, const __half* __restrict__ Wt,
    const float* __restrict__ bias, void* __restrict__ Cv)
{
    extern __shared__ __half smh[];
    // layout: A0 | A1 | A2 | B0 | B1 | B2

    const int tid  = threadIdx.x;
    const int warp = tid >> 5;
    const int lane = tid & 31;
    const int wm   = (warp >> 2) * 64;
    const int wn   = (warp & 3) * 32;
    const int row0 = blockIdx.y * 128;
    const int col0 = blockIdx.x * 128;
    const int fr   = lane >> 2;
    const int fk   = lane & 3;
    const int g    = lane >> 3;      // ldmatrix address group 0..3
    const int rr   = lane & 7;

    const uint32_t sbase = smem_u32(smh);

    uint32_t aoff[4], boff[2];
    #pragma unroll
    for (int mi = 0; mi < 4; mi++)
        aoff[mi] = (uint32_t)((wm + mi * 16 + ((g & 1) << 3) + rr) * HST
                              + ((g >> 1) << 3)) * 2;
    #pragma unroll
    for (int p = 0; p < 2; p++)
        boff[p] = (uint32_t)((wn + p * 16 + ((g >> 1) << 3) + rr) * HST
                             + ((g & 1) << 3)) * 2;

    float acc[4][4][4];
    #pragma unroll
    for (int i = 0; i < 4; i++)
        #pragma unroll
        for (int j = 0; j < 4; j++)
            #pragma unroll
            for (int r = 0; r < 4; r++) acc[i][j][r] = 0.f;

    #define G_ISSUE(kt, s) do {                                              \
        uint32_t abase = sbase + (uint32_t)(s) * (STAGE_H * 2);              \
        uint32_t bbase = sbase + (uint32_t)((GSTAGES + (s)) * STAGE_H) * 2;  \
        _Pragma("unroll")                                                    \
        for (int i = 0; i < 4; i++) {                                        \
            int chunk = tid + 256 * i;                                       \
            int row  = chunk >> 3;                                           \
            int coff = (chunk & 7) * 8;                                      \
            CP16(abase + (uint32_t)(row * HST + coff) * 2,                   \
                 A  + (size_t)(row0 + row) * DM + (kt) * GBK + coff);        \
            CP16(bbase + (uint32_t)(row * HST + coff) * 2,                   \
                 Wt + (size_t)(col0 + row) * DM + (kt) * GBK + coff);        \
        }                                                                    \
        CP_COMMIT();                                                         \
    } while (0)

    G_ISSUE(0, 0);
    G_ISSUE(1, 1);

    for (int kt = 0; kt < GNT; kt++) {
        const int cur = kt % GSTAGES;
        CP_WAIT1();
        __syncthreads();
        if (kt + 2 < GNT) {
            G_ISSUE(kt + 2, (kt + 2) % GSTAGES);
        } else {
            CP_COMMIT();
        }

        const uint32_t abase = sbase + (uint32_t)cur * (STAGE_H * 2);
        const uint32_t bbase = sbase + (uint32_t)((GSTAGES + cur) * STAGE_H) * 2;

        #pragma unroll
        for (int ks = 0; ks < 4; ks++) {     // 4 k-steps of 16
            uint32_t af[4][4];
            uint32_t bf[2][4];
            #pragma unroll
            for (int mi = 0; mi < 4; mi++)
                LDSM4(af[mi][0], af[mi][1], af[mi][2], af[mi][3],
                      abase + aoff[mi] + 32 * ks);
            #pragma unroll
            for (int p = 0; p < 2; p++)
                LDSM4(bf[p][0], bf[p][1], bf[p][2], bf[p][3],
                      bbase + boff[p] + 32 * ks);
            #pragma unroll
            for (int mi = 0; mi < 4; mi++)
                #pragma unroll
                for (int ni = 0; ni < 4; ni++)
                    mma_f16(acc[mi][ni],
                            af[mi][0], af[mi][1], af[mi][2], af[mi][3],
                            bf[ni >> 1][(ni & 1) * 2],
                            bf[ni >> 1][(ni & 1) * 2 + 1]);
        }
    }

    // ---- epilogue ----
    #pragma unroll
    for (int mi = 0; mi < 4; mi++) {
        int r = row0 + wm + mi * 16 + fr;
        #pragma unroll
        for (int ni = 0; ni < 4; ni++) {
            int c = col0 + wn + ni * 8 + 2 * fk;
            float bb0 = bias[c], bb1 = bias[c + 1];
            float v0 = acc[mi][ni][0] + bb0, v1 = acc[mi][ni][1] + bb1;
            float v2 = acc[mi][ni][2] + bb0, v3 = acc[mi][ni][3] + bb1;
            if (OUTMODE == 0) {
                float* C = (float*)Cv;
                *(float2*)&C[(size_t)r * DM + c]       = make_float2(v0, v1);
                *(float2*)&C[(size_t)(r + 8) * DM + c] = make_float2(v2, v3);
            } else if (OUTMODE == 1) {
                __half* C = (__half*)Cv;
                int h = c >> 6, d = c & 63;
                int b0i = r >> 11, s0 = r & 2047;
                size_t i0 = ((((size_t)b0i * NH + h) * SS + s0) * HD) + d;
                *(__half2*)&C[i0] = __floats2half2_rn(v0, v1);
                int r2 = r + 8;
                int b1i = r2 >> 11, s1 = r2 & 2047;
                size_t i1 = ((((size_t)b1i * NH + h) * SS + s1) * HD) + d;
                *(__half2*)&C[i1] = __floats2half2_rn(v2, v3);
            } else {
                __half* C = (__half*)Cv;       // [b,h,d,s]
                int h = c >> 6, d = c & 63;
                int b0i = r >> 11, s0 = r & 2047;
                int r2 = r + 8;
                int b1i = r2 >> 11, s1 = r2 & 2047;
                size_t base0 = (((size_t)b0i * NH + h) * HD);
                size_t base1 = (((size_t)b1i * NH + h) * HD);
                C[(base0 + d    ) * SS + s0] = __float2half_rn(v0);
                C[(base0 + d + 1) * SS + s0] = __float2half_rn(v1);
                C[(base1 + d    ) * SS + s1] = __float2half_rn(v2);
                C[(base1 + d + 1) * SS + s1] = __float2half_rn(v3);
            }
        }
    }
    #undef G_ISSUE
}

__global__ __launch_bounds__(256, 2) void gemm_qkv(
    const __half* __restrict__ A, const __half* __restrict__ Wt,
    const float* __restrict__ b0, const float* __restrict__ b1,
    const float* __restrict__ b2,
    __half* __restrict__ C0, __half* __restrict__ C1, __half* __restrict__ C2)
{
    const int z = blockIdx.z;
    const __half* W = Wt + (size_t)z * DM * DM;
    if (z == 2) {
        gemm_body<2>(A, W, b2, C2);
    } else {
        gemm_body<1>(A, W, z ? b1 : b0, z ? C1 : C0);
    }
}

__global__ __launch_bounds__(256, 2) void gemm_o(
    const __half* __restrict__ A, const __half* __restrict__ Wt,
    const float* __restrict__ bias, float* __restrict__ C)
{
    gemm_body<0>(A, Wt, bias, C);
}

// ---------------------------------------------------------------------------
// fp16 flash attention (causal), m16n8k16, fp32 accum. R13:
//  - exp argument via fmaf(S, tsc, -m): no separate scale pass
//  - ex2.approx.f16x2: one exp per fp16 pair, output IS the P fragment
//  - row max on raw S (masked lanes -> -INF), scaled once per row
// ---------------------------------------------------------------------------
#define ABQ 128
#define LKEYS 64
#define HSTR 72
#define KSTAGE_H (LKEYS*HSTR)
#define ATTN_SMEM (4*KSTAGE_H*2)      // 36864 B

__global__ __launch_bounds__(256, 2) void attn_h(
    const __half* __restrict__ Q, const __half* __restrict__ K,
    const __half* __restrict__ Vt, __half* __restrict__ O)
{
    extern __shared__ __half smh[];
    // layout: K stage0 | K stage1 | V stage0 | V stage1

    const int bh   = blockIdx.y;
    const int qb   = gridDim.x - 1 - blockIdx.x;  // heavy blocks first
    const int q0   = qb * ABQ;
    const int tid  = threadIdx.x;
    const int warp = tid >> 5;
    const int lane = tid & 31;
    const int fr   = lane >> 2;
    const int fk   = lane & 3;
    const int g    = lane >> 3;
    const int rr   = lane & 7;
    const int wrow = warp * 16;

    const __half* Qb  = Q  + (size_t)bh * SS * HD;
    const __half* Kb  = K  + (size_t)bh * SS * HD;
    const __half* Vtb = Vt + (size_t)bh * HD * SS;

    uint32_t Qf[4][4];
    {
        const __half* qr0 = Qb + (size_t)(q0 + wrow + fr) * HD;
        const __half* qr1 = qr0 + 8 * HD;
        #pragma unroll
        for (int ks = 0; ks < 4; ks++) {
            Qf[ks][0] = *(const uint32_t*)(qr0 + 16 * ks + 2 * fk);
            Qf[ks][1] = *(const uint32_t*)(qr1 + 16 * ks + 2 * fk);
            Qf[ks][2] = *(const uint32_t*)(qr0 + 16 * ks + 8 + 2 * fk);
            Qf[ks][3] = *(const uint32_t*)(qr1 + 16 * ks + 8 + 2 * fk);
        }
    }

    float Oacc[8][4];
    #pragma unroll
    for (int nt = 0; nt < 8; nt++)
        #pragma unroll
        for (int r = 0; r < 4; r++) Oacc[nt][r] = 0.f;

    float m0 = -INFINITY, m1 = -INFINITY, l0 = 0.f, l1 = 0.f;
    const float tsc = 0.18033688f;     // (1/sqrt(64)) * log2(e)

    const int r0g = q0 + wrow + fr;
    const int r1g = r0g + 8;

    const int nload = (q0 + ABQ) / LKEYS;

    // ldmatrix lane offsets (bytes): K/V rows as n8k16 B-operand pairs
    uint32_t kvoff[4];
    #pragma unroll
    for (int p = 0; p < 4; p++)
        kvoff[p] = (uint32_t)((p * 16 + ((g >> 1) << 3) + rr) * HSTR
                              + ((g & 1) << 3)) * 2;

    const int crow = tid >> 3;           // 0..31
    const int coff = (tid & 7) * 8;      // halves
    const uint32_t sbase = smem_u32(smh);

    #define A_ISSUE(lt, s) do {                                              \
        const int kk0 = (lt) * LKEYS;                                        \
        uint32_t koff = sbase + (uint32_t)(s) * (KSTAGE_H * 2);              \
        uint32_t voff = sbase + (uint32_t)((2 + (s)) * KSTAGE_H) * 2;        \
        _Pragma("unroll")                                                    \
        for (int i = 0; i < 2; i++) {                                        \
            int row = crow + 32 * i;                                         \
            CP16(koff + (uint32_t)(row * HSTR + coff) * 2,                   \
                 Kb + (size_t)(kk0 + row) * HD + coff);                      \
            CP16(voff + (uint32_t)(row * HSTR + coff) * 2,                   \
                 Vtb + (size_t)row * SS + kk0 + coff);                       \
        }                                                                    \
        CP_COMMIT();                                                         \
    } while (0)

    A_ISSUE(0, 0);

    for (int lt = 0; lt < nload; lt++) {
        const int k0  = lt * LKEYS;
        const int buf = lt & 1;
        CP_WAIT0();
        __syncthreads();
        if (lt + 1 < nload) A_ISSUE(lt + 1, buf ^ 1);

        const bool active = (k0 <= q0 + wrow + 15);   // warp-uniform
        if (active) {
            const uint32_t kbase = sbase + (uint32_t)buf * (KSTAGE_H * 2);
            const uint32_t vbase = sbase + (uint32_t)((2 + buf) * KSTAGE_H) * 2;

            // ---- S = Q K^T over 64 keys (8 n-tiles) ----
            float Sacc[8][4];
            #pragma unroll
            for (int nt = 0; nt < 8; nt++)
                #pragma unroll
                for (int r = 0; r < 4; r++) Sacc[nt][r] = 0.f;

            #pragma unroll
            for (int ks = 0; ks < 4; ks++) {
                uint32_t kf[4][4];
                #pragma unroll
                for (int p = 0; p < 4; p++)
                    LDSM4(kf[p][0], kf[p][1], kf[p][2], kf[p][3],
                          kbase + kvoff[p] + 32 * ks);
                #pragma unroll
                for (int nt = 0; nt < 8; nt++)
                    mma_f16(Sacc[nt],
                            Qf[ks][0], Qf[ks][1], Qf[ks][2], Qf[ks][3],
                            kf[nt >> 1][(nt & 1) * 2],
                            kf[nt >> 1][(nt & 1) * 2 + 1]);
            }

            // ---- causal mask on raw S (only near diagonal) ----
            const bool full = (k0 + 63 <= q0 + wrow);  // warp-uniform
            if (!full) {
                #pragma unroll
                for (int nt = 0; nt < 8; nt++) {
                    int c0 = k0 + nt * 8 + 2 * fk;
                    if (c0     > r0g) Sacc[nt][0] = -INFINITY;
                    if (c0 + 1 > r0g) Sacc[nt][1] = -INFINITY;
                    if (c0     > r1g) Sacc[nt][2] = -INFINITY;
                    if (c0 + 1 > r1g) Sacc[nt][3] = -INFINITY;
                }
            }

            // ---- row max over raw S ----
            float mx0 = Sacc[0][0], mx1 = Sacc[0][2];
            #pragma unroll
            for (int nt = 0; nt < 8; nt++) {
                mx0 = fmaxf(mx0, fmaxf(Sacc[nt][0], Sacc[nt][1]));
                mx1 = fmaxf(mx1, fmaxf(Sacc[nt][2], Sacc[nt][3]));
            }
            mx0 = fmaxf(mx0, __shfl_xor_sync(0xFFFFFFFFu, mx0, 1));
            mx0 = fmaxf(mx0, __shfl_xor_sync(0xFFFFFFFFu, mx0, 2));
            mx1 = fmaxf(mx1, __shfl_xor_sync(0xFFFFFFFFu, mx1, 1));
            mx1 = fmaxf(mx1, __shfl_xor_sync(0xFFFFFFFFu, mx1, 2));

            float mn0 = fmaxf(m0, mx0 * tsc);
            float mn1 = fmaxf(m1, mx1 * tsc);
            float al0 = exp2f(m0 - mn0);
            float al1 = exp2f(m1 - mn1);
            m0 = mn0; m1 = mn1;

            // ---- p = ex2.f16x2(fma(S, tsc, -m)); output IS the fragment ----
            uint32_t P01[8], P23[8];
            float ps0 = 0.f, ps1 = 0.f;
            #pragma unroll
            for (int nt = 0; nt < 8; nt++) {
                float f0 = fmaf(Sacc[nt][0], tsc, -m0);
                float f1 = fmaf(Sacc[nt][1], tsc, -m0);
                float f2 = fmaf(Sacc[nt][2], tsc, -m1);
                float f3 = fmaf(Sacc[nt][3], tsc, -m1);
                __half2 e01 = __floats2half2_rn(f0, f1);
                __half2 e23 = __floats2half2_rn(f2, f3);
                uint32_t p01 = ex2_f16x2(*(const uint32_t*)&e01);
                uint32_t p23 = ex2_f16x2(*(const uint32_t*)&e23);
                P01[nt] = p01;
                P23[nt] = p23;
                float2 q01 = __half22float2(*(const __half2*)&p01);
                float2 q23 = __half22float2(*(const __half2*)&p23);
                ps0 += q01.x + q01.y;
                ps1 += q23.x + q23.y;
            }
            ps0 += __shfl_xor_sync(0xFFFFFFFFu, ps0, 1);
            ps0 += __shfl_xor_sync(0xFFFFFFFFu, ps0, 2);
            ps1 += __shfl_xor_sync(0xFFFFFFFFu, ps1, 1);
            ps1 += __shfl_xor_sync(0xFFFFFFFFu, ps1, 2);
            l0 = l0 * al0 + ps0;
            l1 = l1 * al1 + ps1;

            // ---- rescale O only when the max actually moved ----
            if (!__all_sync(0xFFFFFFFFu, (al0 == 1.f) & (al1 == 1.f))) {
                #pragma unroll
                for (int nt = 0; nt < 8; nt++) {
                    Oacc[nt][0] *= al0; Oacc[nt][1] *= al0;
                    Oacc[nt][2] *= al1; Oacc[nt][3] *= al1;
                }
            }

            // ---- O += P V over 64 keys (4 k-steps, 8 d-tiles) ----
            #pragma unroll
            for (int kst = 0; kst < 4; kst++) {
                uint32_t vf[4][4];
                #pragma unroll
                for (int p = 0; p < 4; p++)
                    LDSM4(vf[p][0], vf[p][1], vf[p][2], vf[p][3],
                          vbase + kvoff[p] + 32 * kst);
                uint32_t a0 = P01[2 * kst];
                uint32_t a1 = P23[2 * kst];
                uint32_t a2 = P01[2 * kst + 1];
                uint32_t a3 = P23[2 * kst + 1];
                #pragma unroll
                for (int nt = 0; nt < 8; nt++)
                    mma_f16(Oacc[nt], a0, a1, a2, a3,
                            vf[nt >> 1][(nt & 1) * 2],
                            vf[nt >> 1][(nt & 1) * 2 + 1]);
            }
        }
        __syncthreads();
    }

    // ---- epilogue: normalize, write fp16 [b, s, h*64+d] ----
    const int b = bh >> 4, h = bh & 15;
    const float inv0 = 1.f / l0;
    const float inv1 = 1.f / l1;
    __half* O0 = O + ((size_t)(b * SS + r0g)) * DM + h * HD;
    __half* O1 = O + ((size_t)(b * SS + r1g)) * DM + h * HD;
    #pragma unroll
    for (int nt = 0; nt < 8; nt++) {
        int d = nt * 8 + 2 * fk;
        *(__half2*)(O0 + d) = __floats2half2_rn(Oacc[nt][0] * inv0,
                                                Oacc[nt][1] * inv0);
        *(__half2*)(O1 + d) = __floats2half2_rn(Oacc[nt][2] * inv1,
                                                Oacc[nt][3] * inv1);
    }
}

// ---------------------------------------------------------------------------
extern "C" void kernel_launch(void* const* d_in, const int* in_sizes, int n_in,
                              void* d_out, int out_size)
{
    const float* x  = (const float*)d_in[0];
    const float* Wq = (const float*)d_in[1];
    const float* bq = (const float*)d_in[2];
    const float* Wk = (const float*)d_in[3];
    const float* bk = (const float*)d_in[4];
    const float* Wv = (const float*)d_in[5];
    const float* bv = (const float*)d_in[6];
    const float* Wo = (const float*)d_in[7];
    const float* bo = (const float*)d_in[8];

    __half *xh, *wt, *qp, *kp, *vp, *ap;
    cudaGetSymbolAddress((void**)&xh, g_xh);
    cudaGetSymbolAddress((void**)&wt, g_Wt);
    cudaGetSymbolAddress((void**)&qp, g_Qh);
    cudaGetSymbolAddress((void**)&kp, g_Kh);
    cudaGetSymbolAddress((void**)&vp, g_Vt);
    cudaGetSymbolAddress((void**)&ap, g_att);

    cudaFuncSetAttribute(gemm_qkv,
        cudaFuncAttributeMaxDynamicSharedMemorySize, GEMM_SMEM);
    cudaFuncSetAttribute(gemm_o,
        cudaFuncAttributeMaxDynamicSharedMemorySize, GEMM_SMEM);
    cudaFuncSetAttribute(attn_h,
        cudaFuncAttributeMaxDynamicSharedMemorySize, ATTN_SMEM);

    // prep: fp16 conversions (+ weight transpose)
    cvt_x_h<<<MROWS * DM / 1024, 256>>>(x, xh);
    cvt_w_t<<<dim3(DM / 32, DM / 32, 4), 256>>>(Wq, Wk, Wv, Wo, wt);

    dim3 gqkv(DM / 128, MROWS / 128, 3);   // (8, 32, 3)
    gemm_qkv<<<gqkv, 256, GEMM_SMEM>>>(xh, wt, bq, bk, bv, qp, kp, vp);

    attn_h<<<dim3(SS / ABQ, BB * NH), 256, ATTN_SMEM>>>(qp, kp, vp, ap);

    dim3 go(DM / 128, MROWS / 128);        // (8, 32)
    gemm_o<<<go, 256, GEMM_SMEM>>>(ap, wt + (size_t)3*DM*DM, bo, (float*)d_out);
}

// round 15
// speedup vs baseline: 10.4047x; 1.0926x over previous
#include <cuda_runtime.h>
#include <cuda_fp16.h>
#include <math.h>
#include <stdint.h>

// Problem constants
#define BB 2
#define SS 2048
#define DM 1024
#define NH 16
#define HD 64
#define MROWS (BB*SS)        // 4096

// Scratch (device globals; no allocations allowed)
__device__ __half g_xh[MROWS*DM];      // fp16 x            [m][k]
__device__ __half g_Wt[4*DM*DM];       // fp16 W^T          [n][k] x4
__device__ __half g_Qh[BB*NH*SS*HD];   // [b,h,s,d] fp16
__device__ __half g_Kh[BB*NH*SS*HD];   // [b,h,s,d] fp16
__device__ __half g_Vt[BB*NH*HD*SS];   // [b,h,d,s] fp16 (transposed)
__device__ __half g_att[BB*SS*DM];     // [b,s, h*64+d] fp16

// ---------------------------------------------------------------------------
// helpers
// ---------------------------------------------------------------------------
__device__ __forceinline__ void mma_f16(float c[4],
    uint32_t a0, uint32_t a1, uint32_t a2, uint32_t a3,
    uint32_t b0, uint32_t b1)
{
    asm volatile(
        "mma.sync.aligned.m16n8k16.row.col.f32.f16.f16.f32 "
        "{%0,%1,%2,%3}, {%4,%5,%6,%7}, {%8,%9}, {%0,%1,%2,%3};"
        : "+f"(c[0]), "+f"(c[1]), "+f"(c[2]), "+f"(c[3])
        : "r"(a0), "r"(a1), "r"(a2), "r"(a3), "r"(b0), "r"(b1));
}

__device__ __forceinline__ uint32_t smem_u32(const void* p) {
    uint32_t a;
    asm("{ .reg .u64 t; cvta.to.shared.u64 t, %1; cvt.u32.u64 %0, t; }"
        : "=r"(a) : "l"(p));
    return a;
}

__device__ __forceinline__ uint32_t ex2_f16x2(uint32_t x) {
    uint32_t y;
    asm("ex2.approx.f16x2 %0, %1;" : "=r"(y) : "r"(x));
    return y;
}

#define LDSM4(r0, r1, r2, r3, addr) \
    asm volatile("ldmatrix.sync.aligned.m8n8.x4.shared.b16 {%0,%1,%2,%3}, [%4];" \
                 : "=r"(r0), "=r"(r1), "=r"(r2), "=r"(r3) : "r"(addr))

#define CP16(dst, src) \
    asm volatile("cp.async.cg.shared.global [%0], [%1], 16;\n" \
                 :: "r"(dst), "l"(src))
#define CP_COMMIT() asm volatile("cp.async.commit_group;\n")
#define CP_WAIT0()  asm volatile("cp.async.wait_group 0;\n")
#define CP_WAIT1()  asm volatile("cp.async.wait_group 1;\n")

// ---------------------------------------------------------------------------
// prep: x -> fp16 (same layout); W -> fp16 transposed [n][k]
// ---------------------------------------------------------------------------
__global__ __launch_bounds__(256) void cvt_x_h(const float* __restrict__ s,
                                               __half* __restrict__ d)
{
    int i = (blockIdx.x * 256 + threadIdx.x) * 4;
    float4 v = *(const float4*)(s + i);
    *(__half2*)(d + i)     = __floats2half2_rn(v.x, v.y);
    *(__half2*)(d + i + 2) = __floats2half2_rn(v.z, v.w);
}

__global__ __launch_bounds__(256) void cvt_w_t(
    const float* __restrict__ w0, const float* __restrict__ w1,
    const float* __restrict__ w2, const float* __restrict__ w3,
    __half* __restrict__ d)
{
    __shared__ float t[32][33];
    const int z = blockIdx.z;
    const float* s = (z == 0) ? w0 : (z == 1) ? w1 : (z == 2) ? w2 : w3;
    const int k0 = blockIdx.y * 32;
    const int n0 = blockIdx.x * 32;
    const int tx = threadIdx.x & 31;
    const int ty = threadIdx.x >> 5;     // 0..7
    #pragma unroll
    for (int i = 0; i < 4; i++)
        t[ty + 8 * i][tx] = s[(size_t)(k0 + ty + 8 * i) * DM + n0 + tx];
    __syncthreads();
    __half* dz = d + (size_t)z * DM * DM;
    #pragma unroll
    for (int i = 0; i < 4; i++)
        dz[(size_t)(n0 + ty + 8 * i) * DM + k0 + tx] =
            __float2half_rn(t[tx][ty + 8 * i]);
}

// ---------------------------------------------------------------------------
// 3-stage cp.async fp16 GEMM body, ldmatrix fragments.  (R13, proven)
// A fp16 [m][k]; Wt fp16 [n][k]. 128x128 tile, BK=64, m16n8k16, fp32 accum.
// OUTMODE: 0 = fp32 row-major; 1 = fp16 [b,h,s,d]; 2 = fp16 [b,h,d,s].
// ---------------------------------------------------------------------------
#define GSTAGES 3
#define GBK 64
#define HST 72                   // halves per smem row (64 + 8 pad)
#define STAGE_H (128*HST)        // halves per A or B stage (9216)
#define GEMM_SMEM (GSTAGES*2*STAGE_H*2)   // 110592 B
#define GNT (DM/GBK)             // 16 k-tiles

template<int OUTMODE>
__device__ __forceinline__ void gemm_body(
    const __half* __restrict__ A, const __half* __restrict__ Wt,
    const float* __restrict__ bias, void* __restrict__ Cv)
{
    extern __shared__ __half smh[];
    // layout: A0 | A1 | A2 | B0 | B1 | B2

    const int tid  = threadIdx.x;
    const int warp = tid >> 5;
    const int lane = tid & 31;
    const int wm   = (warp >> 2) * 64;
    const int wn   = (warp & 3) * 32;
    const int row0 = blockIdx.y * 128;
    const int col0 = blockIdx.x * 128;
    const int fr   = lane >> 2;
    const int fk   = lane & 3;
    const int g    = lane >> 3;      // ldmatrix address group 0..3
    const int rr   = lane & 7;

    const uint32_t sbase = smem_u32(smh);

    uint32_t aoff[4], boff[2];
    #pragma unroll
    for (int mi = 0; mi < 4; mi++)
        aoff[mi] = (uint32_t)((wm + mi * 16 + ((g & 1) << 3) + rr) * HST
                              + ((g >> 1) << 3)) * 2;
    #pragma unroll
    for (int p = 0; p < 2; p++)
        boff[p] = (uint32_t)((wn + p * 16 + ((g >> 1) << 3) + rr) * HST
                             + ((g & 1) << 3)) * 2;

    float acc[4][4][4];
    #pragma unroll
    for (int i = 0; i < 4; i++)
        #pragma unroll
        for (int j = 0; j < 4; j++)
            #pragma unroll
            for (int r = 0; r < 4; r++) acc[i][j][r] = 0.f;

    #define G_ISSUE(kt, s) do {                                              \
        uint32_t abase = sbase + (uint32_t)(s) * (STAGE_H * 2);              \
        uint32_t bbase = sbase + (uint32_t)((GSTAGES + (s)) * STAGE_H) * 2;  \
        _Pragma("unroll")                                                    \
        for (int i = 0; i < 4; i++) {                                        \
            int chunk = tid + 256 * i;                                       \
            int row  = chunk >> 3;                                           \
            int coff = (chunk & 7) * 8;                                      \
            CP16(abase + (uint32_t)(row * HST + coff) * 2,                   \
                 A  + (size_t)(row0 + row) * DM + (kt) * GBK + coff);        \
            CP16(bbase + (uint32_t)(row * HST + coff) * 2,                   \
                 Wt + (size_t)(col0 + row) * DM + (kt) * GBK + coff);        \
        }                                                                    \
        CP_COMMIT();                                                         \
    } while (0)

    G_ISSUE(0, 0);
    G_ISSUE(1, 1);

    for (int kt = 0; kt < GNT; kt++) {
        const int cur = kt % GSTAGES;
        CP_WAIT1();
        __syncthreads();
        if (kt + 2 < GNT) {
            G_ISSUE(kt + 2, (kt + 2) % GSTAGES);
        } else {
            CP_COMMIT();
        }

        const uint32_t abase = sbase + (uint32_t)cur * (STAGE_H * 2);
        const uint32_t bbase = sbase + (uint32_t)((GSTAGES + cur) * STAGE_H) * 2;

        #pragma unroll
        for (int ks = 0; ks < 4; ks++) {     // 4 k-steps of 16
            uint32_t af[4][4];
            uint32_t bf[2][4];
            #pragma unroll
            for (int mi = 0; mi < 4; mi++)
                LDSM4(af[mi][0], af[mi][1], af[mi][2], af[mi][3],
                      abase + aoff[mi] + 32 * ks);
            #pragma unroll
            for (int p = 0; p < 2; p++)
                LDSM4(bf[p][0], bf[p][1], bf[p][2], bf[p][3],
                      bbase + boff[p] + 32 * ks);
            #pragma unroll
            for (int mi = 0; mi < 4; mi++)
                #pragma unroll
                for (int ni = 0; ni < 4; ni++)
                    mma_f16(acc[mi][ni],
                            af[mi][0], af[mi][1], af[mi][2], af[mi][3],
                            bf[ni >> 1][(ni & 1) * 2],
                            bf[ni >> 1][(ni & 1) * 2 + 1]);
        }
    }

    // ---- epilogue ----
    #pragma unroll
    for (int mi = 0; mi < 4; mi++) {
        int r = row0 + wm + mi * 16 + fr;
        #pragma unroll
        for (int ni = 0; ni < 4; ni++) {
            int c = col0 + wn + ni * 8 + 2 * fk;
            float bb0 = bias[c], bb1 = bias[c + 1];
            float v0 = acc[mi][ni][0] + bb0, v1 = acc[mi][ni][1] + bb1;
            float v2 = acc[mi][ni][2] + bb0, v3 = acc[mi][ni][3] + bb1;
            if (OUTMODE == 0) {
                float* C = (float*)Cv;
                *(float2*)&C[(size_t)r * DM + c]       = make_float2(v0, v1);
                *(float2*)&C[(size_t)(r + 8) * DM + c] = make_float2(v2, v3);
            } else if (OUTMODE == 1) {
                __half* C = (__half*)Cv;
                int h = c >> 6, d = c & 63;
                int b0i = r >> 11, s0 = r & 2047;
                size_t i0 = ((((size_t)b0i * NH + h) * SS + s0) * HD) + d;
                *(__half2*)&C[i0] = __floats2half2_rn(v0, v1);
                int r2 = r + 8;
                int b1i = r2 >> 11, s1 = r2 & 2047;
                size_t i1 = ((((size_t)b1i * NH + h) * SS + s1) * HD) + d;
                *(__half2*)&C[i1] = __floats2half2_rn(v2, v3);
            } else {
                __half* C = (__half*)Cv;       // [b,h,d,s]
                int h = c >> 6, d = c & 63;
                int b0i = r >> 11, s0 = r & 2047;
                int r2 = r + 8;
                int b1i = r2 >> 11, s1 = r2 & 2047;
                size_t base0 = (((size_t)b0i * NH + h) * HD);
                size_t base1 = (((size_t)b1i * NH + h) * HD);
                C[(base0 + d    ) * SS + s0] = __float2half_rn(v0);
                C[(base0 + d + 1) * SS + s0] = __float2half_rn(v1);
                C[(base1 + d    ) * SS + s1] = __float2half_rn(v2);
                C[(base1 + d + 1) * SS + s1] = __float2half_rn(v3);
            }
        }
    }
    #undef G_ISSUE
}

__global__ __launch_bounds__(256, 2) void gemm_qkv(
    const __half* __restrict__ A, const __half* __restrict__ Wt,
    const float* __restrict__ b0, const float* __restrict__ b1,
    const float* __restrict__ b2,
    __half* __restrict__ C0, __half* __restrict__ C1, __half* __restrict__ C2)
{
    const int z = blockIdx.z;
    const __half* W = Wt + (size_t)z * DM * DM;
    if (z == 2) {
        gemm_body<2>(A, W, b2, C2);
    } else {
        gemm_body<1>(A, W, z ? b1 : b0, z ? C1 : C0);
    }
}

__global__ __launch_bounds__(256, 2) void gemm_o(
    const __half* __restrict__ A, const __half* __restrict__ Wt,
    const float* __restrict__ bias, float* __restrict__ C)
{
    gemm_body<0>(A, Wt, bias, C);
}

// ---------------------------------------------------------------------------
// fp16 flash attention (causal), m16n8k16, fp32 accum. R15:
//  - PAIRED q-tiles: block processes tiles (qb, NT-1-qb) -> constant work
//    (17 stages) per block; grid 256 = one balanced wave at 2 blocks/SM
//  - body otherwise identical to R13 (ldmatrix, ex2.f16x2 softmax)
// ---------------------------------------------------------------------------
#define ABQ 128
#define LKEYS 64
#define HSTR 72
#define KSTAGE_H (LKEYS*HSTR)
#define ATTN_SMEM (4*KSTAGE_H*2)      // 36864 B
#define NQT (SS/ABQ)                  // 16 q-tiles per (b,h)

__global__ __launch_bounds__(256, 2) void attn_h(
    const __half* __restrict__ Q, const __half* __restrict__ K,
    const __half* __restrict__ Vt, __half* __restrict__ O)
{
    extern __shared__ __half smh[];
    // layout: K stage0 | K stage1 | V stage0 | V stage1

    const int bh   = blockIdx.y;
    const int tid  = threadIdx.x;
    const int warp = tid >> 5;
    const int lane = tid & 31;
    const int fr   = lane >> 2;
    const int fk   = lane & 3;
    const int g    = lane >> 3;
    const int rr   = lane & 7;
    const int wrow = warp * 16;

    const __half* Qb  = Q  + (size_t)bh * SS * HD;
    const __half* Kb  = K  + (size_t)bh * SS * HD;
    const __half* Vtb = Vt + (size_t)bh * HD * SS;

    const float tsc = 0.18033688f;     // (1/sqrt(64)) * log2(e)

    uint32_t kvoff[4];
    #pragma unroll
    for (int p = 0; p < 4; p++)
        kvoff[p] = (uint32_t)((p * 16 + ((g >> 1) << 3) + rr) * HSTR
                              + ((g & 1) << 3)) * 2;

    const int crow = tid >> 3;           // 0..31
    const int coff = (tid & 7) * 8;      // halves
    const uint32_t sbase = smem_u32(smh);

    #define A_ISSUE(lt, s) do {                                              \
        const int kk0 = (lt) * LKEYS;                                        \
        uint32_t koff = sbase + (uint32_t)(s) * (KSTAGE_H * 2);              \
        uint32_t voff = sbase + (uint32_t)((2 + (s)) * KSTAGE_H) * 2;        \
        _Pragma("unroll")                                                    \
        for (int i = 0; i < 2; i++) {                                        \
            int row = crow + 32 * i;                                         \
            CP16(koff + (uint32_t)(row * HSTR + coff) * 2,                   \
                 Kb + (size_t)(kk0 + row) * HD + coff);                      \
            CP16(voff + (uint32_t)(row * HSTR + coff) * 2,                   \
                 Vtb + (size_t)row * SS + kk0 + coff);                       \
        }                                                                    \
        CP_COMMIT();                                                         \
    } while (0)

    // paired q-tiles: work(qb) + work(NT-1-qb) = NQT+1 stages, constant
    #pragma unroll 1
    for (int pass = 0; pass < 2; pass++) {
        const int qb = pass ? (NQT - 1 - blockIdx.x) : blockIdx.x;
        const int q0 = qb * ABQ;

        uint32_t Qf[4][4];
        {
            const __half* qr0 = Qb + (size_t)(q0 + wrow + fr) * HD;
            const __half* qr1 = qr0 + 8 * HD;
            #pragma unroll
            for (int ks = 0; ks < 4; ks++) {
                Qf[ks][0] = *(const uint32_t*)(qr0 + 16 * ks + 2 * fk);
                Qf[ks][1] = *(const uint32_t*)(qr1 + 16 * ks + 2 * fk);
                Qf[ks][2] = *(const uint32_t*)(qr0 + 16 * ks + 8 + 2 * fk);
                Qf[ks][3] = *(const uint32_t*)(qr1 + 16 * ks + 8 + 2 * fk);
            }
        }

        float Oacc[8][4];
        #pragma unroll
        for (int nt = 0; nt < 8; nt++)
            #pragma unroll
            for (int r = 0; r < 4; r++) Oacc[nt][r] = 0.f;

        float m0 = -INFINITY, m1 = -INFINITY, l0 = 0.f, l1 = 0.f;

        const int r0g = q0 + wrow + fr;
        const int r1g = r0g + 8;
        const int nload = (q0 + ABQ) / LKEYS;

        A_ISSUE(0, 0);

        for (int lt = 0; lt < nload; lt++) {
            const int k0  = lt * LKEYS;
            const int buf = lt & 1;
            CP_WAIT0();
            __syncthreads();
            if (lt + 1 < nload) A_ISSUE(lt + 1, buf ^ 1);

            const bool active = (k0 <= q0 + wrow + 15);   // warp-uniform
            if (active) {
                const uint32_t kbase = sbase + (uint32_t)buf * (KSTAGE_H * 2);
                const uint32_t vbase = sbase + (uint32_t)((2 + buf) * KSTAGE_H) * 2;

                float Sacc[8][4];
                #pragma unroll
                for (int nt = 0; nt < 8; nt++)
                    #pragma unroll
                    for (int r = 0; r < 4; r++) Sacc[nt][r] = 0.f;

                #pragma unroll
                for (int ks = 0; ks < 4; ks++) {
                    uint32_t kf[4][4];
                    #pragma unroll
                    for (int p = 0; p < 4; p++)
                        LDSM4(kf[p][0], kf[p][1], kf[p][2], kf[p][3],
                              kbase + kvoff[p] + 32 * ks);
                    #pragma unroll
                    for (int nt = 0; nt < 8; nt++)
                        mma_f16(Sacc[nt],
                                Qf[ks][0], Qf[ks][1], Qf[ks][2], Qf[ks][3],
                                kf[nt >> 1][(nt & 1) * 2],
                                kf[nt >> 1][(nt & 1) * 2 + 1]);
                }

                const bool full = (k0 + 63 <= q0 + wrow);  // warp-uniform
                if (!full) {
                    #pragma unroll
                    for (int nt = 0; nt < 8; nt++) {
                        int c0 = k0 + nt * 8 + 2 * fk;
                        if (c0     > r0g) Sacc[nt][0] = -INFINITY;
                        if (c0 + 1 > r0g) Sacc[nt][1] = -INFINITY;
                        if (c0     > r1g) Sacc[nt][2] = -INFINITY;
                        if (c0 + 1 > r1g) Sacc[nt][3] = -INFINITY;
                    }
                }

                float mx0 = Sacc[0][0], mx1 = Sacc[0][2];
                #pragma unroll
                for (int nt = 0; nt < 8; nt++) {
                    mx0 = fmaxf(mx0, fmaxf(Sacc[nt][0], Sacc[nt][1]));
                    mx1 = fmaxf(mx1, fmaxf(Sacc[nt][2], Sacc[nt][3]));
                }
                mx0 = fmaxf(mx0, __shfl_xor_sync(0xFFFFFFFFu, mx0, 1));
                mx0 = fmaxf(mx0, __shfl_xor_sync(0xFFFFFFFFu, mx0, 2));
                mx1 = fmaxf(mx1, __shfl_xor_sync(0xFFFFFFFFu, mx1, 1));
                mx1 = fmaxf(mx1, __shfl_xor_sync(0xFFFFFFFFu, mx1, 2));

                float mn0 = fmaxf(m0, mx0 * tsc);
                float mn1 = fmaxf(m1, mx1 * tsc);
                float al0 = exp2f(m0 - mn0);
                float al1 = exp2f(m1 - mn1);
                m0 = mn0; m1 = mn1;

                uint32_t P01[8], P23[8];
                float ps0 = 0.f, ps1 = 0.f;
                #pragma unroll
                for (int nt = 0; nt < 8; nt++) {
                    float f0 = fmaf(Sacc[nt][0], tsc, -m0);
                    float f1 = fmaf(Sacc[nt][1], tsc, -m0);
                    float f2 = fmaf(Sacc[nt][2], tsc, -m1);
                    float f3 = fmaf(Sacc[nt][3], tsc, -m1);
                    __half2 e01 = __floats2half2_rn(f0, f1);
                    __half2 e23 = __floats2half2_rn(f2, f3);
                    uint32_t p01 = ex2_f16x2(*(const uint32_t*)&e01);
                    uint32_t p23 = ex2_f16x2(*(const uint32_t*)&e23);
                    P01[nt] = p01;
                    P23[nt] = p23;
                    float2 q01 = __half22float2(*(const __half2*)&p01);
                    float2 q23 = __half22float2(*(const __half2*)&p23);
                    ps0 += q01.x + q01.y;
                    ps1 += q23.x + q23.y;
                }
                ps0 += __shfl_xor_sync(0xFFFFFFFFu, ps0, 1);
                ps0 += __shfl_xor_sync(0xFFFFFFFFu, ps0, 2);
                ps1 += __shfl_xor_sync(0xFFFFFFFFu, ps1, 1);
                ps1 += __shfl_xor_sync(0xFFFFFFFFu, ps1, 2);
                l0 = l0 * al0 + ps0;
                l1 = l1 * al1 + ps1;

                if (!__all_sync(0xFFFFFFFFu, (al0 == 1.f) & (al1 == 1.f))) {
                    #pragma unroll
                    for (int nt = 0; nt < 8; nt++) {
                        Oacc[nt][0] *= al0; Oacc[nt][1] *= al0;
                        Oacc[nt][2] *= al1; Oacc[nt][3] *= al1;
                    }
                }

                #pragma unroll
                for (int kst = 0; kst < 4; kst++) {
                    uint32_t vf[4][4];
                    #pragma unroll
                    for (int p = 0; p < 4; p++)
                        LDSM4(vf[p][0], vf[p][1], vf[p][2], vf[p][3],
                              vbase + kvoff[p] + 32 * kst);
                    uint32_t a0 = P01[2 * kst];
                    uint32_t a1 = P23[2 * kst];
                    uint32_t a2 = P01[2 * kst + 1];
                    uint32_t a3 = P23[2 * kst + 1];
                    #pragma unroll
                    for (int nt = 0; nt < 8; nt++)
                        mma_f16(Oacc[nt], a0, a1, a2, a3,
                                vf[nt >> 1][(nt & 1) * 2],
                                vf[nt >> 1][(nt & 1) * 2 + 1]);
                }
            }
            __syncthreads();
        }

        // ---- epilogue: normalize, write fp16 [b, s, h*64+d] ----
        const int b = bh >> 4, h = bh & 15;
        const float inv0 = 1.f / l0;
        const float inv1 = 1.f / l1;
        __half* O0 = O + ((size_t)(b * SS + r0g)) * DM + h * HD;
        __half* O1 = O + ((size_t)(b * SS + r1g)) * DM + h * HD;
        #pragma unroll
        for (int nt = 0; nt < 8; nt++) {
            int d = nt * 8 + 2 * fk;
            *(__half2*)(O0 + d) = __floats2half2_rn(Oacc[nt][0] * inv0,
                                                    Oacc[nt][1] * inv0);
            *(__half2*)(O1 + d) = __floats2half2_rn(Oacc[nt][2] * inv1,
                                                    Oacc[nt][3] * inv1);
        }
        // pipeline fully drained (no pending cp.async groups); trailing
        // __syncthreads in the last loop iteration fences smem reuse for
        // the next pass (epilogue touches only global memory)
    }
    #undef A_ISSUE
}

// ---------------------------------------------------------------------------
extern "C" void kernel_launch(void* const* d_in, const int* in_sizes, int n_in,
                              void* d_out, int out_size)
{
    const float* x  = (const float*)d_in[0];
    const float* Wq = (const float*)d_in[1];
    const float* bq = (const float*)d_in[2];
    const float* Wk = (const float*)d_in[3];
    const float* bk = (const float*)d_in[4];
    const float* Wv = (const float*)d_in[5];
    const float* bv = (const float*)d_in[6];
    const float* Wo = (const float*)d_in[7];
    const float* bo = (const float*)d_in[8];

    __half *xh, *wt, *qp, *kp, *vp, *ap;
    cudaGetSymbolAddress((void**)&xh, g_xh);
    cudaGetSymbolAddress((void**)&wt, g_Wt);
    cudaGetSymbolAddress((void**)&qp, g_Qh);
    cudaGetSymbolAddress((void**)&kp, g_Kh);
    cudaGetSymbolAddress((void**)&vp, g_Vt);
    cudaGetSymbolAddress((void**)&ap, g_att);

    cudaFuncSetAttribute(gemm_qkv,
        cudaFuncAttributeMaxDynamicSharedMemorySize, GEMM_SMEM);
    cudaFuncSetAttribute(gemm_o,
        cudaFuncAttributeMaxDynamicSharedMemorySize, GEMM_SMEM);
    cudaFuncSetAttribute(attn_h,
        cudaFuncAttributeMaxDynamicSharedMemorySize, ATTN_SMEM);

    // prep: fp16 conversions (+ weight transpose)
    cvt_x_h<<<MROWS * DM / 1024, 256>>>(x, xh);
    cvt_w_t<<<dim3(DM / 32, DM / 32, 4), 256>>>(Wq, Wk, Wv, Wo, wt);

    dim3 gqkv(DM / 128, MROWS / 128, 3);   // (8, 32, 3)
    gemm_qkv<<<gqkv, 256, GEMM_SMEM>>>(xh, wt, bq, bk, bv, qp, kp, vp);

    attn_h<<<dim3(NQT / 2, BB * NH), 256, ATTN_SMEM>>>(qp, kp, vp, ap);

    dim3 go(DM / 128, MROWS / 128);        // (8, 32)
    gemm_o<<<go, 256, GEMM_SMEM>>>(ap, wt + (size_t)3*DM*DM, bo, (float*)d_out);
}